// round 1
// baseline (speedup 1.0000x reference)
#include <cuda_runtime.h>
#include <math.h>

// ---------------- problem constants ----------------
constexpr int kS   = 512;
constexpr int kB   = 16;
constexpr int kD   = 768;
constexpr int kH   = 12;
constexpr int kHD  = 64;
constexpr int kE   = 8;
constexpr int kHID = 3072;
constexpr int kT   = kS * kB;          // 8192 tokens

// attention smem layout
constexpr int SCP = 521;               // score row stride (odd -> conflict-free)
constexpr int KVP = 65;                // q/k/v tile row stride
constexpr int ATTN_SMEM = (64 * SCP + 2 * 64 * KVP) * 4;  // 166656 bytes

// ---------------- scratch (device globals; no allocations) ----------------
__device__ float g_qin [kT * kD];
__device__ float g_q   [kT * kD];
__device__ float g_k   [kT * kD];
__device__ float g_v   [kT * kD];
__device__ float g_attn[kT * kD];
__device__ float g_x1  [kT * kD];
__device__ float g_tn  [kT * kD];
__device__ float g_h   [(size_t)kT * kHID];
__device__ float g_gate[kT];
__device__ int   g_idx [kT];
__device__ int   g_cnt [kE];
__device__ int   g_off [kE];
__device__ int   g_fill[kE];
__device__ int   g_perm[kT];

// ---------------- layernorm (one block per token, 256 threads) ----------------
__global__ void ln_kernel(const float* __restrict__ x, const float* __restrict__ w,
                          const float* __restrict__ bias, float* __restrict__ out)
{
    int t = blockIdx.x;
    const float* r = x + (size_t)t * kD;
    int tid = threadIdx.x;
    float v0 = r[tid], v1 = r[tid + 256], v2 = r[tid + 512];
    float s = v0 + v1 + v2;
    float q = v0 * v0 + v1 * v1 + v2 * v2;
#pragma unroll
    for (int o = 16; o > 0; o >>= 1) {
        s += __shfl_down_sync(0xffffffffu, s, o);
        q += __shfl_down_sync(0xffffffffu, q, o);
    }
    __shared__ float rs[8], rq[8];
    if ((tid & 31) == 0) { rs[tid >> 5] = s; rq[tid >> 5] = q; }
    __syncthreads();
    s = 0.f; q = 0.f;
#pragma unroll
    for (int i = 0; i < 8; ++i) { s += rs[i]; q += rq[i]; }
    float mean = s * (1.0f / kD);
    float var  = q * (1.0f / kD) - mean * mean;
    float inv  = rsqrtf(var + 1e-5f);
    float* o_ = out + (size_t)t * kD;
    o_[tid]       = (v0 - mean) * inv * w[tid]       + bias[tid];
    o_[tid + 256] = (v1 - mean) * inv * w[tid + 256] + bias[tid + 256];
    o_[tid + 512] = (v2 - mean) * inv * w[tid + 512] + bias[tid + 512];
}

// ---------------- generic 128x128x8 SGEMM ----------------
// MODE 0: C = A@W + bias
// MODE 1: C = R + A@W + bias
// MODE 2: per-expert gathered rows (g_perm), gelu(A@W+bias) -> C at sorted rows
// MODE 3: per-expert contiguous A rows, C[tok] = R[tok] + gate[tok]*(A@W+bias)
template <int MODE>
__global__ __launch_bounds__(256)
void gemm_kernel(const float* __restrict__ A, const float* __restrict__ W,
                 const float* __restrict__ bias, const float* __restrict__ R,
                 float* __restrict__ C, int M, int N, int K)
{
    int cntE = M, rowbase = 0;
    if (MODE >= 2) {
        int e = blockIdx.z;
        cntE = g_cnt[e];
        rowbase = g_off[e];
        if ((int)(blockIdx.x * 128) >= cntE) return;
        W    += (size_t)e * K * N;
        bias += (size_t)e * N;
    }
    __shared__ float As[8][128];
    __shared__ float Bs[8][128];
    int tid  = threadIdx.x;
    int arow = tid >> 1;
    int acol = (tid & 1) << 2;
    int brow = tid >> 5;
    int bcol = (tid & 31) << 2;
    int tx = tid & 15, ty = tid >> 4;
    int m0 = blockIdx.x * 128, n0 = blockIdx.y * 128;

    bool avalid = true;
    const float* Arow;
    int lrow = m0 + arow;
    if (MODE == 2) {
        avalid = lrow < cntE;
        int grow = avalid ? g_perm[rowbase + lrow] : 0;
        Arow = A + (size_t)grow * K;
    } else if (MODE == 3) {
        avalid = lrow < cntE;
        Arow = A + (size_t)(rowbase + (avalid ? lrow : 0)) * K;
    } else {
        Arow = A + (size_t)lrow * K;
    }

    float acc[8][8];
#pragma unroll
    for (int i = 0; i < 8; ++i)
#pragma unroll
        for (int j = 0; j < 8; ++j) acc[i][j] = 0.f;

    for (int k0 = 0; k0 < K; k0 += 8) {
        float4 a4 = avalid ? *(const float4*)(Arow + k0 + acol)
                           : make_float4(0.f, 0.f, 0.f, 0.f);
        float4 b4 = *(const float4*)(W + (size_t)(k0 + brow) * N + n0 + bcol);
        __syncthreads();
        As[acol + 0][arow] = a4.x;
        As[acol + 1][arow] = a4.y;
        As[acol + 2][arow] = a4.z;
        As[acol + 3][arow] = a4.w;
        *(float4*)&Bs[brow][bcol] = b4;
        __syncthreads();
#pragma unroll
        for (int kk = 0; kk < 8; ++kk) {
            float ar[8], br[8];
#pragma unroll
            for (int i = 0; i < 8; ++i) ar[i] = As[kk][ty * 8 + i];
#pragma unroll
            for (int j = 0; j < 8; ++j) br[j] = Bs[kk][tx * 8 + j];
#pragma unroll
            for (int i = 0; i < 8; ++i)
#pragma unroll
                for (int j = 0; j < 8; ++j)
                    acc[i][j] = fmaf(ar[i], br[j], acc[i][j]);
        }
    }

#pragma unroll
    for (int i = 0; i < 8; ++i) {
        int rowi = m0 + ty * 8 + i;
        if (MODE >= 2 && rowi >= cntE) continue;
#pragma unroll
        for (int j = 0; j < 8; ++j) {
            int n = n0 + tx * 8 + j;
            float v = acc[i][j] + bias[n];
            if (MODE == 0) {
                C[(size_t)rowi * N + n] = v;
            } else if (MODE == 1) {
                C[(size_t)rowi * N + n] = v + R[(size_t)rowi * N + n];
            } else if (MODE == 2) {
                float g = 0.5f * v * (1.0f + erff(v * 0.70710678118654752f));
                C[(size_t)(rowbase + rowi) * N + n] = g;
            } else {
                int tok = g_perm[rowbase + rowi];
                float gt = g_gate[tok];
                C[(size_t)tok * N + n] = R[(size_t)tok * N + n] + gt * v;
            }
        }
    }
}

// ---------------- fused attention: one (b,h, 64-query tile) per block ----------------
__global__ __launch_bounds__(256)
void attn_kernel(const float* __restrict__ Q, const float* __restrict__ Kx,
                 const float* __restrict__ V, float* __restrict__ O)
{
    extern __shared__ float sm[];
    float* sc = sm;                    // [64][SCP]
    float* qs = sm + 64 * SCP;         // [64][KVP]
    float* kv = qs + 64 * KVP;         // [64][KVP]
    __shared__ float red[64 * 4];

    int bh = blockIdx.x;
    int b = bh / kH, h = bh % kH;
    int qt = blockIdx.y;
    int tid = threadIdx.x;
    int tx = tid & 15, ty = tid >> 4;

    // load Q tile (64 queries x 64 dims)
    for (int idx = tid; idx < 64 * 16; idx += 256) {
        int i = idx >> 4, dv = (idx & 15) << 2;
        int s = qt * 64 + i;
        float4 v4 = *(const float4*)(Q + (size_t)(s * kB + b) * kD + h * kHD + dv);
        float* p = qs + i * KVP + dv;
        p[0] = v4.x; p[1] = v4.y; p[2] = v4.z; p[3] = v4.w;
    }

    // phase 1: scores = Q K^T * 1/8, held in smem [64][512]
    for (int kt = 0; kt < 8; ++kt) {
        __syncthreads();
        for (int idx = tid; idx < 64 * 16; idx += 256) {
            int i = idx >> 4, dv = (idx & 15) << 2;
            int s = kt * 64 + i;
            float4 v4 = *(const float4*)(Kx + (size_t)(s * kB + b) * kD + h * kHD + dv);
            float* p = kv + i * KVP + dv;
            p[0] = v4.x; p[1] = v4.y; p[2] = v4.z; p[3] = v4.w;
        }
        __syncthreads();
        float c[4][4];
#pragma unroll
        for (int r = 0; r < 4; ++r)
#pragma unroll
            for (int cc = 0; cc < 4; ++cc) c[r][cc] = 0.f;
        for (int d = 0; d < 64; ++d) {
            float a[4], bb[4];
#pragma unroll
            for (int r = 0; r < 4; ++r)  a[r]  = qs[(ty * 4 + r) * KVP + d];
#pragma unroll
            for (int cc = 0; cc < 4; ++cc) bb[cc] = kv[(tx * 4 + cc) * KVP + d];
#pragma unroll
            for (int r = 0; r < 4; ++r)
#pragma unroll
                for (int cc = 0; cc < 4; ++cc)
                    c[r][cc] = fmaf(a[r], bb[cc], c[r][cc]);
        }
#pragma unroll
        for (int r = 0; r < 4; ++r)
#pragma unroll
            for (int cc = 0; cc < 4; ++cc)
                sc[(ty * 4 + r) * SCP + kt * 64 + tx * 4 + cc] = c[r][cc] * 0.125f;
    }
    __syncthreads();

    // softmax over 512 keys per row; 4 threads per row
    int row = tid & 63, part = tid >> 6;
    float* srow = sc + row * SCP + part * 128;
    float m = -1e30f;
    for (int c = 0; c < 128; ++c) m = fmaxf(m, srow[c]);
    red[row * 4 + part] = m;
    __syncthreads();
    m = fmaxf(fmaxf(red[row * 4 + 0], red[row * 4 + 1]),
              fmaxf(red[row * 4 + 2], red[row * 4 + 3]));
    __syncthreads();
    float ssum = 0.f;
    for (int c = 0; c < 128; ++c) { float e = expf(srow[c] - m); srow[c] = e; ssum += e; }
    red[row * 4 + part] = ssum;
    __syncthreads();
    float inv = 1.0f / (red[row * 4 + 0] + red[row * 4 + 1] +
                        red[row * 4 + 2] + red[row * 4 + 3]);
    for (int c = 0; c < 128; ++c) srow[c] *= inv;

    // phase 2: O = P @ V
    float o[4][4];
#pragma unroll
    for (int r = 0; r < 4; ++r)
#pragma unroll
        for (int cc = 0; cc < 4; ++cc) o[r][cc] = 0.f;
    for (int kt = 0; kt < 8; ++kt) {
        __syncthreads();
        for (int idx = tid; idx < 64 * 16; idx += 256) {
            int i = idx >> 4, dv = (idx & 15) << 2;
            int s = kt * 64 + i;
            float4 v4 = *(const float4*)(V + (size_t)(s * kB + b) * kD + h * kHD + dv);
            float* p = kv + i * KVP + dv;
            p[0] = v4.x; p[1] = v4.y; p[2] = v4.z; p[3] = v4.w;
        }
        __syncthreads();
        for (int kk = 0; kk < 64; ++kk) {
            float p[4], vv[4];
#pragma unroll
            for (int r = 0; r < 4; ++r)  p[r]  = sc[(ty * 4 + r) * SCP + kt * 64 + kk];
#pragma unroll
            for (int cc = 0; cc < 4; ++cc) vv[cc] = kv[kk * KVP + tx * 4 + cc];
#pragma unroll
            for (int r = 0; r < 4; ++r)
#pragma unroll
                for (int cc = 0; cc < 4; ++cc)
                    o[r][cc] = fmaf(p[r], vv[cc], o[r][cc]);
        }
    }
#pragma unroll
    for (int r = 0; r < 4; ++r) {
        int s = qt * 64 + ty * 4 + r;
#pragma unroll
        for (int cc = 0; cc < 4; ++cc)
            O[(size_t)(s * kB + b) * kD + h * kHD + tx * 4 + cc] = o[r][cc];
    }
}

// ---------------- router: warp per token ----------------
__global__ void router_kernel(const float* __restrict__ tin, const float* __restrict__ wg,
                              const float* __restrict__ bg)
{
    int warp = threadIdx.x >> 5;
    int tok  = blockIdx.x * 8 + warp;
    int lane = threadIdx.x & 31;
    const float* row = tin + (size_t)tok * kD;
    int e = lane >> 2, j = lane & 3;
    float s = 0.f;
    for (int d = j; d < kD; d += 4) s += row[d] * wg[d * kE + e];
    s += __shfl_xor_sync(0xffffffffu, s, 1);
    s += __shfl_xor_sync(0xffffffffu, s, 2);
    s += bg[e];
    float lg[kE];
#pragma unroll
    for (int ee = 0; ee < kE; ++ee) lg[ee] = __shfl_sync(0xffffffffu, s, ee * 4);
    if (lane == 0) {
        int best = 0; float bm = lg[0];
#pragma unroll
        for (int ee = 1; ee < kE; ++ee) if (lg[ee] > bm) { bm = lg[ee]; best = ee; }
        float se = 0.f;
#pragma unroll
        for (int ee = 0; ee < kE; ++ee) se += expf(lg[ee] - bm);
        g_idx[tok]  = best;
        g_gate[tok] = 1.0f / se;   // exp(bm-bm)/se
        atomicAdd(&g_cnt[best], 1);
    }
}

__global__ void init_kernel()
{
    int t = threadIdx.x;
    if (t < kE) { g_cnt[t] = 0; g_fill[t] = 0; }
}

__global__ void prefix_kernel()
{
    int acc = 0;
    for (int e = 0; e < kE; ++e) { g_off[e] = acc; acc += g_cnt[e]; }
}

__global__ void scatter_kernel()
{
    int t = blockIdx.x * 256 + threadIdx.x;
    int e = g_idx[t];
    int p = atomicAdd(&g_fill[e], 1);
    g_perm[g_off[e] + p] = t;
}

// ---------------- launch ----------------
extern "C" void kernel_launch(void* const* d_in, const int* in_sizes, int n_in,
                              void* d_out, int out_size)
{
    const float* x    = (const float*)d_in[0];
    const float* ln1w = (const float*)d_in[1];
    const float* ln1b = (const float*)d_in[2];
    const float* wq   = (const float*)d_in[3];
    const float* bq   = (const float*)d_in[4];
    const float* wk   = (const float*)d_in[5];
    const float* bk   = (const float*)d_in[6];
    const float* wv   = (const float*)d_in[7];
    const float* bv   = (const float*)d_in[8];
    const float* wo   = (const float*)d_in[9];
    const float* bo   = (const float*)d_in[10];
    const float* ln2w = (const float*)d_in[11];
    const float* ln2b = (const float*)d_in[12];
    const float* wg   = (const float*)d_in[13];
    const float* bg   = (const float*)d_in[14];
    const float* w1   = (const float*)d_in[15];
    const float* b1   = (const float*)d_in[16];
    const float* w2   = (const float*)d_in[17];
    const float* b2   = (const float*)d_in[18];
    float* out = (float*)d_out;

    float *p_qin, *p_q, *p_k, *p_v, *p_attn, *p_x1, *p_t, *p_h;
    cudaGetSymbolAddress((void**)&p_qin,  g_qin);
    cudaGetSymbolAddress((void**)&p_q,    g_q);
    cudaGetSymbolAddress((void**)&p_k,    g_k);
    cudaGetSymbolAddress((void**)&p_v,    g_v);
    cudaGetSymbolAddress((void**)&p_attn, g_attn);
    cudaGetSymbolAddress((void**)&p_x1,   g_x1);
    cudaGetSymbolAddress((void**)&p_t,    g_tn);
    cudaGetSymbolAddress((void**)&p_h,    g_h);

    cudaFuncSetAttribute(attn_kernel, cudaFuncAttributeMaxDynamicSharedMemorySize, ATTN_SMEM);

    // LN1 -> q_in
    ln_kernel<<<kT, 256>>>(x, ln1w, ln1b, p_qin);

    // QKV projections (q from LN1 output; k,v from raw x per reference)
    dim3 g0(kT / 128, kD / 128);
    gemm_kernel<0><<<g0, 256>>>(p_qin, wq, bq, nullptr, p_q, kT, kD, kD);
    gemm_kernel<0><<<g0, 256>>>(x,     wk, bk, nullptr, p_k, kT, kD, kD);
    gemm_kernel<0><<<g0, 256>>>(x,     wv, bv, nullptr, p_v, kT, kD, kD);

    // fused attention
    attn_kernel<<<dim3(kB * kH, kS / 64), 256, ATTN_SMEM>>>(p_q, p_k, p_v, p_attn);

    // out projection + residual -> x1
    gemm_kernel<1><<<g0, 256>>>(p_attn, wo, bo, x, p_x1, kT, kD, kD);

    // LN2 -> t
    ln_kernel<<<kT, 256>>>(p_x1, ln2w, ln2b, p_t);

    // routing
    init_kernel<<<1, 32>>>();
    router_kernel<<<kT / 8, 256>>>(p_t, wg, bg);
    prefix_kernel<<<1, 1>>>();
    scatter_kernel<<<kT / 256, 256>>>();

    // MoE expert GEMMs
    gemm_kernel<2><<<dim3(kT / 128, kHID / 128, kE), 256>>>(p_t, w1, b1, nullptr, p_h, kT, kHID, kD);
    gemm_kernel<3><<<dim3(kT / 128, kD / 128, kE), 256>>>(p_h, w2, b2, p_x1, out, kT, kD, kHID);
}

// round 5
// speedup vs baseline: 3.0241x; 3.0241x over previous
#include <cuda_runtime.h>
#include <cuda_bf16.h>
#include <math.h>
#include <stdint.h>

// ---------------- problem constants ----------------
constexpr int kS   = 512;
constexpr int kB   = 16;
constexpr int kD   = 768;
constexpr int kH   = 12;
constexpr int kHD  = 64;
constexpr int kE   = 8;
constexpr int kHID = 3072;
constexpr int kT   = kS * kB;          // 8192 tokens

// attention smem layout
constexpr int SCP = 521;
constexpr int KVP = 65;
constexpr int ATTN_SMEM = (64 * SCP + 2 * 64 * KVP) * 4;

// ---------------- scratch (device globals; no allocations) ----------------
__device__ float g_qin [kT * kD];
__device__ float g_q   [kT * kD];
__device__ float g_k   [kT * kD];
__device__ float g_v   [kT * kD];
__device__ float g_attn[kT * kD];
__device__ float g_x1  [kT * kD];
__device__ float g_tn  [kT * kD];
__device__ float g_gate[kT];
__device__ int   g_idx [kT];
__device__ int   g_cnt [kE];
__device__ int   g_off [kE];
__device__ int   g_fill[kE];
__device__ int   g_perm[kT];

// bf16 scratch
__device__ __nv_bfloat16 g_wqt[kD * kD];
__device__ __nv_bfloat16 g_wkt[kD * kD];
__device__ __nv_bfloat16 g_wvt[kD * kD];
__device__ __nv_bfloat16 g_wot[kD * kD];
__device__ __nv_bfloat16 g_w1t[(size_t)kE * kHID * kD];   // [E][HID][D]
__device__ __nv_bfloat16 g_w2t[(size_t)kE * kD * kHID];   // [E][D][HID]
__device__ __nv_bfloat16 g_qin_b[kT * kD];
__device__ __nv_bfloat16 g_x_b  [kT * kD];
__device__ __nv_bfloat16 g_attn_b[kT * kD];
__device__ __nv_bfloat16 g_t_b  [kT * kD];
__device__ __nv_bfloat16 g_h_b  [(size_t)kT * kHID];

// ---------------- helpers ----------------
__device__ __forceinline__ uint32_t smem_u32(const void* p) {
    uint32_t a;
    asm("{ .reg .u64 t; cvta.to.shared.u64 t, %1; cvt.u32.u64 %0, t; }" : "=r"(a) : "l"(p));
    return a;
}

__device__ __forceinline__ void ldmx4(uint32_t* r, uint32_t addr) {
    asm volatile("ldmatrix.sync.aligned.m8n8.x4.shared.b16 {%0,%1,%2,%3}, [%4];"
                 : "=r"(r[0]), "=r"(r[1]), "=r"(r[2]), "=r"(r[3]) : "r"(addr));
}

__device__ __forceinline__ void mma16816(float* d, const uint32_t* a, uint32_t b0, uint32_t b1) {
    asm volatile(
        "mma.sync.aligned.m16n8k16.row.col.f32.bf16.bf16.f32 "
        "{%0,%1,%2,%3}, {%4,%5,%6,%7}, {%8,%9}, {%0,%1,%2,%3};"
        : "+f"(d[0]), "+f"(d[1]), "+f"(d[2]), "+f"(d[3])
        : "r"(a[0]), "r"(a[1]), "r"(a[2]), "r"(a[3]), "r"(b0), "r"(b1));
}

__device__ __forceinline__ uint32_t sw128(uint32_t off) {
    return off ^ ((off >> 3) & 0x70);
}

// ---------------- layernorm ----------------
__global__ void ln_kernel(const float* __restrict__ x, const float* __restrict__ w,
                          const float* __restrict__ bias, float* __restrict__ out)
{
    int t = blockIdx.x;
    const float* r = x + (size_t)t * kD;
    int tid = threadIdx.x;
    float v0 = r[tid], v1 = r[tid + 256], v2 = r[tid + 512];
    float s = v0 + v1 + v2;
    float q = v0 * v0 + v1 * v1 + v2 * v2;
#pragma unroll
    for (int o = 16; o > 0; o >>= 1) {
        s += __shfl_down_sync(0xffffffffu, s, o);
        q += __shfl_down_sync(0xffffffffu, q, o);
    }
    __shared__ float rs[8], rq[8];
    if ((tid & 31) == 0) { rs[tid >> 5] = s; rq[tid >> 5] = q; }
    __syncthreads();
    s = 0.f; q = 0.f;
#pragma unroll
    for (int i = 0; i < 8; ++i) { s += rs[i]; q += rq[i]; }
    float mean = s * (1.0f / kD);
    float var  = q * (1.0f / kD) - mean * mean;
    float inv  = rsqrtf(var + 1e-5f);
    float* o_ = out + (size_t)t * kD;
    o_[tid]       = (v0 - mean) * inv * w[tid]       + bias[tid];
    o_[tid + 256] = (v1 - mean) * inv * w[tid + 256] + bias[tid + 256];
    o_[tid + 512] = (v2 - mean) * inv * w[tid + 512] + bias[tid + 512];
}

// ---------------- fp32 -> bf16 convert ----------------
__global__ void conv_kernel(const float* __restrict__ in, __nv_bfloat16* __restrict__ out, int n4)
{
    int i = blockIdx.x * 256 + threadIdx.x;
    if (i >= n4) return;
    float4 v = ((const float4*)in)[i];
    ((__nv_bfloat162*)out)[2 * i]     = __floats2bfloat162_rn(v.x, v.y);
    ((__nv_bfloat162*)out)[2 * i + 1] = __floats2bfloat162_rn(v.z, v.w);
}

// ---------------- fp32 [R,C] -> bf16 [C,R] transpose-convert ----------------
__global__ void tconv_kernel(const float* __restrict__ in, __nv_bfloat16* __restrict__ out,
                             int R, int C)
{
    __shared__ float tile[32][33];
    int e = blockIdx.z;
    in  += (size_t)e * R * C;
    out += (size_t)e * R * C;
    int c0 = blockIdx.x * 32, r0 = blockIdx.y * 32;
    int tx = threadIdx.x;
    for (int i = threadIdx.y; i < 32; i += 8)
        tile[i][tx] = in[(size_t)(r0 + i) * C + c0 + tx];
    __syncthreads();
    for (int i = threadIdx.y; i < 32; i += 8)
        out[(size_t)(c0 + i) * R + r0 + tx] = __float2bfloat16(tile[tx][i]);
}

// ---------------- bf16 mma.sync GEMM, 128x128 tile, K chunks of 64 ----------------
// A: [M,K] bf16 row-major, Wt: [N,K] bf16 row-major (= B^T)
// MODE 0: Cf = A@W + bias
// MODE 1: Cf = R + A@W + bias
// MODE 2: gathered rows via g_perm, gelu -> Cb (bf16) at sorted rows
// MODE 3: contiguous sorted rows, Cf[tok] = R[tok] + gate[tok]*(A@W+bias)
template <int MODE>
__global__ __launch_bounds__(256)
void tc_gemm(const __nv_bfloat16* __restrict__ A, const __nv_bfloat16* __restrict__ Wt,
             const float* __restrict__ bias, const float* __restrict__ R,
             float* __restrict__ Cf, __nv_bfloat16* __restrict__ Cb,
             int M, int N, int K)
{
    int cntE = M, rowbase = 0;
    if (MODE >= 2) {
        int e = blockIdx.z;
        cntE = g_cnt[e];
        rowbase = g_off[e];
        if ((int)(blockIdx.x * 128) >= cntE) return;
        Wt   += (size_t)e * K * N;
        bias += (size_t)e * N;
    }
    int m0 = blockIdx.x * 128, n0 = blockIdx.y * 128;
    int tid = threadIdx.x, wid = tid >> 5, lane = tid & 31;
    int wm = (wid & 1) * 64;       // warp M offset (2 warps over M)
    int wn = (wid >> 1) * 32;      // warp N offset (4 warps over N)

    // smem: A tile 128x64 bf16 (16KB) + B tile 128x64 bf16 (16KB), SW128
    __shared__ __align__(128) __nv_bfloat16 sA[128 * 64];
    __shared__ __align__(128) __nv_bfloat16 sB[128 * 64];
    uint32_t sAu = smem_u32(sA);
    uint32_t sBu = smem_u32(sB);

    // global row pointers: each thread loads 4 rows x 16B for A and for B
    int li = tid & 7, r4 = tid >> 3;   // li: 16B column index (8 x 16B = 128B row)
    const __nv_bfloat16* aptr[4];
    const __nv_bfloat16* bptr[4];
#pragma unroll
    for (int rr = 0; rr < 4; ++rr) {
        int row = r4 + rr * 32;
        int lr = m0 + row;
        const __nv_bfloat16* ap;
        if (MODE == 2) {
            int gr = (lr < cntE) ? g_perm[rowbase + lr] : 0;
            ap = A + (size_t)gr * K;
        } else if (MODE == 3) {
            ap = A + (size_t)(rowbase + (lr < cntE ? lr : 0)) * K;
        } else {
            ap = A + (size_t)lr * K;
        }
        aptr[rr] = ap + li * 8;
        bptr[rr] = Wt + (size_t)(n0 + row) * K + li * 8;
    }

    float acc[4][4][4];
#pragma unroll
    for (int i = 0; i < 4; ++i)
#pragma unroll
        for (int j = 0; j < 4; ++j)
#pragma unroll
            for (int v = 0; v < 4; ++v) acc[i][j][v] = 0.f;

    // precomputed ldmatrix smem addresses (chunk-invariant part)
    // A: row = wm + fm*16 + (lane&15), kb = (lane&16)?16:0  (+ kk*32)
    // B: row = wn + fn2*16 + (lane&7) + ((lane>>4)&1)*8, kb = ((lane>>3)&1)*16 (+ kk*32)
    uint32_t aRow = (uint32_t)(wm + (lane & 15));
    uint32_t aKb  = (lane & 16) ? 16u : 0u;
    uint32_t bRow = (uint32_t)(wn + (lane & 7) + ((lane >> 4) & 1) * 8);
    uint32_t bKb  = ((lane >> 3) & 1) * 16u;

    int nc = K >> 6;
    uint4 av[4], bv[4];
#pragma unroll
    for (int rr = 0; rr < 4; ++rr) {
        av[rr] = *(const uint4*)(aptr[rr]);
        bv[rr] = *(const uint4*)(bptr[rr]);
    }

    for (int c = 0; c < nc; ++c) {
        __syncthreads();
#pragma unroll
        for (int rr = 0; rr < 4; ++rr) {
            int row = r4 + rr * 32;
            uint32_t off = sw128((uint32_t)row * 128 + (uint32_t)li * 16);
            *(uint4*)((char*)sA + off) = av[rr];
            *(uint4*)((char*)sB + off) = bv[rr];
        }
        __syncthreads();
        if (c + 1 < nc) {
#pragma unroll
            for (int rr = 0; rr < 4; ++rr) {
                av[rr] = *(const uint4*)(aptr[rr] + (c + 1) * 64);
                bv[rr] = *(const uint4*)(bptr[rr] + (c + 1) * 64);
            }
        }
#pragma unroll
        for (int kk = 0; kk < 4; ++kk) {
            uint32_t afr[4][4];
#pragma unroll
            for (int fm = 0; fm < 4; ++fm) {
                uint32_t off = (aRow + fm * 16) * 128 + (kk * 32 + aKb);
                ldmx4(afr[fm], sAu + sw128(off));
            }
            uint32_t bfr[2][4];
#pragma unroll
            for (int fn2 = 0; fn2 < 2; ++fn2) {
                uint32_t off = (bRow + fn2 * 16) * 128 + (kk * 32 + bKb);
                ldmx4(bfr[fn2], sBu + sw128(off));
            }
#pragma unroll
            for (int fm = 0; fm < 4; ++fm)
#pragma unroll
                for (int fn = 0; fn < 4; ++fn)
                    mma16816(acc[fm][fn], afr[fm],
                             bfr[fn >> 1][(fn & 1) * 2], bfr[fn >> 1][(fn & 1) * 2 + 1]);
        }
    }

    // ---------------- epilogue ----------------
    // thread t of warp holds, per frag (fm,fn): d0,d1 -> (row = lane>>2, col=(lane&3)*2,+1)
    //                                           d2,d3 -> (row+8, same cols)
    int rbase = lane >> 2;
    int cbase = (lane & 3) * 2;
#pragma unroll
    for (int fm = 0; fm < 4; ++fm) {
#pragma unroll
        for (int half = 0; half < 2; ++half) {
            int rloc = wm + fm * 16 + rbase + half * 8;
            int rowi = m0 + rloc;
            bool valid = (MODE < 2) || (rowi < cntE);
            if (!valid) continue;
            int tok = 0;
            float gt = 0.f;
            if (MODE == 3) { tok = g_perm[rowbase + rowi]; gt = g_gate[tok]; }
#pragma unroll
            for (int fn = 0; fn < 4; ++fn) {
                int col = n0 + wn + fn * 8 + cbase;
                float v0 = acc[fm][fn][half * 2 + 0] + bias[col];
                float v1 = acc[fm][fn][half * 2 + 1] + bias[col + 1];
                if (MODE == 0) {
                    float* o = Cf + (size_t)rowi * N + col;
                    o[0] = v0; o[1] = v1;
                } else if (MODE == 1) {
                    float* o = Cf + (size_t)rowi * N + col;
                    const float* rr_ = R + (size_t)rowi * N + col;
                    o[0] = v0 + rr_[0]; o[1] = v1 + rr_[1];
                } else if (MODE == 2) {
                    float gl0 = 0.5f * v0 * (1.0f + erff(v0 * 0.70710678118654752f));
                    float gl1 = 0.5f * v1 * (1.0f + erff(v1 * 0.70710678118654752f));
                    *(__nv_bfloat162*)(Cb + (size_t)(rowbase + rowi) * N + col) =
                        __floats2bfloat162_rn(gl0, gl1);
                } else {
                    float* o = Cf + (size_t)tok * N + col;
                    const float* rr_ = R + (size_t)tok * N + col;
                    o[0] = rr_[0] + gt * v0;
                    o[1] = rr_[1] + gt * v1;
                }
            }
        }
    }
}

// ---------------- fused attention (fp32) ----------------
__global__ __launch_bounds__(256)
void attn_kernel(const float* __restrict__ Q, const float* __restrict__ Kx,
                 const float* __restrict__ V, float* __restrict__ O)
{
    extern __shared__ float sm[];
    float* sc = sm;
    float* qs = sm + 64 * SCP;
    float* kv = qs + 64 * KVP;
    __shared__ float red[64 * 4];

    int bh = blockIdx.x;
    int b = bh / kH, h = bh % kH;
    int qt = blockIdx.y;
    int tid = threadIdx.x;
    int tx = tid & 15, ty = tid >> 4;

    for (int idx = tid; idx < 64 * 16; idx += 256) {
        int i = idx >> 4, dv = (idx & 15) << 2;
        int s = qt * 64 + i;
        float4 v4 = *(const float4*)(Q + (size_t)(s * kB + b) * kD + h * kHD + dv);
        float* p = qs + i * KVP + dv;
        p[0] = v4.x; p[1] = v4.y; p[2] = v4.z; p[3] = v4.w;
    }

    for (int kt = 0; kt < 8; ++kt) {
        __syncthreads();
        for (int idx = tid; idx < 64 * 16; idx += 256) {
            int i = idx >> 4, dv = (idx & 15) << 2;
            int s = kt * 64 + i;
            float4 v4 = *(const float4*)(Kx + (size_t)(s * kB + b) * kD + h * kHD + dv);
            float* p = kv + i * KVP + dv;
            p[0] = v4.x; p[1] = v4.y; p[2] = v4.z; p[3] = v4.w;
        }
        __syncthreads();
        float c[4][4];
#pragma unroll
        for (int r = 0; r < 4; ++r)
#pragma unroll
            for (int cc = 0; cc < 4; ++cc) c[r][cc] = 0.f;
        for (int d = 0; d < 64; ++d) {
            float a[4], bb[4];
#pragma unroll
            for (int r = 0; r < 4; ++r)  a[r]  = qs[(ty * 4 + r) * KVP + d];
#pragma unroll
            for (int cc = 0; cc < 4; ++cc) bb[cc] = kv[(tx * 4 + cc) * KVP + d];
#pragma unroll
            for (int r = 0; r < 4; ++r)
#pragma unroll
                for (int cc = 0; cc < 4; ++cc)
                    c[r][cc] = fmaf(a[r], bb[cc], c[r][cc]);
        }
#pragma unroll
        for (int r = 0; r < 4; ++r)
#pragma unroll
            for (int cc = 0; cc < 4; ++cc)
                sc[(ty * 4 + r) * SCP + kt * 64 + tx * 4 + cc] = c[r][cc] * 0.125f;
    }
    __syncthreads();

    int row = tid & 63, part = tid >> 6;
    float* srow = sc + row * SCP + part * 128;
    float m = -1e30f;
    for (int c = 0; c < 128; ++c) m = fmaxf(m, srow[c]);
    red[row * 4 + part] = m;
    __syncthreads();
    m = fmaxf(fmaxf(red[row * 4 + 0], red[row * 4 + 1]),
              fmaxf(red[row * 4 + 2], red[row * 4 + 3]));
    __syncthreads();
    float ssum = 0.f;
    for (int c = 0; c < 128; ++c) { float e = expf(srow[c] - m); srow[c] = e; ssum += e; }
    red[row * 4 + part] = ssum;
    __syncthreads();
    float inv = 1.0f / (red[row * 4 + 0] + red[row * 4 + 1] +
                        red[row * 4 + 2] + red[row * 4 + 3]);
    for (int c = 0; c < 128; ++c) srow[c] *= inv;

    float o[4][4];
#pragma unroll
    for (int r = 0; r < 4; ++r)
#pragma unroll
        for (int cc = 0; cc < 4; ++cc) o[r][cc] = 0.f;
    for (int kt = 0; kt < 8; ++kt) {
        __syncthreads();
        for (int idx = tid; idx < 64 * 16; idx += 256) {
            int i = idx >> 4, dv = (idx & 15) << 2;
            int s = kt * 64 + i;
            float4 v4 = *(const float4*)(V + (size_t)(s * kB + b) * kD + h * kHD + dv);
            float* p = kv + i * KVP + dv;
            p[0] = v4.x; p[1] = v4.y; p[2] = v4.z; p[3] = v4.w;
        }
        __syncthreads();
        for (int kk = 0; kk < 64; ++kk) {
            float p[4], vv[4];
#pragma unroll
            for (int r = 0; r < 4; ++r)  p[r]  = sc[(ty * 4 + r) * SCP + kt * 64 + kk];
#pragma unroll
            for (int cc = 0; cc < 4; ++cc) vv[cc] = kv[kk * KVP + tx * 4 + cc];
#pragma unroll
            for (int r = 0; r < 4; ++r)
#pragma unroll
                for (int cc = 0; cc < 4; ++cc)
                    o[r][cc] = fmaf(p[r], vv[cc], o[r][cc]);
        }
    }
#pragma unroll
    for (int r = 0; r < 4; ++r) {
        int s = qt * 64 + ty * 4 + r;
#pragma unroll
        for (int cc = 0; cc < 4; ++cc)
            O[(size_t)(s * kB + b) * kD + h * kHD + tx * 4 + cc] = o[r][cc];
    }
}

// ---------------- router ----------------
__global__ void router_kernel(const float* __restrict__ tin, const float* __restrict__ wg,
                              const float* __restrict__ bg)
{
    int warp = threadIdx.x >> 5;
    int tok  = blockIdx.x * 8 + warp;
    int lane = threadIdx.x & 31;
    const float* row = tin + (size_t)tok * kD;
    int e = lane >> 2, j = lane & 3;
    float s = 0.f;
    for (int d = j; d < kD; d += 4) s += row[d] * wg[d * kE + e];
    s += __shfl_xor_sync(0xffffffffu, s, 1);
    s += __shfl_xor_sync(0xffffffffu, s, 2);
    s += bg[e];
    float lg[kE];
#pragma unroll
    for (int ee = 0; ee < kE; ++ee) lg[ee] = __shfl_sync(0xffffffffu, s, ee * 4);
    if (lane == 0) {
        int best = 0; float bm = lg[0];
#pragma unroll
        for (int ee = 1; ee < kE; ++ee) if (lg[ee] > bm) { bm = lg[ee]; best = ee; }
        float se = 0.f;
#pragma unroll
        for (int ee = 0; ee < kE; ++ee) se += expf(lg[ee] - bm);
        g_idx[tok]  = best;
        g_gate[tok] = 1.0f / se;
        atomicAdd(&g_cnt[best], 1);
    }
}

__global__ void init_kernel()
{
    int t = threadIdx.x;
    if (t < kE) { g_cnt[t] = 0; g_fill[t] = 0; }
}

__global__ void prefix_kernel()
{
    int acc = 0;
    for (int e = 0; e < kE; ++e) { g_off[e] = acc; acc += g_cnt[e]; }
}

__global__ void scatter_kernel()
{
    int t = blockIdx.x * 256 + threadIdx.x;
    int e = g_idx[t];
    int p = atomicAdd(&g_fill[e], 1);
    g_perm[g_off[e] + p] = t;
}

// ---------------- launch ----------------
extern "C" void kernel_launch(void* const* d_in, const int* in_sizes, int n_in,
                              void* d_out, int out_size)
{
    const float* x    = (const float*)d_in[0];
    const float* ln1w = (const float*)d_in[1];
    const float* ln1b = (const float*)d_in[2];
    const float* wq   = (const float*)d_in[3];
    const float* bq   = (const float*)d_in[4];
    const float* wk   = (const float*)d_in[5];
    const float* bk   = (const float*)d_in[6];
    const float* wv   = (const float*)d_in[7];
    const float* bv   = (const float*)d_in[8];
    const float* wo   = (const float*)d_in[9];
    const float* bo   = (const float*)d_in[10];
    const float* ln2w = (const float*)d_in[11];
    const float* ln2b = (const float*)d_in[12];
    const float* wg   = (const float*)d_in[13];
    const float* bg   = (const float*)d_in[14];
    const float* w1   = (const float*)d_in[15];
    const float* b1   = (const float*)d_in[16];
    const float* w2   = (const float*)d_in[17];
    const float* b2   = (const float*)d_in[18];
    float* out = (float*)d_out;

    float *p_qin, *p_q, *p_k, *p_v, *p_attn, *p_x1, *p_t;
    __nv_bfloat16 *p_wqt, *p_wkt, *p_wvt, *p_wot, *p_w1t, *p_w2t;
    __nv_bfloat16 *p_qin_b, *p_x_b, *p_attn_b, *p_t_b, *p_h_b;
    cudaGetSymbolAddress((void**)&p_qin,  g_qin);
    cudaGetSymbolAddress((void**)&p_q,    g_q);
    cudaGetSymbolAddress((void**)&p_k,    g_k);
    cudaGetSymbolAddress((void**)&p_v,    g_v);
    cudaGetSymbolAddress((void**)&p_attn, g_attn);
    cudaGetSymbolAddress((void**)&p_x1,   g_x1);
    cudaGetSymbolAddress((void**)&p_t,    g_tn);
    cudaGetSymbolAddress((void**)&p_wqt,  g_wqt);
    cudaGetSymbolAddress((void**)&p_wkt,  g_wkt);
    cudaGetSymbolAddress((void**)&p_wvt,  g_wvt);
    cudaGetSymbolAddress((void**)&p_wot,  g_wot);
    cudaGetSymbolAddress((void**)&p_w1t,  g_w1t);
    cudaGetSymbolAddress((void**)&p_w2t,  g_w2t);
    cudaGetSymbolAddress((void**)&p_qin_b, g_qin_b);
    cudaGetSymbolAddress((void**)&p_x_b,   g_x_b);
    cudaGetSymbolAddress((void**)&p_attn_b, g_attn_b);
    cudaGetSymbolAddress((void**)&p_t_b,   g_t_b);
    cudaGetSymbolAddress((void**)&p_h_b,   g_h_b);

    cudaFuncSetAttribute(attn_kernel, cudaFuncAttributeMaxDynamicSharedMemorySize, ATTN_SMEM);

    // weight convert + transpose (fp32 [K,N] -> bf16 [N,K])
    dim3 tcb(32, 8);
    tconv_kernel<<<dim3(kD / 32, kD / 32, 1), tcb>>>(wq, p_wqt, kD, kD);
    tconv_kernel<<<dim3(kD / 32, kD / 32, 1), tcb>>>(wk, p_wkt, kD, kD);
    tconv_kernel<<<dim3(kD / 32, kD / 32, 1), tcb>>>(wv, p_wvt, kD, kD);
    tconv_kernel<<<dim3(kD / 32, kD / 32, 1), tcb>>>(wo, p_wot, kD, kD);
    tconv_kernel<<<dim3(kHID / 32, kD / 32, kE), tcb>>>(w1, p_w1t, kD, kHID);
    tconv_kernel<<<dim3(kD / 32, kHID / 32, kE), tcb>>>(w2, p_w2t, kHID, kD);

    // LN1 -> q_in ; converts
    ln_kernel<<<kT, 256>>>(x, ln1w, ln1b, p_qin);
    int n4 = kT * kD / 4;
    conv_kernel<<<(n4 + 255) / 256, 256>>>(p_qin, p_qin_b, n4);
    conv_kernel<<<(n4 + 255) / 256, 256>>>(x, p_x_b, n4);

    // QKV projections
    dim3 g0(kT / 128, kD / 128);
    tc_gemm<0><<<g0, 256>>>(p_qin_b, p_wqt, bq, nullptr, p_q, nullptr, kT, kD, kD);
    tc_gemm<0><<<g0, 256>>>(p_x_b,   p_wkt, bk, nullptr, p_k, nullptr, kT, kD, kD);
    tc_gemm<0><<<g0, 256>>>(p_x_b,   p_wvt, bv, nullptr, p_v, nullptr, kT, kD, kD);

    // fused attention
    attn_kernel<<<dim3(kB * kH, kS / 64), 256, ATTN_SMEM>>>(p_q, p_k, p_v, p_attn);

    // out projection + residual
    conv_kernel<<<(n4 + 255) / 256, 256>>>(p_attn, p_attn_b, n4);
    tc_gemm<1><<<g0, 256>>>(p_attn_b, p_wot, bo, x, p_x1, nullptr, kT, kD, kD);

    // LN2 -> t
    ln_kernel<<<kT, 256>>>(p_x1, ln2w, ln2b, p_t);
    conv_kernel<<<(n4 + 255) / 256, 256>>>(p_t, p_t_b, n4);

    // routing
    init_kernel<<<1, 32>>>();
    router_kernel<<<kT / 8, 256>>>(p_t, wg, bg);
    prefix_kernel<<<1, 1>>>();
    scatter_kernel<<<kT / 256, 256>>>();

    // MoE expert GEMMs
    tc_gemm<2><<<dim3(kT / 128, kHID / 128, kE), 256>>>(
        p_t_b, p_w1t, b1, nullptr, nullptr, p_h_b, kT, kHID, kD);
    tc_gemm<3><<<dim3(kT / 128, kD / 128, kE), 256>>>(
        p_h_b, p_w2t, b2, p_x1, out, nullptr, kT, kD, kHID);
}

// round 6
// speedup vs baseline: 4.1486x; 1.3719x over previous
#include <cuda_runtime.h>
#include <cuda_fp16.h>
#include <math.h>
#include <stdint.h>

// ---------------- problem constants ----------------
constexpr int kS   = 512;
constexpr int kB   = 16;
constexpr int kD   = 768;
constexpr int kH   = 12;
constexpr int kHD  = 64;
constexpr int kE   = 8;
constexpr int kHID = 3072;
constexpr int kT   = kS * kB;          // 8192 tokens

// attention smem layout (bytes)
constexpr int ATT_Q  = 0;              // 64x64 half swizzled      (8192)
constexpr int ATT_KV = 8192;           // 64x64 half swizzled      (8192)
constexpr int ATT_P  = 16384;          // 8 chunks of 64x64 half   (65536)
constexpr int ATT_SC = 81920;          // 64x520 fp32              (133120)
constexpr int SCP2   = 520;
constexpr int ATTN_SMEM = ATT_SC + 64 * SCP2 * 4;   // 215040

// ---------------- scratch (device globals; no allocations) ----------------
__device__ float g_x1  [kT * kD];
__device__ float g_tn  [kT * kD];
__device__ float g_gate[kT];
__device__ int   g_idx [kT];
__device__ int   g_cnt [kE];
__device__ int   g_off [kE];
__device__ int   g_fill[kE];
__device__ int   g_perm[kT];

// fp16 scratch
__device__ __half g_wqt[kD * kD];
__device__ __half g_wkt[kD * kD];
__device__ __half g_wvt[kD * kD];
__device__ __half g_wot[kD * kD];
__device__ __half g_w1t[(size_t)kE * kHID * kD];   // [E][HID][D]
__device__ __half g_w2t[(size_t)kE * kD * kHID];   // [E][D][HID]
__device__ __half g_qin_h[kT * kD];
__device__ __half g_x_h  [kT * kD];
__device__ __half g_qh   [kT * kD];
__device__ __half g_kh   [kT * kD];
__device__ __half g_vh   [kT * kD];
__device__ __half g_attn_h[kT * kD];
__device__ __half g_t_h  [kT * kD];
__device__ __half g_h_h  [(size_t)kT * kHID];

// ---------------- helpers ----------------
__device__ __forceinline__ uint32_t smem_u32(const void* p) {
    uint32_t a;
    asm("{ .reg .u64 t; cvta.to.shared.u64 t, %1; cvt.u32.u64 %0, t; }" : "=r"(a) : "l"(p));
    return a;
}

__device__ __forceinline__ void ldmx4(uint32_t* r, uint32_t addr) {
    asm volatile("ldmatrix.sync.aligned.m8n8.x4.shared.b16 {%0,%1,%2,%3}, [%4];"
                 : "=r"(r[0]), "=r"(r[1]), "=r"(r[2]), "=r"(r[3]) : "r"(addr));
}

__device__ __forceinline__ void mma16816(float* d, const uint32_t* a, uint32_t b0, uint32_t b1) {
    asm volatile(
        "mma.sync.aligned.m16n8k16.row.col.f32.f16.f16.f32 "
        "{%0,%1,%2,%3}, {%4,%5,%6,%7}, {%8,%9}, {%0,%1,%2,%3};"
        : "+f"(d[0]), "+f"(d[1]), "+f"(d[2]), "+f"(d[3])
        : "r"(a[0]), "r"(a[1]), "r"(a[2]), "r"(a[3]), "r"(b0), "r"(b1));
}

__device__ __forceinline__ uint32_t sw128(uint32_t off) {
    return off ^ ((off >> 3) & 0x70);
}

// ---------------- layernorm variants ----------------
// LNOUT 0: half only ; 1: fp32 + half
template <int LNOUT>
__global__ void ln_kernel(const float* __restrict__ x, const float* __restrict__ w,
                          const float* __restrict__ bias,
                          float* __restrict__ outf, __half* __restrict__ outh)
{
    int t = blockIdx.x;
    const float* r = x + (size_t)t * kD;
    int tid = threadIdx.x;
    float v0 = r[tid], v1 = r[tid + 256], v2 = r[tid + 512];
    float s = v0 + v1 + v2;
    float q = v0 * v0 + v1 * v1 + v2 * v2;
#pragma unroll
    for (int o = 16; o > 0; o >>= 1) {
        s += __shfl_down_sync(0xffffffffu, s, o);
        q += __shfl_down_sync(0xffffffffu, q, o);
    }
    __shared__ float rs[8], rq[8];
    if ((tid & 31) == 0) { rs[tid >> 5] = s; rq[tid >> 5] = q; }
    __syncthreads();
    s = 0.f; q = 0.f;
#pragma unroll
    for (int i = 0; i < 8; ++i) { s += rs[i]; q += rq[i]; }
    float mean = s * (1.0f / kD);
    float var  = q * (1.0f / kD) - mean * mean;
    float inv  = rsqrtf(var + 1e-5f);
    float o0 = (v0 - mean) * inv * w[tid]       + bias[tid];
    float o1 = (v1 - mean) * inv * w[tid + 256] + bias[tid + 256];
    float o2 = (v2 - mean) * inv * w[tid + 512] + bias[tid + 512];
    if (LNOUT == 1) {
        float* of = outf + (size_t)t * kD;
        of[tid] = o0; of[tid + 256] = o1; of[tid + 512] = o2;
    }
    __half* oh = outh + (size_t)t * kD;
    oh[tid]       = __float2half(o0);
    oh[tid + 256] = __float2half(o1);
    oh[tid + 512] = __float2half(o2);
}

// ---------------- fp32 -> fp16 convert ----------------
__global__ void conv_kernel(const float* __restrict__ in, __half* __restrict__ out, int n4)
{
    int i = blockIdx.x * 256 + threadIdx.x;
    if (i >= n4) return;
    float4 v = ((const float4*)in)[i];
    ((__half2*)out)[2 * i]     = __floats2half2_rn(v.x, v.y);
    ((__half2*)out)[2 * i + 1] = __floats2half2_rn(v.z, v.w);
}

// ---------------- fp32 [R,C] -> fp16 [C,R] transpose-convert ----------------
__global__ void tconv_kernel(const float* __restrict__ in, __half* __restrict__ out,
                             int R, int C)
{
    __shared__ float tile[32][33];
    int e = blockIdx.z;
    in  += (size_t)e * R * C;
    out += (size_t)e * R * C;
    int c0 = blockIdx.x * 32, r0 = blockIdx.y * 32;
    int tx = threadIdx.x;
    for (int i = threadIdx.y; i < 32; i += 8)
        tile[i][tx] = in[(size_t)(r0 + i) * C + c0 + tx];
    __syncthreads();
    for (int i = threadIdx.y; i < 32; i += 8)
        out[(size_t)(c0 + i) * R + r0 + tx] = __float2half(tile[tx][i]);
}

// ---------------- fp16 mma.sync GEMM, 128x128 tile, K chunks of 64 ----------------
// A: [M,K] half row-major, Wt: [N,K] half row-major (= B^T)
// MODE 0: Cf = A@W + bias
// MODE 1: Cf = R + A@W + bias
// MODE 2: gathered rows via g_perm, gelu -> Cb (half) at sorted rows
// MODE 3: contiguous sorted rows, Cf[tok] = R[tok] + gate[tok]*(A@W+bias)
// MODE 4: Cb = half(A@W + bias)
template <int MODE>
__global__ __launch_bounds__(256)
void tc_gemm(const __half* __restrict__ A, const __half* __restrict__ Wt,
             const float* __restrict__ bias, const float* __restrict__ R,
             float* __restrict__ Cf, __half* __restrict__ Cb,
             int M, int N, int K)
{
    int cntE = M, rowbase = 0;
    if (MODE == 2 || MODE == 3) {
        int e = blockIdx.z;
        cntE = g_cnt[e];
        rowbase = g_off[e];
        if ((int)(blockIdx.x * 128) >= cntE) return;
        Wt   += (size_t)e * K * N;
        bias += (size_t)e * N;
    }
    int m0 = blockIdx.x * 128, n0 = blockIdx.y * 128;
    int tid = threadIdx.x, wid = tid >> 5, lane = tid & 31;
    int wm = (wid & 1) * 64;
    int wn = (wid >> 1) * 32;

    __shared__ __align__(128) __half sA[128 * 64];
    __shared__ __align__(128) __half sB[128 * 64];
    uint32_t sAu = smem_u32(sA);
    uint32_t sBu = smem_u32(sB);

    int li = tid & 7, r4 = tid >> 3;
    const __half* aptr[4];
    const __half* bptr[4];
#pragma unroll
    for (int rr = 0; rr < 4; ++rr) {
        int row = r4 + rr * 32;
        int lr = m0 + row;
        const __half* ap;
        if (MODE == 2) {
            int gr = (lr < cntE) ? g_perm[rowbase + lr] : 0;
            ap = A + (size_t)gr * K;
        } else if (MODE == 3) {
            ap = A + (size_t)(rowbase + (lr < cntE ? lr : 0)) * K;
        } else {
            ap = A + (size_t)lr * K;
        }
        aptr[rr] = ap + li * 8;
        bptr[rr] = Wt + (size_t)(n0 + row) * K + li * 8;
    }

    float acc[4][4][4];
#pragma unroll
    for (int i = 0; i < 4; ++i)
#pragma unroll
        for (int j = 0; j < 4; ++j)
#pragma unroll
            for (int v = 0; v < 4; ++v) acc[i][j][v] = 0.f;

    uint32_t aRow = (uint32_t)(wm + (lane & 15));
    uint32_t aKb  = (lane & 16) ? 16u : 0u;
    uint32_t bRow = (uint32_t)(wn + (lane & 7) + ((lane >> 4) & 1) * 8);
    uint32_t bKb  = ((lane >> 3) & 1) * 16u;

    int nc = K >> 6;
    uint4 av[4], bv[4];
#pragma unroll
    for (int rr = 0; rr < 4; ++rr) {
        av[rr] = *(const uint4*)(aptr[rr]);
        bv[rr] = *(const uint4*)(bptr[rr]);
    }

    for (int c = 0; c < nc; ++c) {
        __syncthreads();
#pragma unroll
        for (int rr = 0; rr < 4; ++rr) {
            int row = r4 + rr * 32;
            uint32_t off = sw128((uint32_t)row * 128 + (uint32_t)li * 16);
            *(uint4*)((char*)sA + off) = av[rr];
            *(uint4*)((char*)sB + off) = bv[rr];
        }
        __syncthreads();
        if (c + 1 < nc) {
#pragma unroll
            for (int rr = 0; rr < 4; ++rr) {
                av[rr] = *(const uint4*)(aptr[rr] + (c + 1) * 64);
                bv[rr] = *(const uint4*)(bptr[rr] + (c + 1) * 64);
            }
        }
#pragma unroll
        for (int kk = 0; kk < 4; ++kk) {
            uint32_t afr[4][4];
#pragma unroll
            for (int fm = 0; fm < 4; ++fm) {
                uint32_t off = (aRow + fm * 16) * 128 + (kk * 32 + aKb);
                ldmx4(afr[fm], sAu + sw128(off));
            }
            uint32_t bfr[2][4];
#pragma unroll
            for (int fn2 = 0; fn2 < 2; ++fn2) {
                uint32_t off = (bRow + fn2 * 16) * 128 + (kk * 32 + bKb);
                ldmx4(bfr[fn2], sBu + sw128(off));
            }
#pragma unroll
            for (int fm = 0; fm < 4; ++fm)
#pragma unroll
                for (int fn = 0; fn < 4; ++fn)
                    mma16816(acc[fm][fn], afr[fm],
                             bfr[fn >> 1][(fn & 1) * 2], bfr[fn >> 1][(fn & 1) * 2 + 1]);
        }
    }

    int rbase = lane >> 2;
    int cbase = (lane & 3) * 2;
#pragma unroll
    for (int fm = 0; fm < 4; ++fm) {
#pragma unroll
        for (int half_ = 0; half_ < 2; ++half_) {
            int rloc = wm + fm * 16 + rbase + half_ * 8;
            int rowi = m0 + rloc;
            bool valid = (MODE == 0 || MODE == 1 || MODE == 4) || (rowi < cntE);
            if (!valid) continue;
            int tok = 0;
            float gt = 0.f;
            if (MODE == 3) { tok = g_perm[rowbase + rowi]; gt = g_gate[tok]; }
#pragma unroll
            for (int fn = 0; fn < 4; ++fn) {
                int col = n0 + wn + fn * 8 + cbase;
                float v0 = acc[fm][fn][half_ * 2 + 0] + bias[col];
                float v1 = acc[fm][fn][half_ * 2 + 1] + bias[col + 1];
                if (MODE == 0) {
                    float* o = Cf + (size_t)rowi * N + col;
                    o[0] = v0; o[1] = v1;
                } else if (MODE == 1) {
                    float* o = Cf + (size_t)rowi * N + col;
                    const float* rr_ = R + (size_t)rowi * N + col;
                    o[0] = v0 + rr_[0]; o[1] = v1 + rr_[1];
                } else if (MODE == 2) {
                    float gl0 = 0.5f * v0 * (1.0f + erff(v0 * 0.70710678118654752f));
                    float gl1 = 0.5f * v1 * (1.0f + erff(v1 * 0.70710678118654752f));
                    *(__half2*)(Cb + (size_t)(rowbase + rowi) * N + col) =
                        __floats2half2_rn(gl0, gl1);
                } else if (MODE == 3) {
                    float* o = Cf + (size_t)tok * N + col;
                    const float* rr_ = R + (size_t)tok * N + col;
                    o[0] = rr_[0] + gt * v0;
                    o[1] = rr_[1] + gt * v1;
                } else {
                    *(__half2*)(Cb + (size_t)rowi * N + col) = __floats2half2_rn(v0, v1);
                }
            }
        }
    }
}

// ---------------- tensor-core fused attention ----------------
// one (b,h,qtile64) per block; 256 threads = 8 warps.
__global__ __launch_bounds__(256)
void attn_tc(const __half* __restrict__ Q, const __half* __restrict__ Kx,
             const __half* __restrict__ V, __half* __restrict__ O)
{
    extern __shared__ char sm[];
    __half* sQ  = (__half*)(sm + ATT_Q);
    __half* sKV = (__half*)(sm + ATT_KV);
    __half* sP  = (__half*)(sm + ATT_P);
    float*  sc  = (float*)(sm + ATT_SC);
    __shared__ float red[256];

    int bh = blockIdx.x;
    int b = bh / kH, h = bh % kH;
    int qt = blockIdx.y;
    int tid = threadIdx.x, wid = tid >> 5, lane = tid & 31;
    uint32_t sQu = smem_u32(sQ), sKVu = smem_u32(sKV), sPu = smem_u32(sP);

    // load Q tile [64 q][64 d] swizzled
    for (int idx = tid; idx < 512; idx += 256) {
        int i = idx >> 3, dv = (idx & 7) * 8;
        int s = qt * 64 + i;
        uint4 v4 = *(const uint4*)(Q + (size_t)(s * kB + b) * kD + h * kHD + dv);
        *(uint4*)((char*)sQ + sw128((uint32_t)i * 128 + dv * 2)) = v4;
    }

    int wm = (wid & 3) * 16, wn = (wid >> 2) * 32;
    uint32_t aRow = (uint32_t)(wm + (lane & 15));
    uint32_t aKb  = (lane & 16) ? 16u : 0u;
    uint32_t bRow = (uint32_t)(wn + (lane & 7) + ((lane >> 4) & 1) * 8);
    uint32_t bKb  = ((lane >> 3) & 1) * 16u;
    int crow = lane >> 2, ccol = (lane & 3) * 2;

    // ---- score phase: S = Q K^T / 8 ----
    for (int kt = 0; kt < 8; ++kt) {
        __syncthreads();
        for (int idx = tid; idx < 512; idx += 256) {
            int i = idx >> 3, dv = (idx & 7) * 8;
            int s = kt * 64 + i;
            uint4 v4 = *(const uint4*)(Kx + (size_t)(s * kB + b) * kD + h * kHD + dv);
            *(uint4*)((char*)sKV + sw128((uint32_t)i * 128 + dv * 2)) = v4;
        }
        __syncthreads();
        float acc[4][4];
#pragma unroll
        for (int fn = 0; fn < 4; ++fn)
#pragma unroll
            for (int v = 0; v < 4; ++v) acc[fn][v] = 0.f;
#pragma unroll
        for (int kk = 0; kk < 4; ++kk) {
            uint32_t af[4];
            ldmx4(af, sQu + sw128(aRow * 128 + kk * 32 + aKb));
            uint32_t bfr[2][4];
#pragma unroll
            for (int fn2 = 0; fn2 < 2; ++fn2)
                ldmx4(bfr[fn2], sKVu + sw128((bRow + fn2 * 16) * 128 + kk * 32 + bKb));
#pragma unroll
            for (int fn = 0; fn < 4; ++fn)
                mma16816(acc[fn], af, bfr[fn >> 1][(fn & 1) * 2], bfr[fn >> 1][(fn & 1) * 2 + 1]);
        }
#pragma unroll
        for (int fn = 0; fn < 4; ++fn) {
            int col = kt * 64 + wn + fn * 8 + ccol;
            sc[(wm + crow) * SCP2 + col]         = acc[fn][0] * 0.125f;
            sc[(wm + crow) * SCP2 + col + 1]     = acc[fn][1] * 0.125f;
            sc[(wm + crow + 8) * SCP2 + col]     = acc[fn][2] * 0.125f;
            sc[(wm + crow + 8) * SCP2 + col + 1] = acc[fn][3] * 0.125f;
        }
    }
    __syncthreads();

    // ---- softmax (fp32) + pack P to half chunks ----
    int row = tid & 63, part = tid >> 6;
    float* srow = sc + row * SCP2 + part * 128;
    float m = -1e30f;
    for (int c = 0; c < 128; ++c) m = fmaxf(m, srow[c]);
    red[row * 4 + part] = m;
    __syncthreads();
    m = fmaxf(fmaxf(red[row * 4 + 0], red[row * 4 + 1]),
              fmaxf(red[row * 4 + 2], red[row * 4 + 3]));
    float ssum = 0.f;
    for (int c = 0; c < 128; ++c) { float e = expf(srow[c] - m); srow[c] = e; ssum += e; }
    __syncthreads();
    red[row * 4 + part] = ssum;
    __syncthreads();
    float inv = 1.0f / (red[row * 4 + 0] + red[row * 4 + 1] +
                        red[row * 4 + 2] + red[row * 4 + 3]);
    for (int c = 0; c < 128; ++c) {
        int gcol = part * 128 + c;
        int kt2 = gcol >> 6, cw = gcol & 63;
        *(__half*)((char*)sP + kt2 * 8192 + sw128((uint32_t)row * 128 + cw * 2)) =
            __float2half(srow[c] * inv);
    }
    __syncthreads();

    // ---- PV phase: O = P @ V ----
    float o[4][4];
#pragma unroll
    for (int fn = 0; fn < 4; ++fn)
#pragma unroll
        for (int v = 0; v < 4; ++v) o[fn][v] = 0.f;

    for (int kt = 0; kt < 8; ++kt) {
        if (kt) __syncthreads();
        // load V tile transposed: smem[dim][key]
        for (int idx = tid; idx < 512; idx += 256) {
            int i = idx >> 3, dv = (idx & 7) * 8;   // key i, dims dv..dv+7
            int s = kt * 64 + i;
            union { uint4 u; __half hh[8]; } vv;
            vv.u = *(const uint4*)(V + (size_t)(s * kB + b) * kD + h * kHD + dv);
#pragma unroll
            for (int j = 0; j < 8; ++j)
                *(__half*)((char*)sKV + sw128((uint32_t)(dv + j) * 128 + i * 2)) = vv.hh[j];
        }
        __syncthreads();
#pragma unroll
        for (int kk = 0; kk < 4; ++kk) {
            uint32_t af[4];
            ldmx4(af, sPu + kt * 8192 + sw128(aRow * 128 + kk * 32 + aKb));
            uint32_t bfr[2][4];
#pragma unroll
            for (int fn2 = 0; fn2 < 2; ++fn2)
                ldmx4(bfr[fn2], sKVu + sw128((bRow + fn2 * 16) * 128 + kk * 32 + bKb));
#pragma unroll
            for (int fn = 0; fn < 4; ++fn)
                mma16816(o[fn], af, bfr[fn >> 1][(fn & 1) * 2], bfr[fn >> 1][(fn & 1) * 2 + 1]);
        }
    }

    // write O (half)
#pragma unroll
    for (int fn = 0; fn < 4; ++fn) {
        int col = wn + fn * 8 + ccol;
        int s0 = qt * 64 + wm + crow;
        int s1 = s0 + 8;
        *(__half2*)(O + (size_t)(s0 * kB + b) * kD + h * kHD + col) =
            __floats2half2_rn(o[fn][0], o[fn][1]);
        *(__half2*)(O + (size_t)(s1 * kB + b) * kD + h * kHD + col) =
            __floats2half2_rn(o[fn][2], o[fn][3]);
    }
}

// ---------------- router ----------------
__global__ void router_kernel(const float* __restrict__ tin, const float* __restrict__ wg,
                              const float* __restrict__ bg)
{
    int warp = threadIdx.x >> 5;
    int tok  = blockIdx.x * 8 + warp;
    int lane = threadIdx.x & 31;
    const float* row = tin + (size_t)tok * kD;
    int e = lane >> 2, j = lane & 3;
    float s = 0.f;
    for (int d = j; d < kD; d += 4) s += row[d] * wg[d * kE + e];
    s += __shfl_xor_sync(0xffffffffu, s, 1);
    s += __shfl_xor_sync(0xffffffffu, s, 2);
    s += bg[e];
    float lg[kE];
#pragma unroll
    for (int ee = 0; ee < kE; ++ee) lg[ee] = __shfl_sync(0xffffffffu, s, ee * 4);
    if (lane == 0) {
        int best = 0; float bm = lg[0];
#pragma unroll
        for (int ee = 1; ee < kE; ++ee) if (lg[ee] > bm) { bm = lg[ee]; best = ee; }
        float se = 0.f;
#pragma unroll
        for (int ee = 0; ee < kE; ++ee) se += expf(lg[ee] - bm);
        g_idx[tok]  = best;
        g_gate[tok] = 1.0f / se;
        atomicAdd(&g_cnt[best], 1);
    }
}

__global__ void init_kernel()
{
    int t = threadIdx.x;
    if (t < kE) { g_cnt[t] = 0; g_fill[t] = 0; }
}

__global__ void prefix_kernel()
{
    int acc = 0;
    for (int e = 0; e < kE; ++e) { g_off[e] = acc; acc += g_cnt[e]; }
}

__global__ void scatter_kernel()
{
    int t = blockIdx.x * 256 + threadIdx.x;
    int e = g_idx[t];
    int p = atomicAdd(&g_fill[e], 1);
    g_perm[g_off[e] + p] = t;
}

// ---------------- launch ----------------
extern "C" void kernel_launch(void* const* d_in, const int* in_sizes, int n_in,
                              void* d_out, int out_size)
{
    const float* x    = (const float*)d_in[0];
    const float* ln1w = (const float*)d_in[1];
    const float* ln1b = (const float*)d_in[2];
    const float* wq   = (const float*)d_in[3];
    const float* bq   = (const float*)d_in[4];
    const float* wk   = (const float*)d_in[5];
    const float* bk   = (const float*)d_in[6];
    const float* wv   = (const float*)d_in[7];
    const float* bv   = (const float*)d_in[8];
    const float* wo   = (const float*)d_in[9];
    const float* bo   = (const float*)d_in[10];
    const float* ln2w = (const float*)d_in[11];
    const float* ln2b = (const float*)d_in[12];
    const float* wg   = (const float*)d_in[13];
    const float* bg   = (const float*)d_in[14];
    const float* w1   = (const float*)d_in[15];
    const float* b1   = (const float*)d_in[16];
    const float* w2   = (const float*)d_in[17];
    const float* b2   = (const float*)d_in[18];
    float* out = (float*)d_out;

    float *p_x1, *p_t;
    __half *p_wqt, *p_wkt, *p_wvt, *p_wot, *p_w1t, *p_w2t;
    __half *p_qin_h, *p_x_h, *p_qh, *p_kh, *p_vh, *p_attn_h, *p_t_h, *p_h_h;
    cudaGetSymbolAddress((void**)&p_x1,   g_x1);
    cudaGetSymbolAddress((void**)&p_t,    g_tn);
    cudaGetSymbolAddress((void**)&p_wqt,  g_wqt);
    cudaGetSymbolAddress((void**)&p_wkt,  g_wkt);
    cudaGetSymbolAddress((void**)&p_wvt,  g_wvt);
    cudaGetSymbolAddress((void**)&p_wot,  g_wot);
    cudaGetSymbolAddress((void**)&p_w1t,  g_w1t);
    cudaGetSymbolAddress((void**)&p_w2t,  g_w2t);
    cudaGetSymbolAddress((void**)&p_qin_h, g_qin_h);
    cudaGetSymbolAddress((void**)&p_x_h,   g_x_h);
    cudaGetSymbolAddress((void**)&p_qh,    g_qh);
    cudaGetSymbolAddress((void**)&p_kh,    g_kh);
    cudaGetSymbolAddress((void**)&p_vh,    g_vh);
    cudaGetSymbolAddress((void**)&p_attn_h, g_attn_h);
    cudaGetSymbolAddress((void**)&p_t_h,   g_t_h);
    cudaGetSymbolAddress((void**)&p_h_h,   g_h_h);

    cudaFuncSetAttribute(attn_tc, cudaFuncAttributeMaxDynamicSharedMemorySize, ATTN_SMEM);

    // weight convert + transpose (fp32 [K,N] -> fp16 [N,K])
    dim3 tcb(32, 8);
    tconv_kernel<<<dim3(kD / 32, kD / 32, 1), tcb>>>(wq, p_wqt, kD, kD);
    tconv_kernel<<<dim3(kD / 32, kD / 32, 1), tcb>>>(wk, p_wkt, kD, kD);
    tconv_kernel<<<dim3(kD / 32, kD / 32, 1), tcb>>>(wv, p_wvt, kD, kD);
    tconv_kernel<<<dim3(kD / 32, kD / 32, 1), tcb>>>(wo, p_wot, kD, kD);
    tconv_kernel<<<dim3(kHID / 32, kD / 32, kE), tcb>>>(w1, p_w1t, kD, kHID);
    tconv_kernel<<<dim3(kD / 32, kHID / 32, kE), tcb>>>(w2, p_w2t, kHID, kD);

    // LN1 -> qin (half) ; x -> half
    ln_kernel<0><<<kT, 256>>>(x, ln1w, ln1b, nullptr, p_qin_h);
    int n4 = kT * kD / 4;
    conv_kernel<<<(n4 + 255) / 256, 256>>>(x, p_x_h, n4);

    // QKV projections (half out)
    dim3 g0(kT / 128, kD / 128);
    tc_gemm<4><<<g0, 256>>>(p_qin_h, p_wqt, bq, nullptr, nullptr, p_qh, kT, kD, kD);
    tc_gemm<4><<<g0, 256>>>(p_x_h,   p_wkt, bk, nullptr, nullptr, p_kh, kT, kD, kD);
    tc_gemm<4><<<g0, 256>>>(p_x_h,   p_wvt, bv, nullptr, nullptr, p_vh, kT, kD, kD);

    // tensor-core fused attention (half out)
    attn_tc<<<dim3(kB * kH, kS / 64), 256, ATTN_SMEM>>>(p_qh, p_kh, p_vh, p_attn_h);

    // out projection + residual -> x1 (fp32)
    tc_gemm<1><<<g0, 256>>>(p_attn_h, p_wot, bo, x, p_x1, nullptr, kT, kD, kD);

    // LN2 -> t (fp32 for router) + t_h (half for gemms)
    ln_kernel<1><<<kT, 256>>>(p_x1, ln2w, ln2b, p_t, p_t_h);

    // routing
    init_kernel<<<1, 32>>>();
    router_kernel<<<kT / 8, 256>>>(p_t, wg, bg);
    prefix_kernel<<<1, 1>>>();
    scatter_kernel<<<kT / 256, 256>>>();

    // MoE expert GEMMs
    tc_gemm<2><<<dim3(kT / 128, kHID / 128, kE), 256>>>(
        p_t_h, p_w1t, b1, nullptr, nullptr, p_h_h, kT, kHID, kD);
    tc_gemm<3><<<dim3(kT / 128, kD / 128, kE), 256>>>(
        p_h_h, p_w2t, b2, p_x1, out, nullptr, kT, kD, kHID);
}

// round 8
// speedup vs baseline: 4.8497x; 1.1690x over previous
#include <cuda_runtime.h>
#include <cuda_fp16.h>
#include <math.h>
#include <stdint.h>

// ---------------- problem constants ----------------
constexpr int kS   = 512;
constexpr int kB   = 16;
constexpr int kD   = 768;
constexpr int kH   = 12;
constexpr int kHD  = 64;
constexpr int kE   = 8;
constexpr int kHID = 3072;
constexpr int kT   = kS * kB;          // 8192 tokens

// attention smem layout (bytes)
constexpr int ATT_Q  = 0;              // 64x64 half swizzled          (8192)
constexpr int ATT_KV = 8192;           // 2 x 64x64 half swizzled      (16384)
constexpr int ATT_P  = 24576;          // 8 chunks of 64x64 half       (65536)
constexpr int ATT_SC = 90112;          // 64x520 fp32                  (133120)
constexpr int SCP2   = 520;
constexpr int ATTN_SMEM = ATT_SC + 64 * SCP2 * 4;   // 223232

// gemm smem: 2 buffers x (A 16KB + B 16KB)
constexpr int GEMM_SMEM = 65536;

// ---------------- scratch (device globals; no allocations) ----------------
__device__ float g_x1  [kT * kD];
__device__ float g_tn  [kT * kD];
__device__ float g_gate[kT];
__device__ int   g_idx [kT];
__device__ int   g_cnt [kE];
__device__ int   g_off [kE];
__device__ int   g_fill[kE];
__device__ int   g_perm[kT];

// fp16 scratch
__device__ __half g_wqt[kD * kD];
__device__ __half g_wkt[kD * kD];
__device__ __half g_wvt[kD * kD];
__device__ __half g_wot[kD * kD];
__device__ __half g_w1t[(size_t)kE * kHID * kD];   // [E][HID][D]
__device__ __half g_w2t[(size_t)kE * kD * kHID];   // [E][D][HID]
__device__ __half g_qin_h[kT * kD];
__device__ __half g_x_h  [kT * kD];
__device__ __half g_qh   [kT * kD];
__device__ __half g_kh   [kT * kD];
__device__ __half g_vh   [kT * kD];
__device__ __half g_attn_h[kT * kD];
__device__ __half g_t_h  [kT * kD];
__device__ __half g_h_h  [(size_t)kT * kHID];

// ---------------- helpers ----------------
__device__ __forceinline__ uint32_t smem_u32(const void* p) {
    uint32_t a;
    asm("{ .reg .u64 t; cvta.to.shared.u64 t, %1; cvt.u32.u64 %0, t; }" : "=r"(a) : "l"(p));
    return a;
}
__device__ __forceinline__ void ldmx4(uint32_t* r, uint32_t addr) {
    asm volatile("ldmatrix.sync.aligned.m8n8.x4.shared.b16 {%0,%1,%2,%3}, [%4];"
                 : "=r"(r[0]), "=r"(r[1]), "=r"(r[2]), "=r"(r[3]) : "r"(addr));
}
__device__ __forceinline__ void ldmx4t(uint32_t* r, uint32_t addr) {
    asm volatile("ldmatrix.sync.aligned.m8n8.x4.trans.shared.b16 {%0,%1,%2,%3}, [%4];"
                 : "=r"(r[0]), "=r"(r[1]), "=r"(r[2]), "=r"(r[3]) : "r"(addr));
}
__device__ __forceinline__ void mma16816(float* d, const uint32_t* a, uint32_t b0, uint32_t b1) {
    asm volatile(
        "mma.sync.aligned.m16n8k16.row.col.f32.f16.f16.f32 "
        "{%0,%1,%2,%3}, {%4,%5,%6,%7}, {%8,%9}, {%0,%1,%2,%3};"
        : "+f"(d[0]), "+f"(d[1]), "+f"(d[2]), "+f"(d[3])
        : "r"(a[0]), "r"(a[1]), "r"(a[2]), "r"(a[3]), "r"(b0), "r"(b1));
}
__device__ __forceinline__ uint32_t sw128(uint32_t off) {
    return off ^ ((off >> 3) & 0x70);
}
__device__ __forceinline__ void cp16(uint32_t dst, const void* src) {
    asm volatile("cp.async.ca.shared.global [%0], [%1], 16;" :: "r"(dst), "l"(src));
}
#define CP_COMMIT() asm volatile("cp.async.commit_group;" ::: "memory")
#define CP_WAIT0()  asm volatile("cp.async.wait_group 0;" ::: "memory")

// ---------------- layernorm variants ----------------
template <int LNOUT>
__global__ void ln_kernel(const float* __restrict__ x, const float* __restrict__ w,
                          const float* __restrict__ bias,
                          float* __restrict__ outf, __half* __restrict__ outh)
{
    int t = blockIdx.x;
    const float* r = x + (size_t)t * kD;
    int tid = threadIdx.x;
    float v0 = r[tid], v1 = r[tid + 256], v2 = r[tid + 512];
    float s = v0 + v1 + v2;
    float q = v0 * v0 + v1 * v1 + v2 * v2;
#pragma unroll
    for (int o = 16; o > 0; o >>= 1) {
        s += __shfl_down_sync(0xffffffffu, s, o);
        q += __shfl_down_sync(0xffffffffu, q, o);
    }
    __shared__ float rs[8], rq[8];
    if ((tid & 31) == 0) { rs[tid >> 5] = s; rq[tid >> 5] = q; }
    __syncthreads();
    s = 0.f; q = 0.f;
#pragma unroll
    for (int i = 0; i < 8; ++i) { s += rs[i]; q += rq[i]; }
    float mean = s * (1.0f / kD);
    float var  = q * (1.0f / kD) - mean * mean;
    float inv  = rsqrtf(var + 1e-5f);
    float o0 = (v0 - mean) * inv * w[tid]       + bias[tid];
    float o1 = (v1 - mean) * inv * w[tid + 256] + bias[tid + 256];
    float o2 = (v2 - mean) * inv * w[tid + 512] + bias[tid + 512];
    if (LNOUT == 1) {
        float* of = outf + (size_t)t * kD;
        of[tid] = o0; of[tid + 256] = o1; of[tid + 512] = o2;
    }
    __half* oh = outh + (size_t)t * kD;
    oh[tid]       = __float2half(o0);
    oh[tid + 256] = __float2half(o1);
    oh[tid + 512] = __float2half(o2);
}

// ---------------- fp32 -> fp16 convert ----------------
__global__ void conv_kernel(const float* __restrict__ in, __half* __restrict__ out, int n4)
{
    int i = blockIdx.x * 256 + threadIdx.x;
    if (i >= n4) return;
    float4 v = ((const float4*)in)[i];
    ((__half2*)out)[2 * i]     = __floats2half2_rn(v.x, v.y);
    ((__half2*)out)[2 * i + 1] = __floats2half2_rn(v.z, v.w);
}

// ---------------- fp32 [R,C] -> fp16 [C,R] transpose-convert ----------------
__global__ void tconv_kernel(const float* __restrict__ in, __half* __restrict__ out,
                             int R, int C)
{
    __shared__ float tile[32][33];
    int e = blockIdx.z;
    in  += (size_t)e * R * C;
    out += (size_t)e * R * C;
    int c0 = blockIdx.x * 32, r0 = blockIdx.y * 32;
    int tx = threadIdx.x;
    for (int i = threadIdx.y; i < 32; i += 8)
        tile[i][tx] = in[(size_t)(r0 + i) * C + c0 + tx];
    __syncthreads();
    for (int i = threadIdx.y; i < 32; i += 8)
        out[(size_t)(c0 + i) * R + r0 + tx] = __float2half(tile[tx][i]);
}

// ---------------- fp16 mma.sync GEMM, 128x128 tile, cp.async 2-stage ----------------
// MODE 0: Cf = A@W + bias
// MODE 1: Cf = R + A@W + bias
// MODE 2: gathered rows via g_perm, gelu -> Cb (half) at sorted rows
// MODE 3: contiguous sorted rows, Cf[tok] = R[tok] + gate[tok]*(A@W+bias)
// MODE 4: Cb = half(A@W + bias)
template <int MODE>
__global__ __launch_bounds__(256)
void tc_gemm(const __half* __restrict__ A, const __half* __restrict__ Wt,
             const float* __restrict__ bias, const float* __restrict__ R,
             float* __restrict__ Cf, __half* __restrict__ Cb,
             int M, int N, int K)
{
    int cntE = M, rowbase = 0;
    if (MODE == 2 || MODE == 3) {
        int e = blockIdx.z;
        cntE = g_cnt[e];
        rowbase = g_off[e];
        if ((int)(blockIdx.x * 128) >= cntE) return;
        Wt   += (size_t)e * K * N;
        bias += (size_t)e * N;
    }
    int m0 = blockIdx.x * 128, n0 = blockIdx.y * 128;
    int tid = threadIdx.x, wid = tid >> 5, lane = tid & 31;
    int wm = (wid & 1) * 64;
    int wn = (wid >> 1) * 32;

    extern __shared__ char dynsm[];
    // layout: A0 16K | B0 16K | A1 16K | B1 16K
    uint32_t sAu = smem_u32(dynsm);
    uint32_t sBu = sAu + 16384;

    int li = tid & 7, r4 = tid >> 3;
    const __half* aptr[4];
    const __half* bptr[4];
#pragma unroll
    for (int rr = 0; rr < 4; ++rr) {
        int row = r4 + rr * 32;
        int lr = m0 + row;
        const __half* ap;
        if (MODE == 2) {
            int gr = (lr < cntE) ? g_perm[rowbase + lr] : 0;
            ap = A + (size_t)gr * K;
        } else if (MODE == 3) {
            ap = A + (size_t)(rowbase + (lr < cntE ? lr : 0)) * K;
        } else {
            ap = A + (size_t)lr * K;
        }
        aptr[rr] = ap + li * 8;
        bptr[rr] = Wt + (size_t)(n0 + row) * K + li * 8;
    }
    uint32_t soff[4];
#pragma unroll
    for (int rr = 0; rr < 4; ++rr)
        soff[rr] = sw128((uint32_t)(r4 + rr * 32) * 128 + (uint32_t)li * 16);

    float acc[4][4][4];
#pragma unroll
    for (int i = 0; i < 4; ++i)
#pragma unroll
        for (int j = 0; j < 4; ++j)
#pragma unroll
            for (int v = 0; v < 4; ++v) acc[i][j][v] = 0.f;

    uint32_t aRow = (uint32_t)(wm + (lane & 15));
    uint32_t aKb  = (lane & 16) ? 16u : 0u;
    uint32_t bRow = (uint32_t)(wn + (lane & 7) + ((lane >> 4) & 1) * 8);
    uint32_t bKb  = ((lane >> 3) & 1) * 16u;

    int nc = K >> 6;

    auto issue = [&](int c, int buf) {
        uint32_t bo = (uint32_t)buf * 32768u;
#pragma unroll
        for (int rr = 0; rr < 4; ++rr) {
            cp16(sAu + bo + soff[rr], aptr[rr] + c * 64);
            cp16(sBu + bo + soff[rr], bptr[rr] + c * 64);
        }
        CP_COMMIT();
    };

    issue(0, 0);
    for (int c = 0; c < nc; ++c) {
        CP_WAIT0();
        __syncthreads();
        if (c + 1 < nc) issue(c + 1, (c + 1) & 1);
        uint32_t bo = (uint32_t)(c & 1) * 32768u;
#pragma unroll
        for (int kk = 0; kk < 4; ++kk) {
            uint32_t afr[4][4];
#pragma unroll
            for (int fm = 0; fm < 4; ++fm)
                ldmx4(afr[fm], sAu + bo + sw128((aRow + fm * 16) * 128 + kk * 32 + aKb));
            uint32_t bfr[2][4];
#pragma unroll
            for (int fn2 = 0; fn2 < 2; ++fn2)
                ldmx4(bfr[fn2], sBu + bo + sw128((bRow + fn2 * 16) * 128 + kk * 32 + bKb));
#pragma unroll
            for (int fm = 0; fm < 4; ++fm)
#pragma unroll
                for (int fn = 0; fn < 4; ++fn)
                    mma16816(acc[fm][fn], afr[fm],
                             bfr[fn >> 1][(fn & 1) * 2], bfr[fn >> 1][(fn & 1) * 2 + 1]);
        }
        __syncthreads();
    }

    int rbase = lane >> 2;
    int cbase = (lane & 3) * 2;
#pragma unroll
    for (int fm = 0; fm < 4; ++fm) {
#pragma unroll
        for (int half_ = 0; half_ < 2; ++half_) {
            int rloc = wm + fm * 16 + rbase + half_ * 8;
            int rowi = m0 + rloc;
            bool valid = (MODE == 0 || MODE == 1 || MODE == 4) || (rowi < cntE);
            if (!valid) continue;
            int tok = 0;
            float gt = 0.f;
            if (MODE == 3) { tok = g_perm[rowbase + rowi]; gt = g_gate[tok]; }
#pragma unroll
            for (int fn = 0; fn < 4; ++fn) {
                int col = n0 + wn + fn * 8 + cbase;
                float v0 = acc[fm][fn][half_ * 2 + 0] + bias[col];
                float v1 = acc[fm][fn][half_ * 2 + 1] + bias[col + 1];
                if (MODE == 0) {
                    float* o = Cf + (size_t)rowi * N + col;
                    o[0] = v0; o[1] = v1;
                } else if (MODE == 1) {
                    float* o = Cf + (size_t)rowi * N + col;
                    const float* rr_ = R + (size_t)rowi * N + col;
                    o[0] = v0 + rr_[0]; o[1] = v1 + rr_[1];
                } else if (MODE == 2) {
                    float gl0 = 0.5f * v0 * (1.0f + erff(v0 * 0.70710678118654752f));
                    float gl1 = 0.5f * v1 * (1.0f + erff(v1 * 0.70710678118654752f));
                    *(__half2*)(Cb + (size_t)(rowbase + rowi) * N + col) =
                        __floats2half2_rn(gl0, gl1);
                } else if (MODE == 3) {
                    float* o = Cf + (size_t)tok * N + col;
                    const float* rr_ = R + (size_t)tok * N + col;
                    o[0] = rr_[0] + gt * v0;
                    o[1] = rr_[1] + gt * v1;
                } else {
                    *(__half2*)(Cb + (size_t)rowi * N + col) = __floats2half2_rn(v0, v1);
                }
            }
        }
    }
}

// ---------------- tensor-core fused attention, cp.async pipelined ----------------
__global__ __launch_bounds__(256)
void attn_tc(const __half* __restrict__ Q, const __half* __restrict__ Kx,
             const __half* __restrict__ V, __half* __restrict__ O)
{
    extern __shared__ char sm[];
    uint32_t sQu  = smem_u32(sm + ATT_Q);
    uint32_t sKVu = smem_u32(sm + ATT_KV);
    uint32_t sPu  = smem_u32(sm + ATT_P);
    float*   sc   = (float*)(sm + ATT_SC);
    __shared__ float red[256];

    int bh = blockIdx.x;
    int b = bh / kH, h = bh % kH;
    int qt = blockIdx.y;
    int tid = threadIdx.x, wid = tid >> 5, lane = tid & 31;

    // per-thread tile-load coords: 2 x 16B per tile
    int i0 = tid >> 3, dv0 = (tid & 7) * 8;
    int i1 = (tid + 256) >> 3, dv1 = (tid & 7) * 8;
    uint32_t so0 = sw128((uint32_t)i0 * 128 + dv0 * 2);
    uint32_t so1 = sw128((uint32_t)i1 * 128 + dv1 * 2);

    auto issueTile = [&](const __half* src, int kt, int buf) {
        uint32_t bo = (uint32_t)buf * 8192u;
        int s0 = kt * 64 + i0, s1 = kt * 64 + i1;
        cp16(sKVu + bo + so0, src + (size_t)(s0 * kB + b) * kD + h * kHD + dv0);
        cp16(sKVu + bo + so1, src + (size_t)(s1 * kB + b) * kD + h * kHD + dv1);
        CP_COMMIT();
    };

    // Q load + first K tile (committed together)
    {
        int s0 = qt * 64 + i0, s1 = qt * 64 + i1;
        cp16(sQu + so0, Q + (size_t)(s0 * kB + b) * kD + h * kHD + dv0);
        cp16(sQu + so1, Q + (size_t)(s1 * kB + b) * kD + h * kHD + dv1);
    }
    issueTile(Kx, 0, 0);

    int wm = (wid & 3) * 16, wn = (wid >> 2) * 32;
    uint32_t aRow = (uint32_t)(wm + (lane & 15));
    uint32_t aKb  = (lane & 16) ? 16u : 0u;
    uint32_t bRow = (uint32_t)(wn + (lane & 7) + ((lane >> 4) & 1) * 8);
    uint32_t bKb  = ((lane >> 3) & 1) * 16u;
    int crow = lane >> 2, ccol = (lane & 3) * 2;
    // trans-V addressing
    uint32_t vKey = (uint32_t)(((lane >> 3) & 1) * 8 + (lane & 7));
    uint32_t vDim = (uint32_t)(wn + ((lane >> 4) & 1) * 8) * 2;

    // ---- score phase: S = Q K^T / 8 ----
    for (int kt = 0; kt < 8; ++kt) {
        CP_WAIT0();
        __syncthreads();
        if (kt + 1 < 8) issueTile(Kx, kt + 1, (kt + 1) & 1);
        uint32_t bo = (uint32_t)(kt & 1) * 8192u;
        float acc[4][4];
#pragma unroll
        for (int fn = 0; fn < 4; ++fn)
#pragma unroll
            for (int v = 0; v < 4; ++v) acc[fn][v] = 0.f;
#pragma unroll
        for (int kk = 0; kk < 4; ++kk) {
            uint32_t af[4];
            ldmx4(af, sQu + sw128(aRow * 128 + kk * 32 + aKb));
            uint32_t bfr[2][4];
#pragma unroll
            for (int fn2 = 0; fn2 < 2; ++fn2)
                ldmx4(bfr[fn2], sKVu + bo + sw128((bRow + fn2 * 16) * 128 + kk * 32 + bKb));
#pragma unroll
            for (int fn = 0; fn < 4; ++fn)
                mma16816(acc[fn], af, bfr[fn >> 1][(fn & 1) * 2], bfr[fn >> 1][(fn & 1) * 2 + 1]);
        }
#pragma unroll
        for (int fn = 0; fn < 4; ++fn) {
            int col = kt * 64 + wn + fn * 8 + ccol;
            sc[(wm + crow) * SCP2 + col]         = acc[fn][0] * 0.125f;
            sc[(wm + crow) * SCP2 + col + 1]     = acc[fn][1] * 0.125f;
            sc[(wm + crow + 8) * SCP2 + col]     = acc[fn][2] * 0.125f;
            sc[(wm + crow + 8) * SCP2 + col + 1] = acc[fn][3] * 0.125f;
        }
        __syncthreads();
    }

    // ---- softmax (fp32) + pack P to half chunks ----
    int row = tid & 63, part = tid >> 6;
    float* srow = sc + row * SCP2 + part * 128;
    float m = -1e30f;
    for (int c = 0; c < 128; ++c) m = fmaxf(m, srow[c]);
    red[row * 4 + part] = m;
    __syncthreads();
    m = fmaxf(fmaxf(red[row * 4 + 0], red[row * 4 + 1]),
              fmaxf(red[row * 4 + 2], red[row * 4 + 3]));
    float ssum = 0.f;
    for (int c = 0; c < 128; ++c) { float e = expf(srow[c] - m); srow[c] = e; ssum += e; }
    __syncthreads();
    red[row * 4 + part] = ssum;
    __syncthreads();
    float inv = 1.0f / (red[row * 4 + 0] + red[row * 4 + 1] +
                        red[row * 4 + 2] + red[row * 4 + 3]);
    for (int c = 0; c < 128; ++c) {
        int gcol = part * 128 + c;
        int kt2 = gcol >> 6, cw = gcol & 63;
        *(__half*)(sm + ATT_P + kt2 * 8192 + sw128((uint32_t)row * 128 + cw * 2)) =
            __float2half(srow[c] * inv);
    }
    issueTile(V, 0, 0);     // overlap first V load with the tail of softmax
    __syncthreads();

    // ---- PV phase: O = P @ V  (V [key][dim] in smem; ldmatrix.trans) ----
    float o[4][4];
#pragma unroll
    for (int fn = 0; fn < 4; ++fn)
#pragma unroll
        for (int v = 0; v < 4; ++v) o[fn][v] = 0.f;

    for (int kt = 0; kt < 8; ++kt) {
        CP_WAIT0();
        __syncthreads();
        if (kt + 1 < 8) issueTile(V, kt + 1, (kt + 1) & 1);
        uint32_t bo = (uint32_t)(kt & 1) * 8192u;
#pragma unroll
        for (int kk = 0; kk < 4; ++kk) {
            uint32_t af[4];
            ldmx4(af, sPu + kt * 8192 + sw128(aRow * 128 + kk * 32 + aKb));
            uint32_t bfr[2][4];
#pragma unroll
            for (int fn2 = 0; fn2 < 2; ++fn2) {
                uint32_t off = (kk * 16 + vKey) * 128 + vDim + fn2 * 32;
                ldmx4t(bfr[fn2], sKVu + bo + sw128(off));
            }
#pragma unroll
            for (int fn = 0; fn < 4; ++fn)
                mma16816(o[fn], af, bfr[fn >> 1][(fn & 1) * 2], bfr[fn >> 1][(fn & 1) * 2 + 1]);
        }
        __syncthreads();
    }

    // write O (half)
#pragma unroll
    for (int fn = 0; fn < 4; ++fn) {
        int col = wn + fn * 8 + ccol;
        int s0 = qt * 64 + wm + crow;
        int s1 = s0 + 8;
        *(__half2*)(O + (size_t)(s0 * kB + b) * kD + h * kHD + col) =
            __floats2half2_rn(o[fn][0], o[fn][1]);
        *(__half2*)(O + (size_t)(s1 * kB + b) * kD + h * kHD + col) =
            __floats2half2_rn(o[fn][2], o[fn][3]);
    }
}

// ---------------- router ----------------
__global__ void router_kernel(const float* __restrict__ tin, const float* __restrict__ wg,
                              const float* __restrict__ bg)
{
    int warp = threadIdx.x >> 5;
    int tok  = blockIdx.x * 8 + warp;
    int lane = threadIdx.x & 31;
    const float* row = tin + (size_t)tok * kD;
    int e = lane >> 2, j = lane & 3;
    float s = 0.f;
    for (int d = j; d < kD; d += 4) s += row[d] * wg[d * kE + e];
    s += __shfl_xor_sync(0xffffffffu, s, 1);
    s += __shfl_xor_sync(0xffffffffu, s, 2);
    s += bg[e];
    float lg[kE];
#pragma unroll
    for (int ee = 0; ee < kE; ++ee) lg[ee] = __shfl_sync(0xffffffffu, s, ee * 4);
    if (lane == 0) {
        int best = 0; float bm = lg[0];
#pragma unroll
        for (int ee = 1; ee < kE; ++ee) if (lg[ee] > bm) { bm = lg[ee]; best = ee; }
        float se = 0.f;
#pragma unroll
        for (int ee = 0; ee < kE; ++ee) se += expf(lg[ee] - bm);
        g_idx[tok]  = best;
        g_gate[tok] = 1.0f / se;
        atomicAdd(&g_cnt[best], 1);
    }
}

__global__ void init_kernel()
{
    int t = threadIdx.x;
    if (t < kE) { g_cnt[t] = 0; g_fill[t] = 0; }
}

__global__ void prefix_kernel()
{
    int acc = 0;
    for (int e = 0; e < kE; ++e) { g_off[e] = acc; acc += g_cnt[e]; }
}

__global__ void scatter_kernel()
{
    int t = blockIdx.x * 256 + threadIdx.x;
    int e = g_idx[t];
    int p = atomicAdd(&g_fill[e], 1);
    g_perm[g_off[e] + p] = t;
}

// ---------------- launch ----------------
extern "C" void kernel_launch(void* const* d_in, const int* in_sizes, int n_in,
                              void* d_out, int out_size)
{
    const float* x    = (const float*)d_in[0];
    const float* ln1w = (const float*)d_in[1];
    const float* ln1b = (const float*)d_in[2];
    const float* wq   = (const float*)d_in[3];
    const float* bq   = (const float*)d_in[4];
    const float* wk   = (const float*)d_in[5];
    const float* bk   = (const float*)d_in[6];
    const float* wv   = (const float*)d_in[7];
    const float* bv   = (const float*)d_in[8];
    const float* wo   = (const float*)d_in[9];
    const float* bo   = (const float*)d_in[10];
    const float* ln2w = (const float*)d_in[11];
    const float* ln2b = (const float*)d_in[12];
    const float* wg   = (const float*)d_in[13];
    const float* bg   = (const float*)d_in[14];
    const float* w1   = (const float*)d_in[15];
    const float* b1   = (const float*)d_in[16];
    const float* w2   = (const float*)d_in[17];
    const float* b2   = (const float*)d_in[18];
    float* out = (float*)d_out;

    float *p_x1, *p_t;
    __half *p_wqt, *p_wkt, *p_wvt, *p_wot, *p_w1t, *p_w2t;
    __half *p_qin_h, *p_x_h, *p_qh, *p_kh, *p_vh, *p_attn_h, *p_t_h, *p_h_h;
    cudaGetSymbolAddress((void**)&p_x1,   g_x1);
    cudaGetSymbolAddress((void**)&p_t,    g_tn);
    cudaGetSymbolAddress((void**)&p_wqt,  g_wqt);
    cudaGetSymbolAddress((void**)&p_wkt,  g_wkt);
    cudaGetSymbolAddress((void**)&p_wvt,  g_wvt);
    cudaGetSymbolAddress((void**)&p_wot,  g_wot);
    cudaGetSymbolAddress((void**)&p_w1t,  g_w1t);
    cudaGetSymbolAddress((void**)&p_w2t,  g_w2t);
    cudaGetSymbolAddress((void**)&p_qin_h, g_qin_h);
    cudaGetSymbolAddress((void**)&p_x_h,   g_x_h);
    cudaGetSymbolAddress((void**)&p_qh,    g_qh);
    cudaGetSymbolAddress((void**)&p_kh,    g_kh);
    cudaGetSymbolAddress((void**)&p_vh,    g_vh);
    cudaGetSymbolAddress((void**)&p_attn_h, g_attn_h);
    cudaGetSymbolAddress((void**)&p_t_h,   g_t_h);
    cudaGetSymbolAddress((void**)&p_h_h,   g_h_h);

    cudaFuncSetAttribute(attn_tc, cudaFuncAttributeMaxDynamicSharedMemorySize, ATTN_SMEM);
    cudaFuncSetAttribute(tc_gemm<0>, cudaFuncAttributeMaxDynamicSharedMemorySize, GEMM_SMEM);
    cudaFuncSetAttribute(tc_gemm<1>, cudaFuncAttributeMaxDynamicSharedMemorySize, GEMM_SMEM);
    cudaFuncSetAttribute(tc_gemm<2>, cudaFuncAttributeMaxDynamicSharedMemorySize, GEMM_SMEM);
    cudaFuncSetAttribute(tc_gemm<3>, cudaFuncAttributeMaxDynamicSharedMemorySize, GEMM_SMEM);
    cudaFuncSetAttribute(tc_gemm<4>, cudaFuncAttributeMaxDynamicSharedMemorySize, GEMM_SMEM);

    // weight convert + transpose (fp32 [K,N] -> fp16 [N,K])
    dim3 tcb(32, 8);
    tconv_kernel<<<dim3(kD / 32, kD / 32, 1), tcb>>>(wq, p_wqt, kD, kD);
    tconv_kernel<<<dim3(kD / 32, kD / 32, 1), tcb>>>(wk, p_wkt, kD, kD);
    tconv_kernel<<<dim3(kD / 32, kD / 32, 1), tcb>>>(wv, p_wvt, kD, kD);
    tconv_kernel<<<dim3(kD / 32, kD / 32, 1), tcb>>>(wo, p_wot, kD, kD);
    tconv_kernel<<<dim3(kHID / 32, kD / 32, kE), tcb>>>(w1, p_w1t, kD, kHID);
    tconv_kernel<<<dim3(kD / 32, kHID / 32, kE), tcb>>>(w2, p_w2t, kHID, kD);

    // LN1 -> qin (half) ; x -> half
    ln_kernel<0><<<kT, 256>>>(x, ln1w, ln1b, nullptr, p_qin_h);
    int n4 = kT * kD / 4;
    conv_kernel<<<(n4 + 255) / 256, 256>>>(x, p_x_h, n4);

    // QKV projections (half out)
    dim3 g0(kT / 128, kD / 128);
    tc_gemm<4><<<g0, 256, GEMM_SMEM>>>(p_qin_h, p_wqt, bq, nullptr, nullptr, p_qh, kT, kD, kD);
    tc_gemm<4><<<g0, 256, GEMM_SMEM>>>(p_x_h,   p_wkt, bk, nullptr, nullptr, p_kh, kT, kD, kD);
    tc_gemm<4><<<g0, 256, GEMM_SMEM>>>(p_x_h,   p_wvt, bv, nullptr, nullptr, p_vh, kT, kD, kD);

    // tensor-core fused attention (half out)
    attn_tc<<<dim3(kB * kH, kS / 64), 256, ATTN_SMEM>>>(p_qh, p_kh, p_vh, p_attn_h);

    // out projection + residual -> x1 (fp32)
    tc_gemm<1><<<g0, 256, GEMM_SMEM>>>(p_attn_h, p_wot, bo, x, p_x1, nullptr, kT, kD, kD);

    // LN2 -> t (fp32 for router) + t_h (half for gemms)
    ln_kernel<1><<<kT, 256>>>(p_x1, ln2w, ln2b, p_t, p_t_h);

    // routing
    init_kernel<<<1, 32>>>();
    router_kernel<<<kT / 8, 256>>>(p_t, wg, bg);
    prefix_kernel<<<1, 1>>>();
    scatter_kernel<<<kT / 256, 256>>>();

    // MoE expert GEMMs
    tc_gemm<2><<<dim3(kT / 128, kHID / 128, kE), 256, GEMM_SMEM>>>(
        p_t_h, p_w1t, b1, nullptr, nullptr, p_h_h, kT, kHID, kD);
    tc_gemm<3><<<dim3(kT / 128, kD / 128, kE), 256, GEMM_SMEM>>>(
        p_h_h, p_w2t, b2, p_x1, out, nullptr, kT, kD, kHID);
}

// round 9
// speedup vs baseline: 4.9126x; 1.0130x over previous
#include <cuda_runtime.h>
#include <cuda_fp16.h>
#include <math.h>
#include <stdint.h>

// ---------------- problem constants ----------------
constexpr int kS   = 512;
constexpr int kB   = 16;
constexpr int kD   = 768;
constexpr int kH   = 12;
constexpr int kHD  = 64;
constexpr int kE   = 8;
constexpr int kHID = 3072;
constexpr int kT   = kS * kB;          // 8192 tokens

// attention smem layout (bytes)
constexpr int ATT_Q  = 0;
constexpr int ATT_KV = 8192;           // 2 x 64x64 half
constexpr int ATT_P  = 24576;          // 8 chunks of 64x64 half
constexpr int ATT_SC = 90112;          // 64x520 fp32
constexpr int SCP2   = 520;
constexpr int ATTN_SMEM = ATT_SC + 64 * SCP2 * 4;   // 223232

// gemm smem: 2 buffers x (A 32KB + B 16KB)
constexpr int GEMM_SMEM = 98304;

// ---------------- scratch (device globals; no allocations) ----------------
__device__ float g_x1  [kT * kD];
__device__ float g_tn  [kT * kD];
__device__ float g_gate[kT];
__device__ int   g_idx [kT];
__device__ int   g_cnt [kE];
__device__ int   g_off [kE];
__device__ int   g_fill[kE];
__device__ int   g_perm[kT];

// fp16 scratch
__device__ __half g_wqt[kD * kD];
__device__ __half g_wkvt[2 * kD * kD];             // [1536][768] = wk^T rows then wv^T rows
__device__ __half g_wot[kD * kD];
__device__ __half g_w1t[(size_t)kE * kHID * kD];   // [E][HID][D]
__device__ __half g_w2t[(size_t)kE * kD * kHID];   // [E][D][HID]
__device__ __half g_qin_h[kT * kD];
__device__ __half g_x_h  [kT * kD];
__device__ __half g_qh   [kT * kD];
__device__ __half g_kh   [kT * kD];
__device__ __half g_vh   [kT * kD];
__device__ __half g_attn_h[kT * kD];
__device__ __half g_t_h  [kT * kD];
__device__ __half g_h_h  [(size_t)kT * kHID];

// ---------------- helpers ----------------
__device__ __forceinline__ uint32_t smem_u32(const void* p) {
    uint32_t a;
    asm("{ .reg .u64 t; cvta.to.shared.u64 t, %1; cvt.u32.u64 %0, t; }" : "=r"(a) : "l"(p));
    return a;
}
__device__ __forceinline__ void ldmx4(uint32_t* r, uint32_t addr) {
    asm volatile("ldmatrix.sync.aligned.m8n8.x4.shared.b16 {%0,%1,%2,%3}, [%4];"
                 : "=r"(r[0]), "=r"(r[1]), "=r"(r[2]), "=r"(r[3]) : "r"(addr));
}
__device__ __forceinline__ void ldmx4t(uint32_t* r, uint32_t addr) {
    asm volatile("ldmatrix.sync.aligned.m8n8.x4.trans.shared.b16 {%0,%1,%2,%3}, [%4];"
                 : "=r"(r[0]), "=r"(r[1]), "=r"(r[2]), "=r"(r[3]) : "r"(addr));
}
__device__ __forceinline__ void mma16816(float* d, const uint32_t* a, uint32_t b0, uint32_t b1) {
    asm volatile(
        "mma.sync.aligned.m16n8k16.row.col.f32.f16.f16.f32 "
        "{%0,%1,%2,%3}, {%4,%5,%6,%7}, {%8,%9}, {%0,%1,%2,%3};"
        : "+f"(d[0]), "+f"(d[1]), "+f"(d[2]), "+f"(d[3])
        : "r"(a[0]), "r"(a[1]), "r"(a[2]), "r"(a[3]), "r"(b0), "r"(b1));
}
__device__ __forceinline__ uint32_t sw128(uint32_t off) {
    return off ^ ((off >> 3) & 0x70);
}
__device__ __forceinline__ void cp16(uint32_t dst, const void* src) {
    asm volatile("cp.async.ca.shared.global [%0], [%1], 16;" :: "r"(dst), "l"(src));
}
#define CP_COMMIT() asm volatile("cp.async.commit_group;" ::: "memory")
#define CP_WAIT0()  asm volatile("cp.async.wait_group 0;" ::: "memory")

// ---------------- layernorm variants ----------------
template <int LNOUT>
__global__ void ln_kernel(const float* __restrict__ x, const float* __restrict__ w,
                          const float* __restrict__ bias,
                          float* __restrict__ outf, __half* __restrict__ outh)
{
    int t = blockIdx.x;
    const float* r = x + (size_t)t * kD;
    int tid = threadIdx.x;
    float v0 = r[tid], v1 = r[tid + 256], v2 = r[tid + 512];
    float s = v0 + v1 + v2;
    float q = v0 * v0 + v1 * v1 + v2 * v2;
#pragma unroll
    for (int o = 16; o > 0; o >>= 1) {
        s += __shfl_down_sync(0xffffffffu, s, o);
        q += __shfl_down_sync(0xffffffffu, q, o);
    }
    __shared__ float rs[8], rq[8];
    if ((tid & 31) == 0) { rs[tid >> 5] = s; rq[tid >> 5] = q; }
    __syncthreads();
    s = 0.f; q = 0.f;
#pragma unroll
    for (int i = 0; i < 8; ++i) { s += rs[i]; q += rq[i]; }
    float mean = s * (1.0f / kD);
    float var  = q * (1.0f / kD) - mean * mean;
    float inv  = rsqrtf(var + 1e-5f);
    float o0 = (v0 - mean) * inv * w[tid]       + bias[tid];
    float o1 = (v1 - mean) * inv * w[tid + 256] + bias[tid + 256];
    float o2 = (v2 - mean) * inv * w[tid + 512] + bias[tid + 512];
    if (LNOUT == 1) {
        float* of = outf + (size_t)t * kD;
        of[tid] = o0; of[tid + 256] = o1; of[tid + 512] = o2;
    }
    __half* oh = outh + (size_t)t * kD;
    oh[tid]       = __float2half(o0);
    oh[tid + 256] = __float2half(o1);
    oh[tid + 512] = __float2half(o2);
}

// ---------------- fp32 -> fp16 convert ----------------
__global__ void conv_kernel(const float* __restrict__ in, __half* __restrict__ out, int n4)
{
    int i = blockIdx.x * 256 + threadIdx.x;
    if (i >= n4) return;
    float4 v = ((const float4*)in)[i];
    ((__half2*)out)[2 * i]     = __floats2half2_rn(v.x, v.y);
    ((__half2*)out)[2 * i + 1] = __floats2half2_rn(v.z, v.w);
}

// ---------------- fp32 [R,C] -> fp16 [C,R] transpose-convert, 64x64 tiles ----------------
__global__ void tconv_kernel(const float* __restrict__ in, __half* __restrict__ out,
                             int R, int C)
{
    __shared__ float tile[64][65];
    int e = blockIdx.z;
    in  += (size_t)e * R * C;
    out += (size_t)e * R * C;
    int c0 = blockIdx.x * 64, r0 = blockIdx.y * 64;
    int tx = threadIdx.x;      // 0..63
    int ty = threadIdx.y;      // 0..3
#pragma unroll
    for (int i = ty; i < 64; i += 4)
        tile[i][tx] = in[(size_t)(r0 + i) * C + c0 + tx];
    __syncthreads();
#pragma unroll
    for (int i = ty; i < 64; i += 4)
        out[(size_t)(c0 + i) * R + r0 + tx] = __float2half(tile[tx][i]);
}

// ---------------- fp16 mma.sync GEMM, 256x128 tile, cp.async 2-stage ----------------
// MODE 0: Cf = A@W + bias
// MODE 1: Cf = R + A@W + bias
// MODE 2: gathered rows via g_perm, gelu -> Cb (half) at sorted rows
// MODE 3: contiguous sorted rows, Cf[tok] = R[tok] + gate[tok]*(A@W+bias)
// MODE 4: Cb = half(A@W + bias)
// MODE 5: fused KV: N=1536 weight space, col<768 -> Cb (K), col>=768 -> (half*)Cf (V);
//         bias = bk, R = bv (reinterpreted)
template <int MODE>
__global__ __launch_bounds__(256)
void tc_gemm(const __half* __restrict__ A, const __half* __restrict__ Wt,
             const float* __restrict__ bias, const float* __restrict__ R,
             float* __restrict__ Cf, __half* __restrict__ Cb,
             int M, int N, int K)
{
    int cntE = M, rowbase = 0;
    if (MODE == 2 || MODE == 3) {
        int e = blockIdx.z;
        cntE = g_cnt[e];
        rowbase = g_off[e];
        if ((int)(blockIdx.x * 256) >= cntE) return;
        Wt   += (size_t)e * K * N;
        bias += (size_t)e * N;
    }
    int m0 = blockIdx.x * 256, n0 = blockIdx.y * 128;
    int tid = threadIdx.x, wid = tid >> 5, lane = tid & 31;
    int wm = (wid & 3) * 64;       // 4 warps over 256 M
    int wn = (wid >> 2) * 64;      // 2 warps over 128 N

    extern __shared__ char dynsm[];
    // layout: A0 32K | B0 16K | A1 32K | B1 16K
    uint32_t sAu = smem_u32(dynsm);
    uint32_t sBu = sAu + 32768;

    int li = tid & 7, r4 = tid >> 3;
    const __half* aptr[8];
    const __half* bptr[4];
#pragma unroll
    for (int rr = 0; rr < 8; ++rr) {
        int row = r4 + rr * 32;
        int lr = m0 + row;
        const __half* ap;
        if (MODE == 2) {
            int gr = (lr < cntE) ? g_perm[rowbase + lr] : 0;
            ap = A + (size_t)gr * K;
        } else if (MODE == 3) {
            ap = A + (size_t)(rowbase + (lr < cntE ? lr : 0)) * K;
        } else {
            ap = A + (size_t)lr * K;
        }
        aptr[rr] = ap + li * 8;
    }
#pragma unroll
    for (int rr = 0; rr < 4; ++rr)
        bptr[rr] = Wt + (size_t)(n0 + r4 + rr * 32) * K + li * 8;

    uint32_t soff[8];
#pragma unroll
    for (int rr = 0; rr < 8; ++rr)
        soff[rr] = sw128((uint32_t)(r4 + rr * 32) * 128 + (uint32_t)li * 16);

    float acc[4][8][4];
#pragma unroll
    for (int i = 0; i < 4; ++i)
#pragma unroll
        for (int j = 0; j < 8; ++j)
#pragma unroll
            for (int v = 0; v < 4; ++v) acc[i][j][v] = 0.f;

    uint32_t aRow = (uint32_t)(wm + (lane & 15));
    uint32_t aKb  = (lane & 16) ? 16u : 0u;
    uint32_t bRow = (uint32_t)(wn + (lane & 7) + ((lane >> 4) & 1) * 8);
    uint32_t bKb  = ((lane >> 3) & 1) * 16u;

    int nc = K >> 6;

    auto issue = [&](int c, int buf) {
        uint32_t bo = (uint32_t)buf * 49152u;
#pragma unroll
        for (int rr = 0; rr < 8; ++rr)
            cp16(sAu + bo + soff[rr], aptr[rr] + c * 64);
#pragma unroll
        for (int rr = 0; rr < 4; ++rr)
            cp16(sBu + bo + soff[rr], bptr[rr] + c * 64);
        CP_COMMIT();
    };

    issue(0, 0);
    for (int c = 0; c < nc; ++c) {
        CP_WAIT0();
        __syncthreads();
        if (c + 1 < nc) issue(c + 1, (c + 1) & 1);
        uint32_t bo = (uint32_t)(c & 1) * 49152u;
#pragma unroll
        for (int kk = 0; kk < 4; ++kk) {
            uint32_t afr[4][4];
#pragma unroll
            for (int fm = 0; fm < 4; ++fm)
                ldmx4(afr[fm], sAu + bo + sw128((aRow + fm * 16) * 128 + kk * 32 + aKb));
            uint32_t bfr[4][4];
#pragma unroll
            for (int fn4 = 0; fn4 < 4; ++fn4)
                ldmx4(bfr[fn4], sBu + bo + sw128((bRow + fn4 * 16) * 128 + kk * 32 + bKb));
#pragma unroll
            for (int fm = 0; fm < 4; ++fm)
#pragma unroll
                for (int fn = 0; fn < 8; ++fn)
                    mma16816(acc[fm][fn], afr[fm],
                             bfr[fn >> 1][(fn & 1) * 2], bfr[fn >> 1][(fn & 1) * 2 + 1]);
        }
    }

    int rbase = lane >> 2;
    int cbase = (lane & 3) * 2;
#pragma unroll
    for (int fm = 0; fm < 4; ++fm) {
#pragma unroll
        for (int half_ = 0; half_ < 2; ++half_) {
            int rloc = wm + fm * 16 + rbase + half_ * 8;
            int rowi = m0 + rloc;
            bool valid = !(MODE == 2 || MODE == 3) || (rowi < cntE);
            if (!valid) continue;
            int tok = 0;
            float gt = 0.f;
            if (MODE == 3) { tok = g_perm[rowbase + rowi]; gt = g_gate[tok]; }
#pragma unroll
            for (int fn = 0; fn < 8; ++fn) {
                int col = n0 + wn + fn * 8 + cbase;
                float b0, b1;
                if (MODE == 5) {
                    const float* bv = R;
                    b0 = (col < 768) ? bias[col] : bv[col - 768];
                    b1 = (col + 1 < 768) ? bias[col + 1] : bv[col + 1 - 768];
                } else {
                    b0 = bias[col]; b1 = bias[col + 1];
                }
                float v0 = acc[fm][fn][half_ * 2 + 0] + b0;
                float v1 = acc[fm][fn][half_ * 2 + 1] + b1;
                if (MODE == 0) {
                    float* o = Cf + (size_t)rowi * N + col;
                    o[0] = v0; o[1] = v1;
                } else if (MODE == 1) {
                    float* o = Cf + (size_t)rowi * N + col;
                    const float* rr_ = R + (size_t)rowi * N + col;
                    o[0] = v0 + rr_[0]; o[1] = v1 + rr_[1];
                } else if (MODE == 2) {
                    float gl0 = 0.5f * v0 * (1.0f + erff(v0 * 0.70710678118654752f));
                    float gl1 = 0.5f * v1 * (1.0f + erff(v1 * 0.70710678118654752f));
                    *(__half2*)(Cb + (size_t)(rowbase + rowi) * N + col) =
                        __floats2half2_rn(gl0, gl1);
                } else if (MODE == 3) {
                    float* o = Cf + (size_t)tok * N + col;
                    const float* rr_ = R + (size_t)tok * N + col;
                    o[0] = rr_[0] + gt * v0;
                    o[1] = rr_[1] + gt * v1;
                } else if (MODE == 4) {
                    *(__half2*)(Cb + (size_t)rowi * N + col) = __floats2half2_rn(v0, v1);
                } else {
                    // MODE 5: split K/V
                    __half2 hv = __floats2half2_rn(v0, v1);
                    if (col < 768)
                        *(__half2*)(Cb + (size_t)rowi * 768 + col) = hv;
                    else
                        *(__half2*)((__half*)Cf + (size_t)rowi * 768 + (col - 768)) = hv;
                }
            }
        }
    }
}

// ---------------- tensor-core fused attention, cp.async pipelined ----------------
__global__ __launch_bounds__(256)
void attn_tc(const __half* __restrict__ Q, const __half* __restrict__ Kx,
             const __half* __restrict__ V, __half* __restrict__ O)
{
    extern __shared__ char sm[];
    uint32_t sQu  = smem_u32(sm + ATT_Q);
    uint32_t sKVu = smem_u32(sm + ATT_KV);
    uint32_t sPu  = smem_u32(sm + ATT_P);
    float*   sc   = (float*)(sm + ATT_SC);
    __shared__ float red[256];

    int bh = blockIdx.x;
    int b = bh / kH, h = bh % kH;
    int qt = blockIdx.y;
    int tid = threadIdx.x, wid = tid >> 5, lane = tid & 31;

    int i0 = tid >> 3, dv0 = (tid & 7) * 8;
    int i1 = (tid + 256) >> 3, dv1 = (tid & 7) * 8;
    uint32_t so0 = sw128((uint32_t)i0 * 128 + dv0 * 2);
    uint32_t so1 = sw128((uint32_t)i1 * 128 + dv1 * 2);

    auto issueTile = [&](const __half* src, int kt, int buf) {
        uint32_t bo = (uint32_t)buf * 8192u;
        int s0 = kt * 64 + i0, s1 = kt * 64 + i1;
        cp16(sKVu + bo + so0, src + (size_t)(s0 * kB + b) * kD + h * kHD + dv0);
        cp16(sKVu + bo + so1, src + (size_t)(s1 * kB + b) * kD + h * kHD + dv1);
        CP_COMMIT();
    };

    {
        int s0 = qt * 64 + i0, s1 = qt * 64 + i1;
        cp16(sQu + so0, Q + (size_t)(s0 * kB + b) * kD + h * kHD + dv0);
        cp16(sQu + so1, Q + (size_t)(s1 * kB + b) * kD + h * kHD + dv1);
    }
    issueTile(Kx, 0, 0);

    int wm = (wid & 3) * 16, wn = (wid >> 2) * 32;
    uint32_t aRow = (uint32_t)(wm + (lane & 15));
    uint32_t aKb  = (lane & 16) ? 16u : 0u;
    uint32_t bRow = (uint32_t)(wn + (lane & 7) + ((lane >> 4) & 1) * 8);
    uint32_t bKb  = ((lane >> 3) & 1) * 16u;
    int crow = lane >> 2, ccol = (lane & 3) * 2;
    uint32_t vKey = (uint32_t)(((lane >> 3) & 1) * 8 + (lane & 7));
    uint32_t vDim = (uint32_t)(wn + ((lane >> 4) & 1) * 8) * 2;

    // ---- score phase: S = Q K^T / 8 ----
    for (int kt = 0; kt < 8; ++kt) {
        CP_WAIT0();
        __syncthreads();
        if (kt + 1 < 8) issueTile(Kx, kt + 1, (kt + 1) & 1);
        uint32_t bo = (uint32_t)(kt & 1) * 8192u;
        float acc[4][4];
#pragma unroll
        for (int fn = 0; fn < 4; ++fn)
#pragma unroll
            for (int v = 0; v < 4; ++v) acc[fn][v] = 0.f;
#pragma unroll
        for (int kk = 0; kk < 4; ++kk) {
            uint32_t af[4];
            ldmx4(af, sQu + sw128(aRow * 128 + kk * 32 + aKb));
            uint32_t bfr[2][4];
#pragma unroll
            for (int fn2 = 0; fn2 < 2; ++fn2)
                ldmx4(bfr[fn2], sKVu + bo + sw128((bRow + fn2 * 16) * 128 + kk * 32 + bKb));
#pragma unroll
            for (int fn = 0; fn < 4; ++fn)
                mma16816(acc[fn], af, bfr[fn >> 1][(fn & 1) * 2], bfr[fn >> 1][(fn & 1) * 2 + 1]);
        }
#pragma unroll
        for (int fn = 0; fn < 4; ++fn) {
            int col = kt * 64 + wn + fn * 8 + ccol;
            sc[(wm + crow) * SCP2 + col]         = acc[fn][0] * 0.125f;
            sc[(wm + crow) * SCP2 + col + 1]     = acc[fn][1] * 0.125f;
            sc[(wm + crow + 8) * SCP2 + col]     = acc[fn][2] * 0.125f;
            sc[(wm + crow + 8) * SCP2 + col + 1] = acc[fn][3] * 0.125f;
        }
    }
    __syncthreads();

    // ---- softmax (fp32) + pack P to half chunks ----
    int row = tid & 63, part = tid >> 6;
    float* srow = sc + row * SCP2 + part * 128;
    float m = -1e30f;
    for (int c = 0; c < 128; ++c) m = fmaxf(m, srow[c]);
    red[row * 4 + part] = m;
    __syncthreads();
    m = fmaxf(fmaxf(red[row * 4 + 0], red[row * 4 + 1]),
              fmaxf(red[row * 4 + 2], red[row * 4 + 3]));
    float ssum = 0.f;
    for (int c = 0; c < 128; ++c) { float e = expf(srow[c] - m); srow[c] = e; ssum += e; }
    __syncthreads();
    red[row * 4 + part] = ssum;
    __syncthreads();
    float inv = 1.0f / (red[row * 4 + 0] + red[row * 4 + 1] +
                        red[row * 4 + 2] + red[row * 4 + 3]);
    for (int c = 0; c < 128; ++c) {
        int gcol = part * 128 + c;
        int kt2 = gcol >> 6, cw = gcol & 63;
        *(__half*)(sm + ATT_P + kt2 * 8192 + sw128((uint32_t)row * 128 + cw * 2)) =
            __float2half(srow[c] * inv);
    }
    issueTile(V, 0, 0);
    __syncthreads();

    // ---- PV phase: O = P @ V ----
    float o[4][4];
#pragma unroll
    for (int fn = 0; fn < 4; ++fn)
#pragma unroll
        for (int v = 0; v < 4; ++v) o[fn][v] = 0.f;

    for (int kt = 0; kt < 8; ++kt) {
        CP_WAIT0();
        __syncthreads();
        if (kt + 1 < 8) issueTile(V, kt + 1, (kt + 1) & 1);
        uint32_t bo = (uint32_t)(kt & 1) * 8192u;
#pragma unroll
        for (int kk = 0; kk < 4; ++kk) {
            uint32_t af[4];
            ldmx4(af, sPu + kt * 8192 + sw128(aRow * 128 + kk * 32 + aKb));
            uint32_t bfr[2][4];
#pragma unroll
            for (int fn2 = 0; fn2 < 2; ++fn2) {
                uint32_t off = (kk * 16 + vKey) * 128 + vDim + fn2 * 32;
                ldmx4t(bfr[fn2], sKVu + bo + sw128(off));
            }
#pragma unroll
            for (int fn = 0; fn < 4; ++fn)
                mma16816(o[fn], af, bfr[fn >> 1][(fn & 1) * 2], bfr[fn >> 1][(fn & 1) * 2 + 1]);
        }
    }

#pragma unroll
    for (int fn = 0; fn < 4; ++fn) {
        int col = wn + fn * 8 + ccol;
        int s0 = qt * 64 + wm + crow;
        int s1 = s0 + 8;
        *(__half2*)(O + (size_t)(s0 * kB + b) * kD + h * kHD + col) =
            __floats2half2_rn(o[fn][0], o[fn][1]);
        *(__half2*)(O + (size_t)(s1 * kB + b) * kD + h * kHD + col) =
            __floats2half2_rn(o[fn][2], o[fn][3]);
    }
}

// ---------------- router ----------------
__global__ void router_kernel(const float* __restrict__ tin, const float* __restrict__ wg,
                              const float* __restrict__ bg)
{
    int warp = threadIdx.x >> 5;
    int tok  = blockIdx.x * 8 + warp;
    int lane = threadIdx.x & 31;
    const float* row = tin + (size_t)tok * kD;
    int e = lane >> 2, j = lane & 3;
    float s = 0.f;
    for (int d = j; d < kD; d += 4) s += row[d] * wg[d * kE + e];
    s += __shfl_xor_sync(0xffffffffu, s, 1);
    s += __shfl_xor_sync(0xffffffffu, s, 2);
    s += bg[e];
    float lg[kE];
#pragma unroll
    for (int ee = 0; ee < kE; ++ee) lg[ee] = __shfl_sync(0xffffffffu, s, ee * 4);
    if (lane == 0) {
        int best = 0; float bm = lg[0];
#pragma unroll
        for (int ee = 1; ee < kE; ++ee) if (lg[ee] > bm) { bm = lg[ee]; best = ee; }
        float se = 0.f;
#pragma unroll
        for (int ee = 0; ee < kE; ++ee) se += expf(lg[ee] - bm);
        g_idx[tok]  = best;
        g_gate[tok] = 1.0f / se;
        atomicAdd(&g_cnt[best], 1);
    }
}

__global__ void init_kernel()
{
    int t = threadIdx.x;
    if (t < kE) { g_cnt[t] = 0; g_fill[t] = 0; }
}

__global__ void prefix_kernel()
{
    int acc = 0;
    for (int e = 0; e < kE; ++e) { g_off[e] = acc; acc += g_cnt[e]; }
}

__global__ void scatter_kernel()
{
    int t = blockIdx.x * 256 + threadIdx.x;
    int e = g_idx[t];
    int p = atomicAdd(&g_fill[e], 1);
    g_perm[g_off[e] + p] = t;
}

// ---------------- launch ----------------
extern "C" void kernel_launch(void* const* d_in, const int* in_sizes, int n_in,
                              void* d_out, int out_size)
{
    const float* x    = (const float*)d_in[0];
    const float* ln1w = (const float*)d_in[1];
    const float* ln1b = (const float*)d_in[2];
    const float* wq   = (const float*)d_in[3];
    const float* bq   = (const float*)d_in[4];
    const float* wk   = (const float*)d_in[5];
    const float* bk   = (const float*)d_in[6];
    const float* wv   = (const float*)d_in[7];
    const float* bv   = (const float*)d_in[8];
    const float* wo   = (const float*)d_in[9];
    const float* bo   = (const float*)d_in[10];
    const float* ln2w = (const float*)d_in[11];
    const float* ln2b = (const float*)d_in[12];
    const float* wg   = (const float*)d_in[13];
    const float* bg   = (const float*)d_in[14];
    const float* w1   = (const float*)d_in[15];
    const float* b1   = (const float*)d_in[16];
    const float* w2   = (const float*)d_in[17];
    const float* b2   = (const float*)d_in[18];
    float* out = (float*)d_out;

    float *p_x1, *p_t;
    __half *p_wqt, *p_wkvt, *p_wot, *p_w1t, *p_w2t;
    __half *p_qin_h, *p_x_h, *p_qh, *p_kh, *p_vh, *p_attn_h, *p_t_h, *p_h_h;
    cudaGetSymbolAddress((void**)&p_x1,   g_x1);
    cudaGetSymbolAddress((void**)&p_t,    g_tn);
    cudaGetSymbolAddress((void**)&p_wqt,  g_wqt);
    cudaGetSymbolAddress((void**)&p_wkvt, g_wkvt);
    cudaGetSymbolAddress((void**)&p_wot,  g_wot);
    cudaGetSymbolAddress((void**)&p_w1t,  g_w1t);
    cudaGetSymbolAddress((void**)&p_w2t,  g_w2t);
    cudaGetSymbolAddress((void**)&p_qin_h, g_qin_h);
    cudaGetSymbolAddress((void**)&p_x_h,   g_x_h);
    cudaGetSymbolAddress((void**)&p_qh,    g_qh);
    cudaGetSymbolAddress((void**)&p_kh,    g_kh);
    cudaGetSymbolAddress((void**)&p_vh,    g_vh);
    cudaGetSymbolAddress((void**)&p_attn_h, g_attn_h);
    cudaGetSymbolAddress((void**)&p_t_h,   g_t_h);
    cudaGetSymbolAddress((void**)&p_h_h,   g_h_h);

    cudaFuncSetAttribute(attn_tc, cudaFuncAttributeMaxDynamicSharedMemorySize, ATTN_SMEM);
    cudaFuncSetAttribute(tc_gemm<0>, cudaFuncAttributeMaxDynamicSharedMemorySize, GEMM_SMEM);
    cudaFuncSetAttribute(tc_gemm<1>, cudaFuncAttributeMaxDynamicSharedMemorySize, GEMM_SMEM);
    cudaFuncSetAttribute(tc_gemm<2>, cudaFuncAttributeMaxDynamicSharedMemorySize, GEMM_SMEM);
    cudaFuncSetAttribute(tc_gemm<3>, cudaFuncAttributeMaxDynamicSharedMemorySize, GEMM_SMEM);
    cudaFuncSetAttribute(tc_gemm<4>, cudaFuncAttributeMaxDynamicSharedMemorySize, GEMM_SMEM);
    cudaFuncSetAttribute(tc_gemm<5>, cudaFuncAttributeMaxDynamicSharedMemorySize, GEMM_SMEM);

    // weight convert + transpose (fp32 [K,N] -> fp16 [N,K]), 64x64 tiles
    dim3 tcb(64, 4);
    tconv_kernel<<<dim3(kD / 64, kD / 64, 1), tcb>>>(wq, p_wqt, kD, kD);
    tconv_kernel<<<dim3(kD / 64, kD / 64, 1), tcb>>>(wk, p_wkvt, kD, kD);
    tconv_kernel<<<dim3(kD / 64, kD / 64, 1), tcb>>>(wv, p_wkvt + (size_t)kD * kD, kD, kD);
    tconv_kernel<<<dim3(kD / 64, kD / 64, 1), tcb>>>(wo, p_wot, kD, kD);
    tconv_kernel<<<dim3(kHID / 64, kD / 64, kE), tcb>>>(w1, p_w1t, kD, kHID);
    tconv_kernel<<<dim3(kD / 64, kHID / 64, kE), tcb>>>(w2, p_w2t, kHID, kD);

    // LN1 -> qin (half) ; x -> half
    ln_kernel<0><<<kT, 256>>>(x, ln1w, ln1b, nullptr, p_qin_h);
    int n4 = kT * kD / 4;
    conv_kernel<<<(n4 + 255) / 256, 256>>>(x, p_x_h, n4);

    // Q projection; fused K+V projection
    dim3 gq(kT / 256, kD / 128);
    tc_gemm<4><<<gq, 256, GEMM_SMEM>>>(p_qin_h, p_wqt, bq, nullptr, nullptr, p_qh, kT, kD, kD);
    tc_gemm<5><<<dim3(kT / 256, 2 * kD / 128), 256, GEMM_SMEM>>>(
        p_x_h, p_wkvt, bk, bv, (float*)p_vh, p_kh, kT, 2 * kD, kD);

    // tensor-core fused attention (half out)
    attn_tc<<<dim3(kB * kH, kS / 64), 256, ATTN_SMEM>>>(p_qh, p_kh, p_vh, p_attn_h);

    // out projection + residual -> x1 (fp32)
    tc_gemm<1><<<gq, 256, GEMM_SMEM>>>(p_attn_h, p_wot, bo, x, p_x1, nullptr, kT, kD, kD);

    // LN2 -> t (fp32 for router) + t_h (half for gemms)
    ln_kernel<1><<<kT, 256>>>(p_x1, ln2w, ln2b, p_t, p_t_h);

    // routing
    init_kernel<<<1, 32>>>();
    router_kernel<<<kT / 8, 256>>>(p_t, wg, bg);
    prefix_kernel<<<1, 1>>>();
    scatter_kernel<<<kT / 256, 256>>>();

    // MoE expert GEMMs
    tc_gemm<2><<<dim3(kT / 256, kHID / 128, kE), 256, GEMM_SMEM>>>(
        p_t_h, p_w1t, b1, nullptr, nullptr, p_h_h, kT, kHID, kD);
    tc_gemm<3><<<dim3(kT / 256, kD / 128, kE), 256, GEMM_SMEM>>>(
        p_h_h, p_w2t, b2, p_x1, out, nullptr, kT, kD, kHID);
}

// round 10
// speedup vs baseline: 5.1020x; 1.0385x over previous
#include <cuda_runtime.h>
#include <cuda_fp16.h>
#include <math.h>
#include <stdint.h>

// ---------------- problem constants ----------------
constexpr int kS   = 512;
constexpr int kB   = 16;
constexpr int kD   = 768;
constexpr int kH   = 12;
constexpr int kHD  = 64;
constexpr int kE   = 8;
constexpr int kHID = 3072;
constexpr int kT   = kS * kB;          // 8192 tokens

// attention smem layout (bytes)
constexpr int ATT_Q  = 0;
constexpr int ATT_KV = 8192;
constexpr int ATT_P  = 24576;
constexpr int ATT_SC = 90112;
constexpr int SCP2   = 520;
constexpr int ATTN_SMEM = ATT_SC + 64 * SCP2 * 4;   // 223232

// gemm smem: 2 buffers x (A 32KB + B 16KB)
constexpr int GEMM_SMEM = 98304;

// ---------------- scratch (device globals; no allocations) ----------------
__device__ float g_x1  [kT * kD];
__device__ float g_tn  [kT * kD];
__device__ float g_gate[kT];
__device__ int   g_idx [kT];
__device__ int   g_cnt [kE];
__device__ int   g_off [kE];
__device__ int   g_fill[kE];
__device__ int   g_perm[kT];

// fp16 scratch
__device__ __half g_wqkvt[3 * kD * kD];            // [2304][768]: wq^T | wk^T | wv^T
__device__ __half g_wot[kD * kD];
__device__ __half g_w1t[(size_t)kE * kHID * kD];   // [E][HID][D]
__device__ __half g_w2t[(size_t)kE * kD * kHID];   // [E][D][HID]
__device__ __half g_qin_h[kT * kD];
__device__ __half g_x_h  [kT * kD];
__device__ __half g_qh   [kT * kD];
__device__ __half g_kh   [kT * kD];
__device__ __half g_vh   [kT * kD];
__device__ __half g_attn_h[kT * kD];
__device__ __half g_t_h  [kT * kD];
__device__ __half g_h_h  [(size_t)kT * kHID];

// ---------------- helpers ----------------
__device__ __forceinline__ uint32_t smem_u32(const void* p) {
    uint32_t a;
    asm("{ .reg .u64 t; cvta.to.shared.u64 t, %1; cvt.u32.u64 %0, t; }" : "=r"(a) : "l"(p));
    return a;
}
__device__ __forceinline__ void ldmx4(uint32_t* r, uint32_t addr) {
    asm volatile("ldmatrix.sync.aligned.m8n8.x4.shared.b16 {%0,%1,%2,%3}, [%4];"
                 : "=r"(r[0]), "=r"(r[1]), "=r"(r[2]), "=r"(r[3]) : "r"(addr));
}
__device__ __forceinline__ void ldmx4t(uint32_t* r, uint32_t addr) {
    asm volatile("ldmatrix.sync.aligned.m8n8.x4.trans.shared.b16 {%0,%1,%2,%3}, [%4];"
                 : "=r"(r[0]), "=r"(r[1]), "=r"(r[2]), "=r"(r[3]) : "r"(addr));
}
__device__ __forceinline__ void mma16816(float* d, const uint32_t* a, uint32_t b0, uint32_t b1) {
    asm volatile(
        "mma.sync.aligned.m16n8k16.row.col.f32.f16.f16.f32 "
        "{%0,%1,%2,%3}, {%4,%5,%6,%7}, {%8,%9}, {%0,%1,%2,%3};"
        : "+f"(d[0]), "+f"(d[1]), "+f"(d[2]), "+f"(d[3])
        : "r"(a[0]), "r"(a[1]), "r"(a[2]), "r"(a[3]), "r"(b0), "r"(b1));
}
__device__ __forceinline__ uint32_t sw128(uint32_t off) {
    return off ^ ((off >> 3) & 0x70);
}
__device__ __forceinline__ void cp16(uint32_t dst, const void* src) {
    asm volatile("cp.async.ca.shared.global [%0], [%1], 16;" :: "r"(dst), "l"(src));
}
#define CP_COMMIT() asm volatile("cp.async.commit_group;" ::: "memory")
#define CP_WAIT0()  asm volatile("cp.async.wait_group 0;" ::: "memory")

// ---------------- layernorm variants ----------------
// LNOUT 0: half only ; 1: fp32 + half ; 2: LN->outh + raw x -> outh2
template <int LNOUT>
__global__ void ln_kernel(const float* __restrict__ x, const float* __restrict__ w,
                          const float* __restrict__ bias,
                          float* __restrict__ outf, __half* __restrict__ outh,
                          __half* __restrict__ outh2)
{
    int t = blockIdx.x;
    const float* r = x + (size_t)t * kD;
    int tid = threadIdx.x;
    float v0 = r[tid], v1 = r[tid + 256], v2 = r[tid + 512];
    float s = v0 + v1 + v2;
    float q = v0 * v0 + v1 * v1 + v2 * v2;
#pragma unroll
    for (int o = 16; o > 0; o >>= 1) {
        s += __shfl_down_sync(0xffffffffu, s, o);
        q += __shfl_down_sync(0xffffffffu, q, o);
    }
    __shared__ float rs[8], rq[8];
    if ((tid & 31) == 0) { rs[tid >> 5] = s; rq[tid >> 5] = q; }
    __syncthreads();
    s = 0.f; q = 0.f;
#pragma unroll
    for (int i = 0; i < 8; ++i) { s += rs[i]; q += rq[i]; }
    float mean = s * (1.0f / kD);
    float var  = q * (1.0f / kD) - mean * mean;
    float inv  = rsqrtf(var + 1e-5f);
    float o0 = (v0 - mean) * inv * w[tid]       + bias[tid];
    float o1 = (v1 - mean) * inv * w[tid + 256] + bias[tid + 256];
    float o2 = (v2 - mean) * inv * w[tid + 512] + bias[tid + 512];
    if (LNOUT == 1) {
        float* of = outf + (size_t)t * kD;
        of[tid] = o0; of[tid + 256] = o1; of[tid + 512] = o2;
    }
    __half* oh = outh + (size_t)t * kD;
    oh[tid]       = __float2half(o0);
    oh[tid + 256] = __float2half(o1);
    oh[tid + 512] = __float2half(o2);
    if (LNOUT == 2) {
        __half* oh2 = outh2 + (size_t)t * kD;
        oh2[tid]       = __float2half(v0);
        oh2[tid + 256] = __float2half(v1);
        oh2[tid + 512] = __float2half(v2);
    }
}

// ---------------- merged transpose-convert: all 6 weights in one launch ----------------
// 32x32 tiles; job decoded from flat blockIdx.x.
__global__ void tconv_all(const float* __restrict__ wq, const float* __restrict__ wk,
                          const float* __restrict__ wv, const float* __restrict__ wo,
                          const float* __restrict__ w1, const float* __restrict__ w2,
                          __half* __restrict__ wqkvt, __half* __restrict__ wot,
                          __half* __restrict__ w1t, __half* __restrict__ w2t)
{
    __shared__ float tile[32][33];
    int bid = blockIdx.x;
    const float* in;
    __half* out;
    int R, C, tile_id;
    if (bid < 2304) {                       // 4 jobs of 576 tiles (768x768)
        int j = bid / 576; tile_id = bid % 576;
        R = 768; C = 768;
        if (j == 0)      { in = wq; out = wqkvt; }
        else if (j == 1) { in = wk; out = wqkvt + 768 * 768; }
        else if (j == 2) { in = wv; out = wqkvt + 2 * 768 * 768; }
        else             { in = wo; out = wot; }
    } else if (bid < 2304 + 18432) {        // w1: 8 experts x 2304 tiles (768x3072)
        int t = bid - 2304; int e = t / 2304; tile_id = t % 2304;
        R = 768; C = 3072;
        in  = w1  + (size_t)e * R * C;
        out = w1t + (size_t)e * R * C;
    } else {                                // w2: 8 experts x 2304 tiles (3072x768)
        int t = bid - 2304 - 18432; int e = t / 2304; tile_id = t % 2304;
        R = 3072; C = 768;
        in  = w2  + (size_t)e * R * C;
        out = w2t + (size_t)e * R * C;
    }
    int tpr = C / 32;
    int c0 = (tile_id % tpr) * 32;
    int r0 = (tile_id / tpr) * 32;
    int tx = threadIdx.x;
    for (int i = threadIdx.y; i < 32; i += 8)
        tile[i][tx] = in[(size_t)(r0 + i) * C + c0 + tx];
    __syncthreads();
    for (int i = threadIdx.y; i < 32; i += 8)
        out[(size_t)(c0 + i) * R + r0 + tx] = __float2half(tile[tx][i]);
}

// ---------------- fp16 mma.sync GEMM, 256x128 tile, cp.async 2-stage ----------------
// MODE 0: Cf = A@W + bias
// MODE 1: Cf = R + A@W + bias
// MODE 2: gathered rows via g_perm, gelu -> Cb (half) at sorted rows
// MODE 3: contiguous sorted rows, Cf[tok] = R[tok] + gate[tok]*(A@W+bias)
// MODE 4: Cb = half(A@W + bias)
// MODE 6: fused QKV. N=2304 weight space. blockIdx.y<6 -> A=g_qin_h else g_x_h.
//         cols [0,768) -> g_qh (+bias=bq); [768,1536) -> g_kh (+R=bk);
//         [1536,2304) -> g_vh (+Cf reinterpreted = bv).
template <int MODE>
__global__ __launch_bounds__(256)
void tc_gemm(const __half* __restrict__ A, const __half* __restrict__ Wt,
             const float* __restrict__ bias, const float* __restrict__ R,
             float* __restrict__ Cf, __half* __restrict__ Cb,
             int M, int N, int K)
{
    int cntE = M, rowbase = 0;
    if (MODE == 2 || MODE == 3) {
        int e = blockIdx.z;
        cntE = g_cnt[e];
        rowbase = g_off[e];
        if ((int)(blockIdx.x * 256) >= cntE) return;
        Wt   += (size_t)e * K * N;
        bias += (size_t)e * N;
    }
    int m0 = blockIdx.x * 256, n0 = blockIdx.y * 128;
    int tid = threadIdx.x, wid = tid >> 5, lane = tid & 31;
    int wm = (wid & 3) * 64;
    int wn = (wid >> 2) * 64;

    const __half* Abase = A;
    if (MODE == 6) Abase = (blockIdx.y < 6) ? g_qin_h : g_x_h;

    extern __shared__ char dynsm[];
    uint32_t sAu = smem_u32(dynsm);
    uint32_t sBu = sAu + 32768;

    int li = tid & 7, r4 = tid >> 3;
    const __half* aptr[8];
    const __half* bptr[4];
#pragma unroll
    for (int rr = 0; rr < 8; ++rr) {
        int row = r4 + rr * 32;
        int lr = m0 + row;
        const __half* ap;
        if (MODE == 2) {
            int gr = (lr < cntE) ? g_perm[rowbase + lr] : 0;
            ap = Abase + (size_t)gr * K;
        } else if (MODE == 3) {
            ap = Abase + (size_t)(rowbase + (lr < cntE ? lr : 0)) * K;
        } else {
            ap = Abase + (size_t)lr * K;
        }
        aptr[rr] = ap + li * 8;
    }
#pragma unroll
    for (int rr = 0; rr < 4; ++rr)
        bptr[rr] = Wt + (size_t)(n0 + r4 + rr * 32) * K + li * 8;

    uint32_t soff[8];
#pragma unroll
    for (int rr = 0; rr < 8; ++rr)
        soff[rr] = sw128((uint32_t)(r4 + rr * 32) * 128 + (uint32_t)li * 16);

    float acc[4][8][4];
#pragma unroll
    for (int i = 0; i < 4; ++i)
#pragma unroll
        for (int j = 0; j < 8; ++j)
#pragma unroll
            for (int v = 0; v < 4; ++v) acc[i][j][v] = 0.f;

    uint32_t aRow = (uint32_t)(wm + (lane & 15));
    uint32_t aKb  = (lane & 16) ? 16u : 0u;
    uint32_t bRow = (uint32_t)(wn + (lane & 7) + ((lane >> 4) & 1) * 8);
    uint32_t bKb  = ((lane >> 3) & 1) * 16u;

    int nc = K >> 6;

    auto issue = [&](int c, int buf) {
        uint32_t bo = (uint32_t)buf * 49152u;
#pragma unroll
        for (int rr = 0; rr < 8; ++rr)
            cp16(sAu + bo + soff[rr], aptr[rr] + c * 64);
#pragma unroll
        for (int rr = 0; rr < 4; ++rr)
            cp16(sBu + bo + soff[rr], bptr[rr] + c * 64);
        CP_COMMIT();
    };

    issue(0, 0);
    for (int c = 0; c < nc; ++c) {
        CP_WAIT0();
        __syncthreads();
        if (c + 1 < nc) issue(c + 1, (c + 1) & 1);
        uint32_t bo = (uint32_t)(c & 1) * 49152u;
#pragma unroll
        for (int kk = 0; kk < 4; ++kk) {
            uint32_t afr[4][4];
#pragma unroll
            for (int fm = 0; fm < 4; ++fm)
                ldmx4(afr[fm], sAu + bo + sw128((aRow + fm * 16) * 128 + kk * 32 + aKb));
            uint32_t bfr[4][4];
#pragma unroll
            for (int fn4 = 0; fn4 < 4; ++fn4)
                ldmx4(bfr[fn4], sBu + bo + sw128((bRow + fn4 * 16) * 128 + kk * 32 + bKb));
#pragma unroll
            for (int fm = 0; fm < 4; ++fm)
#pragma unroll
                for (int fn = 0; fn < 8; ++fn)
                    mma16816(acc[fm][fn], afr[fm],
                             bfr[fn >> 1][(fn & 1) * 2], bfr[fn >> 1][(fn & 1) * 2 + 1]);
        }
    }

    int rbase = lane >> 2;
    int cbase = (lane & 3) * 2;
#pragma unroll
    for (int fm = 0; fm < 4; ++fm) {
#pragma unroll
        for (int half_ = 0; half_ < 2; ++half_) {
            int rloc = wm + fm * 16 + rbase + half_ * 8;
            int rowi = m0 + rloc;
            bool valid = !(MODE == 2 || MODE == 3) || (rowi < cntE);
            if (!valid) continue;
            int tok = 0;
            float gt = 0.f;
            if (MODE == 3) { tok = g_perm[rowbase + rowi]; gt = g_gate[tok]; }
#pragma unroll
            for (int fn = 0; fn < 8; ++fn) {
                int col = n0 + wn + fn * 8 + cbase;
                if (MODE == 6) {
                    int grp = col / 768;
                    int lc  = col - grp * 768;
                    const float* bp = (grp == 0) ? bias : (grp == 1) ? R : (const float*)Cf;
                    __half* dst = (grp == 0) ? g_qh : (grp == 1) ? g_kh : g_vh;
                    float v0 = acc[fm][fn][half_ * 2 + 0] + bp[lc];
                    float v1 = acc[fm][fn][half_ * 2 + 1] + bp[lc + 1];
                    *(__half2*)(dst + (size_t)rowi * 768 + lc) = __floats2half2_rn(v0, v1);
                    continue;
                }
                float v0 = acc[fm][fn][half_ * 2 + 0] + bias[col];
                float v1 = acc[fm][fn][half_ * 2 + 1] + bias[col + 1];
                if (MODE == 0) {
                    float* o = Cf + (size_t)rowi * N + col;
                    o[0] = v0; o[1] = v1;
                } else if (MODE == 1) {
                    float* o = Cf + (size_t)rowi * N + col;
                    const float* rr_ = R + (size_t)rowi * N + col;
                    o[0] = v0 + rr_[0]; o[1] = v1 + rr_[1];
                } else if (MODE == 2) {
                    float gl0 = 0.5f * v0 * (1.0f + erff(v0 * 0.70710678118654752f));
                    float gl1 = 0.5f * v1 * (1.0f + erff(v1 * 0.70710678118654752f));
                    *(__half2*)(Cb + (size_t)(rowbase + rowi) * N + col) =
                        __floats2half2_rn(gl0, gl1);
                } else if (MODE == 3) {
                    float* o = Cf + (size_t)tok * N + col;
                    const float* rr_ = R + (size_t)tok * N + col;
                    o[0] = rr_[0] + gt * v0;
                    o[1] = rr_[1] + gt * v1;
                } else {
                    *(__half2*)(Cb + (size_t)rowi * N + col) = __floats2half2_rn(v0, v1);
                }
            }
        }
    }
}

// ---------------- tensor-core fused attention, cp.async pipelined ----------------
__global__ __launch_bounds__(256)
void attn_tc(const __half* __restrict__ Q, const __half* __restrict__ Kx,
             const __half* __restrict__ V, __half* __restrict__ O)
{
    extern __shared__ char sm[];
    uint32_t sQu  = smem_u32(sm + ATT_Q);
    uint32_t sKVu = smem_u32(sm + ATT_KV);
    uint32_t sPu  = smem_u32(sm + ATT_P);
    float*   sc   = (float*)(sm + ATT_SC);
    __shared__ float red[256];

    int bh = blockIdx.x;
    int b = bh / kH, h = bh % kH;
    int qt = blockIdx.y;
    int tid = threadIdx.x, wid = tid >> 5, lane = tid & 31;

    int i0 = tid >> 3, dv0 = (tid & 7) * 8;
    int i1 = (tid + 256) >> 3, dv1 = (tid & 7) * 8;
    uint32_t so0 = sw128((uint32_t)i0 * 128 + dv0 * 2);
    uint32_t so1 = sw128((uint32_t)i1 * 128 + dv1 * 2);

    auto issueTile = [&](const __half* src, int kt, int buf) {
        uint32_t bo = (uint32_t)buf * 8192u;
        int s0 = kt * 64 + i0, s1 = kt * 64 + i1;
        cp16(sKVu + bo + so0, src + (size_t)(s0 * kB + b) * kD + h * kHD + dv0);
        cp16(sKVu + bo + so1, src + (size_t)(s1 * kB + b) * kD + h * kHD + dv1);
        CP_COMMIT();
    };

    {
        int s0 = qt * 64 + i0, s1 = qt * 64 + i1;
        cp16(sQu + so0, Q + (size_t)(s0 * kB + b) * kD + h * kHD + dv0);
        cp16(sQu + so1, Q + (size_t)(s1 * kB + b) * kD + h * kHD + dv1);
    }
    issueTile(Kx, 0, 0);

    int wm = (wid & 3) * 16, wn = (wid >> 2) * 32;
    uint32_t aRow = (uint32_t)(wm + (lane & 15));
    uint32_t aKb  = (lane & 16) ? 16u : 0u;
    uint32_t bRow = (uint32_t)(wn + (lane & 7) + ((lane >> 4) & 1) * 8);
    uint32_t bKb  = ((lane >> 3) & 1) * 16u;
    int crow = lane >> 2, ccol = (lane & 3) * 2;
    uint32_t vKey = (uint32_t)(((lane >> 3) & 1) * 8 + (lane & 7));
    uint32_t vDim = (uint32_t)(wn + ((lane >> 4) & 1) * 8) * 2;

    // ---- score phase ----
    for (int kt = 0; kt < 8; ++kt) {
        CP_WAIT0();
        __syncthreads();
        if (kt + 1 < 8) issueTile(Kx, kt + 1, (kt + 1) & 1);
        uint32_t bo = (uint32_t)(kt & 1) * 8192u;
        float acc[4][4];
#pragma unroll
        for (int fn = 0; fn < 4; ++fn)
#pragma unroll
            for (int v = 0; v < 4; ++v) acc[fn][v] = 0.f;
#pragma unroll
        for (int kk = 0; kk < 4; ++kk) {
            uint32_t af[4];
            ldmx4(af, sQu + sw128(aRow * 128 + kk * 32 + aKb));
            uint32_t bfr[2][4];
#pragma unroll
            for (int fn2 = 0; fn2 < 2; ++fn2)
                ldmx4(bfr[fn2], sKVu + bo + sw128((bRow + fn2 * 16) * 128 + kk * 32 + bKb));
#pragma unroll
            for (int fn = 0; fn < 4; ++fn)
                mma16816(acc[fn], af, bfr[fn >> 1][(fn & 1) * 2], bfr[fn >> 1][(fn & 1) * 2 + 1]);
        }
#pragma unroll
        for (int fn = 0; fn < 4; ++fn) {
            int col = kt * 64 + wn + fn * 8 + ccol;
            sc[(wm + crow) * SCP2 + col]         = acc[fn][0] * 0.125f;
            sc[(wm + crow) * SCP2 + col + 1]     = acc[fn][1] * 0.125f;
            sc[(wm + crow + 8) * SCP2 + col]     = acc[fn][2] * 0.125f;
            sc[(wm + crow + 8) * SCP2 + col + 1] = acc[fn][3] * 0.125f;
        }
    }
    __syncthreads();

    // ---- softmax + pack P ----
    int row = tid & 63, part = tid >> 6;
    float* srow = sc + row * SCP2 + part * 128;
    float m = -1e30f;
    for (int c = 0; c < 128; ++c) m = fmaxf(m, srow[c]);
    red[row * 4 + part] = m;
    __syncthreads();
    m = fmaxf(fmaxf(red[row * 4 + 0], red[row * 4 + 1]),
              fmaxf(red[row * 4 + 2], red[row * 4 + 3]));
    float ssum = 0.f;
    for (int c = 0; c < 128; ++c) { float e = expf(srow[c] - m); srow[c] = e; ssum += e; }
    __syncthreads();
    red[row * 4 + part] = ssum;
    __syncthreads();
    float inv = 1.0f / (red[row * 4 + 0] + red[row * 4 + 1] +
                        red[row * 4 + 2] + red[row * 4 + 3]);
    for (int c = 0; c < 128; ++c) {
        int gcol = part * 128 + c;
        int kt2 = gcol >> 6, cw = gcol & 63;
        *(__half*)(sm + ATT_P + kt2 * 8192 + sw128((uint32_t)row * 128 + cw * 2)) =
            __float2half(srow[c] * inv);
    }
    issueTile(V, 0, 0);
    __syncthreads();

    // ---- PV phase ----
    float o[4][4];
#pragma unroll
    for (int fn = 0; fn < 4; ++fn)
#pragma unroll
        for (int v = 0; v < 4; ++v) o[fn][v] = 0.f;

    for (int kt = 0; kt < 8; ++kt) {
        CP_WAIT0();
        __syncthreads();
        if (kt + 1 < 8) issueTile(V, kt + 1, (kt + 1) & 1);
        uint32_t bo = (uint32_t)(kt & 1) * 8192u;
#pragma unroll
        for (int kk = 0; kk < 4; ++kk) {
            uint32_t af[4];
            ldmx4(af, sPu + kt * 8192 + sw128(aRow * 128 + kk * 32 + aKb));
            uint32_t bfr[2][4];
#pragma unroll
            for (int fn2 = 0; fn2 < 2; ++fn2) {
                uint32_t off = (kk * 16 + vKey) * 128 + vDim + fn2 * 32;
                ldmx4t(bfr[fn2], sKVu + bo + sw128(off));
            }
#pragma unroll
            for (int fn = 0; fn < 4; ++fn)
                mma16816(o[fn], af, bfr[fn >> 1][(fn & 1) * 2], bfr[fn >> 1][(fn & 1) * 2 + 1]);
        }
    }

#pragma unroll
    for (int fn = 0; fn < 4; ++fn) {
        int col = wn + fn * 8 + ccol;
        int s0 = qt * 64 + wm + crow;
        int s1 = s0 + 8;
        *(__half2*)(O + (size_t)(s0 * kB + b) * kD + h * kHD + col) =
            __floats2half2_rn(o[fn][0], o[fn][1]);
        *(__half2*)(O + (size_t)(s1 * kB + b) * kD + h * kHD + col) =
            __floats2half2_rn(o[fn][2], o[fn][3]);
    }
}

// ---------------- router ----------------
__global__ void router_kernel(const float* __restrict__ tin, const float* __restrict__ wg,
                              const float* __restrict__ bg)
{
    int warp = threadIdx.x >> 5;
    int tok  = blockIdx.x * 8 + warp;
    int lane = threadIdx.x & 31;
    const float* row = tin + (size_t)tok * kD;
    int e = lane >> 2, j = lane & 3;
    float s = 0.f;
    for (int d = j; d < kD; d += 4) s += row[d] * wg[d * kE + e];
    s += __shfl_xor_sync(0xffffffffu, s, 1);
    s += __shfl_xor_sync(0xffffffffu, s, 2);
    s += bg[e];
    float lg[kE];
#pragma unroll
    for (int ee = 0; ee < kE; ++ee) lg[ee] = __shfl_sync(0xffffffffu, s, ee * 4);
    if (lane == 0) {
        int best = 0; float bm = lg[0];
#pragma unroll
        for (int ee = 1; ee < kE; ++ee) if (lg[ee] > bm) { bm = lg[ee]; best = ee; }
        float se = 0.f;
#pragma unroll
        for (int ee = 0; ee < kE; ++ee) se += expf(lg[ee] - bm);
        g_idx[tok]  = best;
        g_gate[tok] = 1.0f / se;
        atomicAdd(&g_cnt[best], 1);
    }
}

__global__ void init_kernel()
{
    int t = threadIdx.x;
    if (t < kE) { g_cnt[t] = 0; g_fill[t] = 0; }
}

__global__ void prefix_kernel()
{
    int acc = 0;
    for (int e = 0; e < kE; ++e) { g_off[e] = acc; acc += g_cnt[e]; }
}

__global__ void scatter_kernel()
{
    int t = blockIdx.x * 256 + threadIdx.x;
    int e = g_idx[t];
    int p = atomicAdd(&g_fill[e], 1);
    g_perm[g_off[e] + p] = t;
}

// ---------------- launch ----------------
extern "C" void kernel_launch(void* const* d_in, const int* in_sizes, int n_in,
                              void* d_out, int out_size)
{
    const float* x    = (const float*)d_in[0];
    const float* ln1w = (const float*)d_in[1];
    const float* ln1b = (const float*)d_in[2];
    const float* wq   = (const float*)d_in[3];
    const float* bq   = (const float*)d_in[4];
    const float* wk   = (const float*)d_in[5];
    const float* bk   = (const float*)d_in[6];
    const float* wv   = (const float*)d_in[7];
    const float* bv   = (const float*)d_in[8];
    const float* wo   = (const float*)d_in[9];
    const float* bo   = (const float*)d_in[10];
    const float* ln2w = (const float*)d_in[11];
    const float* ln2b = (const float*)d_in[12];
    const float* wg   = (const float*)d_in[13];
    const float* bg   = (const float*)d_in[14];
    const float* w1   = (const float*)d_in[15];
    const float* b1   = (const float*)d_in[16];
    const float* w2   = (const float*)d_in[17];
    const float* b2   = (const float*)d_in[18];
    float* out = (float*)d_out;

    float *p_x1, *p_t;
    __half *p_wqkvt, *p_wot, *p_w1t, *p_w2t;
    __half *p_qin_h, *p_x_h, *p_qh, *p_kh, *p_vh, *p_attn_h, *p_t_h, *p_h_h;
    cudaGetSymbolAddress((void**)&p_x1,    g_x1);
    cudaGetSymbolAddress((void**)&p_t,     g_tn);
    cudaGetSymbolAddress((void**)&p_wqkvt, g_wqkvt);
    cudaGetSymbolAddress((void**)&p_wot,   g_wot);
    cudaGetSymbolAddress((void**)&p_w1t,   g_w1t);
    cudaGetSymbolAddress((void**)&p_w2t,   g_w2t);
    cudaGetSymbolAddress((void**)&p_qin_h, g_qin_h);
    cudaGetSymbolAddress((void**)&p_x_h,   g_x_h);
    cudaGetSymbolAddress((void**)&p_qh,    g_qh);
    cudaGetSymbolAddress((void**)&p_kh,    g_kh);
    cudaGetSymbolAddress((void**)&p_vh,    g_vh);
    cudaGetSymbolAddress((void**)&p_attn_h, g_attn_h);
    cudaGetSymbolAddress((void**)&p_t_h,   g_t_h);
    cudaGetSymbolAddress((void**)&p_h_h,   g_h_h);

    cudaFuncSetAttribute(attn_tc, cudaFuncAttributeMaxDynamicSharedMemorySize, ATTN_SMEM);
    cudaFuncSetAttribute(tc_gemm<1>, cudaFuncAttributeMaxDynamicSharedMemorySize, GEMM_SMEM);
    cudaFuncSetAttribute(tc_gemm<2>, cudaFuncAttributeMaxDynamicSharedMemorySize, GEMM_SMEM);
    cudaFuncSetAttribute(tc_gemm<3>, cudaFuncAttributeMaxDynamicSharedMemorySize, GEMM_SMEM);
    cudaFuncSetAttribute(tc_gemm<6>, cudaFuncAttributeMaxDynamicSharedMemorySize, GEMM_SMEM);

    // all weight transposes in one launch (2304 + 2*18432 blocks)
    tconv_all<<<2304 + 2 * 18432, dim3(32, 8)>>>(wq, wk, wv, wo, w1, w2,
                                                 p_wqkvt, p_wot, p_w1t, p_w2t);

    // LN1 -> qin_h, and x -> x_h, in one pass
    ln_kernel<2><<<kT, 256>>>(x, ln1w, ln1b, nullptr, p_qin_h, p_x_h);

    // fused QKV projection (single launch)
    tc_gemm<6><<<dim3(kT / 256, 18), 256, GEMM_SMEM>>>(
        nullptr, p_wqkvt, bq, bk, (float*)bv, nullptr, kT, 3 * kD, kD);

    // tensor-core fused attention (half out)
    attn_tc<<<dim3(kB * kH, kS / 64), 256, ATTN_SMEM>>>(p_qh, p_kh, p_vh, p_attn_h);

    // out projection + residual -> x1 (fp32)
    tc_gemm<1><<<dim3(kT / 256, kD / 128), 256, GEMM_SMEM>>>(
        p_attn_h, p_wot, bo, x, p_x1, nullptr, kT, kD, kD);

    // LN2 -> t (fp32 for router) + t_h (half for gemms)
    ln_kernel<1><<<kT, 256>>>(p_x1, ln2w, ln2b, p_t, p_t_h, nullptr);

    // routing
    init_kernel<<<1, 32>>>();
    router_kernel<<<kT / 8, 256>>>(p_t, wg, bg);
    prefix_kernel<<<1, 1>>>();
    scatter_kernel<<<kT / 256, 256>>>();

    // MoE expert GEMMs
    tc_gemm<2><<<dim3(kT / 256, kHID / 128, kE), 256, GEMM_SMEM>>>(
        p_t_h, p_w1t, b1, nullptr, nullptr, p_h_h, kT, kHID, kD);
    tc_gemm<3><<<dim3(kT / 256, kD / 128, kE), 256, GEMM_SMEM>>>(
        p_h_h, p_w2t, b2, p_x1, out, nullptr, kT, kD, kHID);
}

// round 14
// speedup vs baseline: 6.0168x; 1.1793x over previous
#include <cuda_runtime.h>
#include <cuda_fp16.h>
#include <math.h>
#include <stdint.h>

// ---------------- problem constants ----------------
constexpr int kS   = 512;
constexpr int kB   = 16;
constexpr int kD   = 768;
constexpr int kH   = 12;
constexpr int kHD  = 64;
constexpr int kE   = 8;
constexpr int kHID = 3072;
constexpr int kT   = kS * kB;          // 8192 tokens

// flash-attention smem: Q 16K | K 2x8K | V 2x8K
constexpr int FA_SMEM = 16384 + 16384 + 16384;   // 49152

// gemm smem: 2 buffers x (A 32KB + B 16KB)
constexpr int GEMM_SMEM = 98304;

// ---------------- scratch (device globals; no allocations) ----------------
__device__ float g_x1  [kT * kD];
__device__ float g_tn  [kT * kD];
__device__ float g_gate[kT];
__device__ int   g_idx [kT];
__device__ int   g_cnt [kE];
__device__ int   g_off [kE];
__device__ int   g_fill[kE];
__device__ int   g_perm[kT];

// fp16 scratch
__device__ __half g_wqkvt[3 * kD * kD];            // [2304][768]: wq^T | wk^T | wv^T
__device__ __half g_wot[kD * kD];
__device__ __half g_w1t[(size_t)kE * kHID * kD];   // [E][HID][D]
__device__ __half g_w2t[(size_t)kE * kD * kHID];   // [E][D][HID]
__device__ __half g_qin_h[kT * kD];
__device__ __half g_x_h  [kT * kD];
__device__ __half g_qh   [kT * kD];
__device__ __half g_kh   [kT * kD];
__device__ __half g_vh   [kT * kD];
__device__ __half g_attn_h[kT * kD];
__device__ __half g_t_h  [kT * kD];
__device__ __half g_h_h  [(size_t)kT * kHID];

// ---------------- helpers ----------------
__device__ __forceinline__ uint32_t smem_u32(const void* p) {
    uint32_t a;
    asm("{ .reg .u64 t; cvta.to.shared.u64 t, %1; cvt.u32.u64 %0, t; }" : "=r"(a) : "l"(p));
    return a;
}
__device__ __forceinline__ void ldmx4(uint32_t* r, uint32_t addr) {
    asm volatile("ldmatrix.sync.aligned.m8n8.x4.shared.b16 {%0,%1,%2,%3}, [%4];"
                 : "=r"(r[0]), "=r"(r[1]), "=r"(r[2]), "=r"(r[3]) : "r"(addr));
}
__device__ __forceinline__ void ldmx4t(uint32_t* r, uint32_t addr) {
    asm volatile("ldmatrix.sync.aligned.m8n8.x4.trans.shared.b16 {%0,%1,%2,%3}, [%4];"
                 : "=r"(r[0]), "=r"(r[1]), "=r"(r[2]), "=r"(r[3]) : "r"(addr));
}
__device__ __forceinline__ void mma16816(float* d, const uint32_t* a, uint32_t b0, uint32_t b1) {
    asm volatile(
        "mma.sync.aligned.m16n8k16.row.col.f32.f16.f16.f32 "
        "{%0,%1,%2,%3}, {%4,%5,%6,%7}, {%8,%9}, {%0,%1,%2,%3};"
        : "+f"(d[0]), "+f"(d[1]), "+f"(d[2]), "+f"(d[3])
        : "r"(a[0]), "r"(a[1]), "r"(a[2]), "r"(a[3]), "r"(b0), "r"(b1));
}
__device__ __forceinline__ uint32_t sw128(uint32_t off) {
    return off ^ ((off >> 3) & 0x70);
}
__device__ __forceinline__ void cp16(uint32_t dst, const void* src) {
    asm volatile("cp.async.ca.shared.global [%0], [%1], 16;" :: "r"(dst), "l"(src));
}
#define CP_COMMIT() asm volatile("cp.async.commit_group;" ::: "memory")
#define CP_WAIT0()  asm volatile("cp.async.wait_group 0;" ::: "memory")

// ---------------- layernorm variants ----------------
// LNOUT 0: half only ; 1: fp32 + half ; 2: LN->outh + raw x -> outh2
template <int LNOUT>
__global__ void ln_kernel(const float* __restrict__ x, const float* __restrict__ w,
                          const float* __restrict__ bias,
                          float* __restrict__ outf, __half* __restrict__ outh,
                          __half* __restrict__ outh2)
{
    int t = blockIdx.x;
    const float* r = x + (size_t)t * kD;
    int tid = threadIdx.x;
    float v0 = r[tid], v1 = r[tid + 256], v2 = r[tid + 512];
    float s = v0 + v1 + v2;
    float q = v0 * v0 + v1 * v1 + v2 * v2;
#pragma unroll
    for (int o = 16; o > 0; o >>= 1) {
        s += __shfl_down_sync(0xffffffffu, s, o);
        q += __shfl_down_sync(0xffffffffu, q, o);
    }
    __shared__ float rs[8], rq[8];
    if ((tid & 31) == 0) { rs[tid >> 5] = s; rq[tid >> 5] = q; }
    __syncthreads();
    s = 0.f; q = 0.f;
#pragma unroll
    for (int i = 0; i < 8; ++i) { s += rs[i]; q += rq[i]; }
    float mean = s * (1.0f / kD);
    float var  = q * (1.0f / kD) - mean * mean;
    float inv  = rsqrtf(var + 1e-5f);
    float o0 = (v0 - mean) * inv * w[tid]       + bias[tid];
    float o1 = (v1 - mean) * inv * w[tid + 256] + bias[tid + 256];
    float o2 = (v2 - mean) * inv * w[tid + 512] + bias[tid + 512];
    if (LNOUT == 1) {
        float* of = outf + (size_t)t * kD;
        of[tid] = o0; of[tid + 256] = o1; of[tid + 512] = o2;
    }
    __half* oh = outh + (size_t)t * kD;
    oh[tid]       = __float2half(o0);
    oh[tid + 256] = __float2half(o1);
    oh[tid + 512] = __float2half(o2);
    if (LNOUT == 2) {
        __half* oh2 = outh2 + (size_t)t * kD;
        oh2[tid]       = __float2half(v0);
        oh2[tid + 256] = __float2half(v1);
        oh2[tid + 512] = __float2half(v2);
    }
}

// ---------------- merged transpose-convert: all 6 weights in one launch ----------------
__global__ void tconv_all(const float* __restrict__ wq, const float* __restrict__ wk,
                          const float* __restrict__ wv, const float* __restrict__ wo,
                          const float* __restrict__ w1, const float* __restrict__ w2,
                          __half* __restrict__ wqkvt, __half* __restrict__ wot,
                          __half* __restrict__ w1t, __half* __restrict__ w2t)
{
    __shared__ float tile[32][33];
    int bid = blockIdx.x;
    const float* in;
    __half* out;
    int R, C, tile_id;
    if (bid < 2304) {
        int j = bid / 576; tile_id = bid % 576;
        R = 768; C = 768;
        if (j == 0)      { in = wq; out = wqkvt; }
        else if (j == 1) { in = wk; out = wqkvt + 768 * 768; }
        else if (j == 2) { in = wv; out = wqkvt + 2 * 768 * 768; }
        else             { in = wo; out = wot; }
    } else if (bid < 2304 + 18432) {
        int t = bid - 2304; int e = t / 2304; tile_id = t % 2304;
        R = 768; C = 3072;
        in  = w1  + (size_t)e * R * C;
        out = w1t + (size_t)e * R * C;
    } else {
        int t = bid - 2304 - 18432; int e = t / 2304; tile_id = t % 2304;
        R = 3072; C = 768;
        in  = w2  + (size_t)e * R * C;
        out = w2t + (size_t)e * R * C;
    }
    int tpr = C / 32;
    int c0 = (tile_id % tpr) * 32;
    int r0 = (tile_id / tpr) * 32;
    int tx = threadIdx.x;
    for (int i = threadIdx.y; i < 32; i += 8)
        tile[i][tx] = in[(size_t)(r0 + i) * C + c0 + tx];
    __syncthreads();
    for (int i = threadIdx.y; i < 32; i += 8)
        out[(size_t)(c0 + i) * R + r0 + tx] = __float2half(tile[tx][i]);
}

// ---------------- fp16 mma.sync GEMM, 256x128 tile, cp.async 2-stage ----------------
// MODE 1: Cf = R + A@W + bias
// MODE 2: gathered rows via g_perm, gelu -> Cb (half) at sorted rows
// MODE 3: contiguous sorted rows, Cf[tok] = R[tok] + gate[tok]*(A@W+bias)
// MODE 6: fused QKV (see R10)
template <int MODE>
__global__ __launch_bounds__(256)
void tc_gemm(const __half* __restrict__ A, const __half* __restrict__ Wt,
             const float* __restrict__ bias, const float* __restrict__ R,
             float* __restrict__ Cf, __half* __restrict__ Cb,
             int M, int N, int K)
{
    int cntE = M, rowbase = 0;
    if (MODE == 2 || MODE == 3) {
        int e = blockIdx.z;
        cntE = g_cnt[e];
        rowbase = g_off[e];
        if ((int)(blockIdx.x * 256) >= cntE) return;
        Wt   += (size_t)e * K * N;
        bias += (size_t)e * N;
    }
    int m0 = blockIdx.x * 256, n0 = blockIdx.y * 128;
    int tid = threadIdx.x, wid = tid >> 5, lane = tid & 31;
    int wm = (wid & 3) * 64;
    int wn = (wid >> 2) * 64;

    const __half* Abase = A;
    if (MODE == 6) Abase = (blockIdx.y < 6) ? g_qin_h : g_x_h;

    extern __shared__ char dynsm[];
    uint32_t sAu = smem_u32(dynsm);
    uint32_t sBu = sAu + 32768;

    int li = tid & 7, r4 = tid >> 3;
    const __half* aptr[8];
    const __half* bptr[4];
#pragma unroll
    for (int rr = 0; rr < 8; ++rr) {
        int row = r4 + rr * 32;
        int lr = m0 + row;
        const __half* ap;
        if (MODE == 2) {
            int gr = (lr < cntE) ? g_perm[rowbase + lr] : 0;
            ap = Abase + (size_t)gr * K;
        } else if (MODE == 3) {
            ap = Abase + (size_t)(rowbase + (lr < cntE ? lr : 0)) * K;
        } else {
            ap = Abase + (size_t)lr * K;
        }
        aptr[rr] = ap + li * 8;
    }
#pragma unroll
    for (int rr = 0; rr < 4; ++rr)
        bptr[rr] = Wt + (size_t)(n0 + r4 + rr * 32) * K + li * 8;

    uint32_t soff[8];
#pragma unroll
    for (int rr = 0; rr < 8; ++rr)
        soff[rr] = sw128((uint32_t)(r4 + rr * 32) * 128 + (uint32_t)li * 16);

    float acc[4][8][4];
#pragma unroll
    for (int i = 0; i < 4; ++i)
#pragma unroll
        for (int j = 0; j < 8; ++j)
#pragma unroll
            for (int v = 0; v < 4; ++v) acc[i][j][v] = 0.f;

    uint32_t aRow = (uint32_t)(wm + (lane & 15));
    uint32_t aKb  = (lane & 16) ? 16u : 0u;
    uint32_t bRow = (uint32_t)(wn + (lane & 7) + ((lane >> 4) & 1) * 8);
    uint32_t bKb  = ((lane >> 3) & 1) * 16u;

    int nc = K >> 6;

    auto issue = [&](int c, int buf) {
        uint32_t bo = (uint32_t)buf * 49152u;
#pragma unroll
        for (int rr = 0; rr < 8; ++rr)
            cp16(sAu + bo + soff[rr], aptr[rr] + c * 64);
#pragma unroll
        for (int rr = 0; rr < 4; ++rr)
            cp16(sBu + bo + soff[rr], bptr[rr] + c * 64);
        CP_COMMIT();
    };

    issue(0, 0);
    for (int c = 0; c < nc; ++c) {
        CP_WAIT0();
        __syncthreads();
        if (c + 1 < nc) issue(c + 1, (c + 1) & 1);
        uint32_t bo = (uint32_t)(c & 1) * 49152u;
#pragma unroll
        for (int kk = 0; kk < 4; ++kk) {
            uint32_t afr[4][4];
#pragma unroll
            for (int fm = 0; fm < 4; ++fm)
                ldmx4(afr[fm], sAu + bo + sw128((aRow + fm * 16) * 128 + kk * 32 + aKb));
            uint32_t bfr[4][4];
#pragma unroll
            for (int fn4 = 0; fn4 < 4; ++fn4)
                ldmx4(bfr[fn4], sBu + bo + sw128((bRow + fn4 * 16) * 128 + kk * 32 + bKb));
#pragma unroll
            for (int fm = 0; fm < 4; ++fm)
#pragma unroll
                for (int fn = 0; fn < 8; ++fn)
                    mma16816(acc[fm][fn], afr[fm],
                             bfr[fn >> 1][(fn & 1) * 2], bfr[fn >> 1][(fn & 1) * 2 + 1]);
        }
    }

    int rbase = lane >> 2;
    int cbase = (lane & 3) * 2;
#pragma unroll
    for (int fm = 0; fm < 4; ++fm) {
#pragma unroll
        for (int half_ = 0; half_ < 2; ++half_) {
            int rloc = wm + fm * 16 + rbase + half_ * 8;
            int rowi = m0 + rloc;
            bool valid = !(MODE == 2 || MODE == 3) || (rowi < cntE);
            if (!valid) continue;
            int tok = 0;
            float gt = 0.f;
            if (MODE == 3) { tok = g_perm[rowbase + rowi]; gt = g_gate[tok]; }
#pragma unroll
            for (int fn = 0; fn < 8; ++fn) {
                int col = n0 + wn + fn * 8 + cbase;
                if (MODE == 6) {
                    int grp = col / 768;
                    int lc  = col - grp * 768;
                    const float* bp = (grp == 0) ? bias : (grp == 1) ? R : (const float*)Cf;
                    __half* dst = (grp == 0) ? g_qh : (grp == 1) ? g_kh : g_vh;
                    float v0 = acc[fm][fn][half_ * 2 + 0] + bp[lc];
                    float v1 = acc[fm][fn][half_ * 2 + 1] + bp[lc + 1];
                    *(__half2*)(dst + (size_t)rowi * 768 + lc) = __floats2half2_rn(v0, v1);
                    continue;
                }
                float v0 = acc[fm][fn][half_ * 2 + 0] + bias[col];
                float v1 = acc[fm][fn][half_ * 2 + 1] + bias[col + 1];
                if (MODE == 1) {
                    float* o = Cf + (size_t)rowi * N + col;
                    const float* rr_ = R + (size_t)rowi * N + col;
                    o[0] = v0 + rr_[0]; o[1] = v1 + rr_[1];
                } else if (MODE == 2) {
                    float gl0 = 0.5f * v0 * (1.0f + erff(v0 * 0.70710678118654752f));
                    float gl1 = 0.5f * v1 * (1.0f + erff(v1 * 0.70710678118654752f));
                    *(__half2*)(Cb + (size_t)(rowbase + rowi) * N + col) =
                        __floats2half2_rn(gl0, gl1);
                } else if (MODE == 3) {
                    float* o = Cf + (size_t)tok * N + col;
                    const float* rr_ = R + (size_t)tok * N + col;
                    o[0] = rr_[0] + gt * v0;
                    o[1] = rr_[1] + gt * v1;
                }
            }
        }
    }
}

// ---------------- flash attention: 128 queries x (b,h) per block ----------------
__global__ __launch_bounds__(256)
void attn_fa(const __half* __restrict__ Q, const __half* __restrict__ Kx,
             const __half* __restrict__ V, __half* __restrict__ O)
{
    extern __shared__ char sm[];
    uint32_t sQu = smem_u32(sm);
    uint32_t sKu = sQu + 16384;
    uint32_t sVu = sKu + 16384;

    int bh = blockIdx.x;
    int b = bh / kH, h = bh % kH;
    int qt = blockIdx.y;
    int tid = threadIdx.x, wid = tid >> 5, lane = tid & 31;
    int wm = wid * 16;

    int i0 = tid >> 3, dv0 = (tid & 7) * 8;
    uint32_t so0 = sw128((uint32_t)i0 * 128 + dv0 * 2);
    uint32_t so1 = sw128((uint32_t)(i0 + 32) * 128 + dv0 * 2);

    auto issueKV = [&](int kt, int buf) {
        uint32_t bo = (uint32_t)buf * 8192u;
        int s0 = kt * 64 + i0, s1 = s0 + 32;
        const __half* kp0 = Kx + (size_t)(s0 * kB + b) * kD + h * kHD + dv0;
        const __half* kp1 = Kx + (size_t)(s1 * kB + b) * kD + h * kHD + dv0;
        const __half* vp0 = V  + (size_t)(s0 * kB + b) * kD + h * kHD + dv0;
        const __half* vp1 = V  + (size_t)(s1 * kB + b) * kD + h * kHD + dv0;
        cp16(sKu + bo + so0, kp0);
        cp16(sKu + bo + so1, kp1);
        cp16(sVu + bo + so0, vp0);
        cp16(sVu + bo + so1, vp1);
        CP_COMMIT();
    };

    // Q tile (128 rows), committed with K0/V0
#pragma unroll
    for (int r = 0; r < 4; ++r) {
        int s = qt * 128 + i0 + r * 32;
        cp16(sQu + sw128((uint32_t)(i0 + r * 32) * 128 + dv0 * 2),
             Q + (size_t)(s * kB + b) * kD + h * kHD + dv0);
    }
    issueKV(0, 0);

    uint32_t aRow = (uint32_t)(wm + (lane & 15));
    uint32_t aKb  = (lane & 16) ? 16u : 0u;
    uint32_t bRow = (uint32_t)((lane & 7) + ((lane >> 4) & 1) * 8);
    uint32_t bKb  = ((lane >> 3) & 1) * 16u;
    uint32_t vKey = (uint32_t)(((lane >> 3) & 1) * 8 + (lane & 7));
    uint32_t vDimB = (uint32_t)(((lane >> 4) & 1) * 8) * 2;

    uint32_t qf[4][4];
    float acc_o[8][4];
#pragma unroll
    for (int fn = 0; fn < 8; ++fn)
#pragma unroll
        for (int v = 0; v < 4; ++v) acc_o[fn][v] = 0.f;
    float m0 = -1e30f, m1 = -1e30f, l0 = 0.f, l1 = 0.f;

    for (int kt = 0; kt < 8; ++kt) {
        CP_WAIT0();
        __syncthreads();
        if (kt == 0) {
#pragma unroll
            for (int kk = 0; kk < 4; ++kk)
                ldmx4(qf[kk], sQu + sw128(aRow * 128 + kk * 32 + aKb));
        }
        if (kt + 1 < 8) issueKV(kt + 1, (kt + 1) & 1);
        uint32_t bo = (uint32_t)(kt & 1) * 8192u;

        // S = Q K^T (16 x 64 per warp)
        float s_[8][4];
#pragma unroll
        for (int fn = 0; fn < 8; ++fn)
#pragma unroll
            for (int v = 0; v < 4; ++v) s_[fn][v] = 0.f;
#pragma unroll
        for (int kk = 0; kk < 4; ++kk) {
            uint32_t bfr[4][4];
#pragma unroll
            for (int f4 = 0; f4 < 4; ++f4)
                ldmx4(bfr[f4], sKu + bo + sw128((bRow + f4 * 16) * 128 + kk * 32 + bKb));
#pragma unroll
            for (int fn = 0; fn < 8; ++fn)
                mma16816(s_[fn], qf[kk], bfr[fn >> 1][(fn & 1) * 2], bfr[fn >> 1][(fn & 1) * 2 + 1]);
        }

        // online softmax (rows: r0 = lane>>2, r1 = r0+8; quad = 4 lanes sharing a row)
        float mt0 = -1e30f, mt1 = -1e30f;
#pragma unroll
        for (int fn = 0; fn < 8; ++fn) {
            s_[fn][0] *= 0.125f; s_[fn][1] *= 0.125f;
            s_[fn][2] *= 0.125f; s_[fn][3] *= 0.125f;
            mt0 = fmaxf(mt0, fmaxf(s_[fn][0], s_[fn][1]));
            mt1 = fmaxf(mt1, fmaxf(s_[fn][2], s_[fn][3]));
        }
        mt0 = fmaxf(mt0, __shfl_xor_sync(0xffffffffu, mt0, 1));
        mt0 = fmaxf(mt0, __shfl_xor_sync(0xffffffffu, mt0, 2));
        mt1 = fmaxf(mt1, __shfl_xor_sync(0xffffffffu, mt1, 1));
        mt1 = fmaxf(mt1, __shfl_xor_sync(0xffffffffu, mt1, 2));
        float nm0 = fmaxf(m0, mt0), nm1 = fmaxf(m1, mt1);
        float sc0 = __expf(m0 - nm0), sc1 = __expf(m1 - nm1);

        uint32_t ph0[8], ph1[8];
        float rs0 = 0.f, rs1 = 0.f;
#pragma unroll
        for (int fn = 0; fn < 8; ++fn) {
            float p0 = __expf(s_[fn][0] - nm0);
            float p1 = __expf(s_[fn][1] - nm0);
            float p2 = __expf(s_[fn][2] - nm1);
            float p3 = __expf(s_[fn][3] - nm1);
            rs0 += p0 + p1; rs1 += p2 + p3;
            __half2 h0 = __floats2half2_rn(p0, p1);
            __half2 h1 = __floats2half2_rn(p2, p3);
            ph0[fn] = *(uint32_t*)&h0;
            ph1[fn] = *(uint32_t*)&h1;
        }
        rs0 += __shfl_xor_sync(0xffffffffu, rs0, 1);
        rs0 += __shfl_xor_sync(0xffffffffu, rs0, 2);
        rs1 += __shfl_xor_sync(0xffffffffu, rs1, 1);
        rs1 += __shfl_xor_sync(0xffffffffu, rs1, 2);
        l0 = l0 * sc0 + rs0;
        l1 = l1 * sc1 + rs1;
        m0 = nm0; m1 = nm1;
#pragma unroll
        for (int fn = 0; fn < 8; ++fn) {
            acc_o[fn][0] *= sc0; acc_o[fn][1] *= sc0;
            acc_o[fn][2] *= sc1; acc_o[fn][3] *= sc1;
        }

        // O += P @ V ; P fragments come straight from registers
#pragma unroll
        for (int kk2 = 0; kk2 < 4; ++kk2) {
            uint32_t a[4] = { ph0[2 * kk2], ph1[2 * kk2], ph0[2 * kk2 + 1], ph1[2 * kk2 + 1] };
            uint32_t bv_[4][4];
#pragma unroll
            for (int fd = 0; fd < 4; ++fd)
                ldmx4t(bv_[fd], sVu + bo + sw128((kk2 * 16 + vKey) * 128 + vDimB + fd * 32));
#pragma unroll
            for (int fn = 0; fn < 8; ++fn)
                mma16816(acc_o[fn], a, bv_[fn >> 1][(fn & 1) * 2], bv_[fn >> 1][(fn & 1) * 2 + 1]);
        }
    }

    // epilogue
    float inv0 = 1.0f / l0, inv1 = 1.0f / l1;
    int r0g = qt * 128 + wm + (lane >> 2);
    int r1g = r0g + 8;
#pragma unroll
    for (int fn = 0; fn < 8; ++fn) {
        int col = fn * 8 + (lane & 3) * 2;
        *(__half2*)(O + (size_t)(r0g * kB + b) * kD + h * kHD + col) =
            __floats2half2_rn(acc_o[fn][0] * inv0, acc_o[fn][1] * inv0);
        *(__half2*)(O + (size_t)(r1g * kB + b) * kD + h * kHD + col) =
            __floats2half2_rn(acc_o[fn][2] * inv1, acc_o[fn][3] * inv1);
    }
}

// ---------------- router ----------------
__global__ void router_kernel(const float* __restrict__ tin, const float* __restrict__ wg,
                              const float* __restrict__ bg)
{
    int warp = threadIdx.x >> 5;
    int tok  = blockIdx.x * 8 + warp;
    int lane = threadIdx.x & 31;
    const float* row = tin + (size_t)tok * kD;
    int e = lane >> 2, j = lane & 3;
    float s = 0.f;
    for (int d = j; d < kD; d += 4) s += row[d] * wg[d * kE + e];
    s += __shfl_xor_sync(0xffffffffu, s, 1);
    s += __shfl_xor_sync(0xffffffffu, s, 2);
    s += bg[e];
    float lg[kE];
#pragma unroll
    for (int ee = 0; ee < kE; ++ee) lg[ee] = __shfl_sync(0xffffffffu, s, ee * 4);
    if (lane == 0) {
        int best = 0; float bm = lg[0];
#pragma unroll
        for (int ee = 1; ee < kE; ++ee) if (lg[ee] > bm) { bm = lg[ee]; best = ee; }
        float se = 0.f;
#pragma unroll
        for (int ee = 0; ee < kE; ++ee) se += expf(lg[ee] - bm);
        g_idx[tok]  = best;
        g_gate[tok] = 1.0f / se;
        atomicAdd(&g_cnt[best], 1);
    }
}

__global__ void init_kernel()
{
    int t = threadIdx.x;
    if (t < kE) { g_cnt[t] = 0; g_fill[t] = 0; }
}

__global__ void prefix_kernel()
{
    int acc = 0;
    for (int e = 0; e < kE; ++e) { g_off[e] = acc; acc += g_cnt[e]; }
}

__global__ void scatter_kernel()
{
    int t = blockIdx.x * 256 + threadIdx.x;
    int e = g_idx[t];
    int p = atomicAdd(&g_fill[e], 1);
    g_perm[g_off[e] + p] = t;
}

// ---------------- launch ----------------
extern "C" void kernel_launch(void* const* d_in, const int* in_sizes, int n_in,
                              void* d_out, int out_size)
{
    const float* x    = (const float*)d_in[0];
    const float* ln1w = (const float*)d_in[1];
    const float* ln1b = (const float*)d_in[2];
    const float* wq   = (const float*)d_in[3];
    const float* bq   = (const float*)d_in[4];
    const float* wk   = (const float*)d_in[5];
    const float* bk   = (const float*)d_in[6];
    const float* wv   = (const float*)d_in[7];
    const float* bv   = (const float*)d_in[8];
    const float* wo   = (const float*)d_in[9];
    const float* bo   = (const float*)d_in[10];
    const float* ln2w = (const float*)d_in[11];
    const float* ln2b = (const float*)d_in[12];
    const float* wg   = (const float*)d_in[13];
    const float* bg   = (const float*)d_in[14];
    const float* w1   = (const float*)d_in[15];
    const float* b1   = (const float*)d_in[16];
    const float* w2   = (const float*)d_in[17];
    const float* b2   = (const float*)d_in[18];
    float* out = (float*)d_out;

    float *p_x1, *p_t;
    __half *p_wqkvt, *p_wot, *p_w1t, *p_w2t;
    __half *p_qin_h, *p_x_h, *p_qh, *p_kh, *p_vh, *p_attn_h, *p_t_h, *p_h_h;
    cudaGetSymbolAddress((void**)&p_x1,    g_x1);
    cudaGetSymbolAddress((void**)&p_t,     g_tn);
    cudaGetSymbolAddress((void**)&p_wqkvt, g_wqkvt);
    cudaGetSymbolAddress((void**)&p_wot,   g_wot);
    cudaGetSymbolAddress((void**)&p_w1t,   g_w1t);
    cudaGetSymbolAddress((void**)&p_w2t,   g_w2t);
    cudaGetSymbolAddress((void**)&p_qin_h, g_qin_h);
    cudaGetSymbolAddress((void**)&p_x_h,   g_x_h);
    cudaGetSymbolAddress((void**)&p_qh,    g_qh);
    cudaGetSymbolAddress((void**)&p_kh,    g_kh);
    cudaGetSymbolAddress((void**)&p_vh,    g_vh);
    cudaGetSymbolAddress((void**)&p_attn_h, g_attn_h);
    cudaGetSymbolAddress((void**)&p_t_h,   g_t_h);
    cudaGetSymbolAddress((void**)&p_h_h,   g_h_h);

    cudaFuncSetAttribute(attn_fa, cudaFuncAttributeMaxDynamicSharedMemorySize, FA_SMEM);
    cudaFuncSetAttribute(tc_gemm<1>, cudaFuncAttributeMaxDynamicSharedMemorySize, GEMM_SMEM);
    cudaFuncSetAttribute(tc_gemm<2>, cudaFuncAttributeMaxDynamicSharedMemorySize, GEMM_SMEM);
    cudaFuncSetAttribute(tc_gemm<3>, cudaFuncAttributeMaxDynamicSharedMemorySize, GEMM_SMEM);
    cudaFuncSetAttribute(tc_gemm<6>, cudaFuncAttributeMaxDynamicSharedMemorySize, GEMM_SMEM);

    // all weight transposes in one launch
    tconv_all<<<2304 + 2 * 18432, dim3(32, 8)>>>(wq, wk, wv, wo, w1, w2,
                                                 p_wqkvt, p_wot, p_w1t, p_w2t);

    // LN1 -> qin_h, x -> x_h in one pass
    ln_kernel<2><<<kT, 256>>>(x, ln1w, ln1b, nullptr, p_qin_h, p_x_h);

    // fused QKV projection
    tc_gemm<6><<<dim3(kT / 256, 18), 256, GEMM_SMEM>>>(
        nullptr, p_wqkvt, bq, bk, (float*)bv, nullptr, kT, 3 * kD, kD);

    // flash attention (half out)
    attn_fa<<<dim3(kB * kH, kS / 128), 256, FA_SMEM>>>(p_qh, p_kh, p_vh, p_attn_h);

    // out projection + residual -> x1 (fp32)
    tc_gemm<1><<<dim3(kT / 256, kD / 128), 256, GEMM_SMEM>>>(
        p_attn_h, p_wot, bo, x, p_x1, nullptr, kT, kD, kD);

    // LN2 -> t (fp32 for router) + t_h (half for gemms)
    ln_kernel<1><<<kT, 256>>>(p_x1, ln2w, ln2b, p_t, p_t_h, nullptr);

    // routing
    init_kernel<<<1, 32>>>();
    router_kernel<<<kT / 8, 256>>>(p_t, wg, bg);
    prefix_kernel<<<1, 1>>>();
    scatter_kernel<<<kT / 256, 256>>>();

    // MoE expert GEMMs
    tc_gemm<2><<<dim3(kT / 256, kHID / 128, kE), 256, GEMM_SMEM>>>(
        p_t_h, p_w1t, b1, nullptr, nullptr, p_h_h, kT, kHID, kD);
    tc_gemm<3><<<dim3(kT / 256, kD / 128, kE), 256, GEMM_SMEM>>>(
        p_h_h, p_w2t, b2, p_x1, out, nullptr, kT, kD, kHID);
}

// round 16
// speedup vs baseline: 6.0928x; 1.0126x over previous
#include <cuda_runtime.h>
#include <cuda_fp16.h>
#include <math.h>
#include <stdint.h>

// ---------------- problem constants ----------------
constexpr int kS   = 512;
constexpr int kB   = 16;
constexpr int kD   = 768;
constexpr int kH   = 12;
constexpr int kHD  = 64;
constexpr int kE   = 8;
constexpr int kHID = 3072;
constexpr int kT   = kS * kB;          // 8192 tokens

// flash-attention smem: Q 16K | K 2x8K | V 2x8K
constexpr int FA_SMEM = 16384 + 16384 + 16384;   // 49152

// gemm smem: 2 buffers x (A 32KB + B 16KB)
constexpr int GEMM_SMEM = 98304;

// ---------------- scratch (device globals; no allocations) ----------------
__device__ float g_x1  [kT * kD];
__device__ float g_tn  [kT * kD];
__device__ float g_gate[kT];
__device__ int   g_idx [kT];
__device__ int   g_cnt [kE];
__device__ int   g_off [kE];
__device__ int   g_fill[kE];
__device__ int   g_perm[kT];

// fp16 scratch
__device__ __half g_wqkvt[3 * kD * kD];            // [2304][768]: wq^T | wk^T | wv^T
__device__ __half g_wot[kD * kD];
__device__ __half g_w1t[(size_t)kE * kHID * kD];   // [E][HID][D]
__device__ __half g_w2t[(size_t)kE * kD * kHID];   // [E][D][HID]
__device__ __half g_qin_h[kT * kD];
__device__ __half g_x_h  [kT * kD];
__device__ __half g_qh   [kT * kD];
__device__ __half g_kh   [kT * kD];
__device__ __half g_vh   [kT * kD];
__device__ __half g_attn_h[kT * kD];
__device__ __half g_t_h  [kT * kD];
__device__ __half g_h_h  [(size_t)kT * kHID];

// ---------------- helpers ----------------
__device__ __forceinline__ uint32_t smem_u32(const void* p) {
    uint32_t a;
    asm("{ .reg .u64 t; cvta.to.shared.u64 t, %1; cvt.u32.u64 %0, t; }" : "=r"(a) : "l"(p));
    return a;
}
__device__ __forceinline__ void ldmx4(uint32_t* r, uint32_t addr) {
    asm volatile("ldmatrix.sync.aligned.m8n8.x4.shared.b16 {%0,%1,%2,%3}, [%4];"
                 : "=r"(r[0]), "=r"(r[1]), "=r"(r[2]), "=r"(r[3]) : "r"(addr));
}
__device__ __forceinline__ void ldmx4t(uint32_t* r, uint32_t addr) {
    asm volatile("ldmatrix.sync.aligned.m8n8.x4.trans.shared.b16 {%0,%1,%2,%3}, [%4];"
                 : "=r"(r[0]), "=r"(r[1]), "=r"(r[2]), "=r"(r[3]) : "r"(addr));
}
__device__ __forceinline__ void mma16816(float* d, const uint32_t* a, uint32_t b0, uint32_t b1) {
    asm volatile(
        "mma.sync.aligned.m16n8k16.row.col.f32.f16.f16.f32 "
        "{%0,%1,%2,%3}, {%4,%5,%6,%7}, {%8,%9}, {%0,%1,%2,%3};"
        : "+f"(d[0]), "+f"(d[1]), "+f"(d[2]), "+f"(d[3])
        : "r"(a[0]), "r"(a[1]), "r"(a[2]), "r"(a[3]), "r"(b0), "r"(b1));
}
__device__ __forceinline__ uint32_t sw128(uint32_t off) {
    return off ^ ((off >> 3) & 0x70);
}
__device__ __forceinline__ void cp16(uint32_t dst, const void* src) {
    asm volatile("cp.async.ca.shared.global [%0], [%1], 16;" :: "r"(dst), "l"(src));
}
#define CP_COMMIT() asm volatile("cp.async.commit_group;" ::: "memory")
#define CP_WAIT0()  asm volatile("cp.async.wait_group 0;" ::: "memory")

// ---------------- layernorm variants ----------------
// LNOUT 0: half only ; 1: fp32 + half ; 2: LN->outh + raw x -> outh2
template <int LNOUT>
__global__ void ln_kernel(const float* __restrict__ x, const float* __restrict__ w,
                          const float* __restrict__ bias,
                          float* __restrict__ outf, __half* __restrict__ outh,
                          __half* __restrict__ outh2)
{
    int t = blockIdx.x;
    const float* r = x + (size_t)t * kD;
    int tid = threadIdx.x;
    float v0 = r[tid], v1 = r[tid + 256], v2 = r[tid + 512];
    float s = v0 + v1 + v2;
    float q = v0 * v0 + v1 * v1 + v2 * v2;
#pragma unroll
    for (int o = 16; o > 0; o >>= 1) {
        s += __shfl_down_sync(0xffffffffu, s, o);
        q += __shfl_down_sync(0xffffffffu, q, o);
    }
    __shared__ float rs[8], rq[8];
    if ((tid & 31) == 0) { rs[tid >> 5] = s; rq[tid >> 5] = q; }
    __syncthreads();
    s = 0.f; q = 0.f;
#pragma unroll
    for (int i = 0; i < 8; ++i) { s += rs[i]; q += rq[i]; }
    float mean = s * (1.0f / kD);
    float var  = q * (1.0f / kD) - mean * mean;
    float inv  = rsqrtf(var + 1e-5f);
    float o0 = (v0 - mean) * inv * w[tid]       + bias[tid];
    float o1 = (v1 - mean) * inv * w[tid + 256] + bias[tid + 256];
    float o2 = (v2 - mean) * inv * w[tid + 512] + bias[tid + 512];
    if (LNOUT == 1) {
        float* of = outf + (size_t)t * kD;
        of[tid] = o0; of[tid + 256] = o1; of[tid + 512] = o2;
    }
    __half* oh = outh + (size_t)t * kD;
    oh[tid]       = __float2half(o0);
    oh[tid + 256] = __float2half(o1);
    oh[tid + 512] = __float2half(o2);
    if (LNOUT == 2) {
        __half* oh2 = outh2 + (size_t)t * kD;
        oh2[tid]       = __float2half(v0);
        oh2[tid + 256] = __float2half(v1);
        oh2[tid + 512] = __float2half(v2);
    }
}

// ---------------- merged transpose-convert: all 6 weights in one launch ----------------
__global__ void tconv_all(const float* __restrict__ wq, const float* __restrict__ wk,
                          const float* __restrict__ wv, const float* __restrict__ wo,
                          const float* __restrict__ w1, const float* __restrict__ w2,
                          __half* __restrict__ wqkvt, __half* __restrict__ wot,
                          __half* __restrict__ w1t, __half* __restrict__ w2t)
{
    __shared__ float tile[32][33];
    int bid = blockIdx.x;
    const float* in;
    __half* out;
    int R, C, tile_id;
    if (bid < 2304) {
        int j = bid / 576; tile_id = bid % 576;
        R = 768; C = 768;
        if (j == 0)      { in = wq; out = wqkvt; }
        else if (j == 1) { in = wk; out = wqkvt + 768 * 768; }
        else if (j == 2) { in = wv; out = wqkvt + 2 * 768 * 768; }
        else             { in = wo; out = wot; }
    } else if (bid < 2304 + 18432) {
        int t = bid - 2304; int e = t / 2304; tile_id = t % 2304;
        R = 768; C = 3072;
        in  = w1  + (size_t)e * R * C;
        out = w1t + (size_t)e * R * C;
    } else {
        int t = bid - 2304 - 18432; int e = t / 2304; tile_id = t % 2304;
        R = 3072; C = 768;
        in  = w2  + (size_t)e * R * C;
        out = w2t + (size_t)e * R * C;
    }
    int tpr = C / 32;
    int c0 = (tile_id % tpr) * 32;
    int r0 = (tile_id / tpr) * 32;
    int tx = threadIdx.x;
    for (int i = threadIdx.y; i < 32; i += 8)
        tile[i][tx] = in[(size_t)(r0 + i) * C + c0 + tx];
    __syncthreads();
    for (int i = threadIdx.y; i < 32; i += 8)
        out[(size_t)(c0 + i) * R + r0 + tx] = __float2half(tile[tx][i]);
}

// ---------------- fp16 mma.sync GEMM, 256x128 tile, 512 threads, cp.async 2-stage ----
// 16 warps: wm = (wid&3)*64 (M), wn = (wid>>2)*32 (N); warp tile 64x32.
// MODE 1: Cf = R + A@W + bias
// MODE 2: gathered rows via g_perm, gelu -> Cb (half) at sorted rows
// MODE 3: contiguous sorted rows, Cf[tok] = R[tok] + gate[tok]*(A@W+bias)
// MODE 6: fused QKV (N=2304; outputs split to g_qh/g_kh/g_vh)
template <int MODE>
__global__ __launch_bounds__(512)
void tc_gemm(const __half* __restrict__ A, const __half* __restrict__ Wt,
             const float* __restrict__ bias, const float* __restrict__ R,
             float* __restrict__ Cf, __half* __restrict__ Cb,
             int M, int N, int K)
{
    int cntE = M, rowbase = 0;
    if (MODE == 2 || MODE == 3) {
        int e = blockIdx.z;
        cntE = g_cnt[e];
        rowbase = g_off[e];
        if ((int)(blockIdx.x * 256) >= cntE) return;
        Wt   += (size_t)e * K * N;
        bias += (size_t)e * N;
    }
    int m0 = blockIdx.x * 256, n0 = blockIdx.y * 128;
    int tid = threadIdx.x, wid = tid >> 5, lane = tid & 31;
    int wm = (wid & 3) * 64;
    int wn = (wid >> 2) * 32;

    const __half* Abase = A;
    if (MODE == 6) Abase = (blockIdx.y < 6) ? g_qin_h : g_x_h;

    extern __shared__ char dynsm[];
    uint32_t sAu = smem_u32(dynsm);
    uint32_t sBu = sAu + 32768;

    int li = tid & 7, r4 = tid >> 3;   // r4: 0..63
    const __half* aptr[4];
    const __half* bptr[2];
#pragma unroll
    for (int rr = 0; rr < 4; ++rr) {
        int row = r4 + rr * 64;
        int lr = m0 + row;
        const __half* ap;
        if (MODE == 2) {
            int gr = (lr < cntE) ? g_perm[rowbase + lr] : 0;
            ap = Abase + (size_t)gr * K;
        } else if (MODE == 3) {
            ap = Abase + (size_t)(rowbase + (lr < cntE ? lr : 0)) * K;
        } else {
            ap = Abase + (size_t)lr * K;
        }
        aptr[rr] = ap + li * 8;
    }
#pragma unroll
    for (int rr = 0; rr < 2; ++rr)
        bptr[rr] = Wt + (size_t)(n0 + r4 + rr * 64) * K + li * 8;

    uint32_t soff[4];
#pragma unroll
    for (int rr = 0; rr < 4; ++rr)
        soff[rr] = sw128((uint32_t)(r4 + rr * 64) * 128 + (uint32_t)li * 16);

    float acc[4][4][4];
#pragma unroll
    for (int i = 0; i < 4; ++i)
#pragma unroll
        for (int j = 0; j < 4; ++j)
#pragma unroll
            for (int v = 0; v < 4; ++v) acc[i][j][v] = 0.f;

    uint32_t aRow = (uint32_t)(wm + (lane & 15));
    uint32_t aKb  = (lane & 16) ? 16u : 0u;
    uint32_t bRow = (uint32_t)(wn + (lane & 7) + ((lane >> 4) & 1) * 8);
    uint32_t bKb  = ((lane >> 3) & 1) * 16u;

    int nc = K >> 6;

    auto issue = [&](int c, int buf) {
        uint32_t bo = (uint32_t)buf * 49152u;
#pragma unroll
        for (int rr = 0; rr < 4; ++rr)
            cp16(sAu + bo + soff[rr], aptr[rr] + c * 64);
#pragma unroll
        for (int rr = 0; rr < 2; ++rr)
            cp16(sBu + bo + soff[rr], bptr[rr] + c * 64);
        CP_COMMIT();
    };

    issue(0, 0);
    for (int c = 0; c < nc; ++c) {
        CP_WAIT0();
        __syncthreads();
        if (c + 1 < nc) issue(c + 1, (c + 1) & 1);
        uint32_t bo = (uint32_t)(c & 1) * 49152u;
#pragma unroll
        for (int kk = 0; kk < 4; ++kk) {
            uint32_t afr[4][4];
#pragma unroll
            for (int fm = 0; fm < 4; ++fm)
                ldmx4(afr[fm], sAu + bo + sw128((aRow + fm * 16) * 128 + kk * 32 + aKb));
            uint32_t bfr[2][4];
#pragma unroll
            for (int fn2 = 0; fn2 < 2; ++fn2)
                ldmx4(bfr[fn2], sBu + bo + sw128((bRow + fn2 * 16) * 128 + kk * 32 + bKb));
#pragma unroll
            for (int fm = 0; fm < 4; ++fm)
#pragma unroll
                for (int fn = 0; fn < 4; ++fn)
                    mma16816(acc[fm][fn], afr[fm],
                             bfr[fn >> 1][(fn & 1) * 2], bfr[fn >> 1][(fn & 1) * 2 + 1]);
        }
    }

    int rbase = lane >> 2;
    int cbase = (lane & 3) * 2;
#pragma unroll
    for (int fm = 0; fm < 4; ++fm) {
#pragma unroll
        for (int half_ = 0; half_ < 2; ++half_) {
            int rloc = wm + fm * 16 + rbase + half_ * 8;
            int rowi = m0 + rloc;
            bool valid = !(MODE == 2 || MODE == 3) || (rowi < cntE);
            if (!valid) continue;
            int tok = 0;
            float gt = 0.f;
            if (MODE == 3) { tok = g_perm[rowbase + rowi]; gt = g_gate[tok]; }
#pragma unroll
            for (int fn = 0; fn < 4; ++fn) {
                int col = n0 + wn + fn * 8 + cbase;
                if (MODE == 6) {
                    int grp = col / 768;
                    int lc  = col - grp * 768;
                    const float* bp = (grp == 0) ? bias : (grp == 1) ? R : (const float*)Cf;
                    __half* dst = (grp == 0) ? g_qh : (grp == 1) ? g_kh : g_vh;
                    float v0 = acc[fm][fn][half_ * 2 + 0] + bp[lc];
                    float v1 = acc[fm][fn][half_ * 2 + 1] + bp[lc + 1];
                    *(__half2*)(dst + (size_t)rowi * 768 + lc) = __floats2half2_rn(v0, v1);
                    continue;
                }
                float v0 = acc[fm][fn][half_ * 2 + 0] + bias[col];
                float v1 = acc[fm][fn][half_ * 2 + 1] + bias[col + 1];
                if (MODE == 1) {
                    float* o = Cf + (size_t)rowi * N + col;
                    const float* rr_ = R + (size_t)rowi * N + col;
                    o[0] = v0 + rr_[0]; o[1] = v1 + rr_[1];
                } else if (MODE == 2) {
                    float gl0 = 0.5f * v0 * (1.0f + erff(v0 * 0.70710678118654752f));
                    float gl1 = 0.5f * v1 * (1.0f + erff(v1 * 0.70710678118654752f));
                    *(__half2*)(Cb + (size_t)(rowbase + rowi) * N + col) =
                        __floats2half2_rn(gl0, gl1);
                } else if (MODE == 3) {
                    float* o = Cf + (size_t)tok * N + col;
                    const float* rr_ = R + (size_t)tok * N + col;
                    o[0] = rr_[0] + gt * v0;
                    o[1] = rr_[1] + gt * v1;
                }
            }
        }
    }
}

// ---------------- flash attention: 128 queries x (b,h) per block ----------------
__global__ __launch_bounds__(256)
void attn_fa(const __half* __restrict__ Q, const __half* __restrict__ Kx,
             const __half* __restrict__ V, __half* __restrict__ O)
{
    extern __shared__ char sm[];
    uint32_t sQu = smem_u32(sm);
    uint32_t sKu = sQu + 16384;
    uint32_t sVu = sKu + 16384;

    int bh = blockIdx.x;
    int b = bh / kH, h = bh % kH;
    int qt = blockIdx.y;
    int tid = threadIdx.x, wid = tid >> 5, lane = tid & 31;
    int wm = wid * 16;

    int i0 = tid >> 3, dv0 = (tid & 7) * 8;
    uint32_t so0 = sw128((uint32_t)i0 * 128 + dv0 * 2);
    uint32_t so1 = sw128((uint32_t)(i0 + 32) * 128 + dv0 * 2);

    auto issueKV = [&](int kt, int buf) {
        uint32_t bo = (uint32_t)buf * 8192u;
        int s0 = kt * 64 + i0, s1 = s0 + 32;
        const __half* kp0 = Kx + (size_t)(s0 * kB + b) * kD + h * kHD + dv0;
        const __half* kp1 = Kx + (size_t)(s1 * kB + b) * kD + h * kHD + dv0;
        const __half* vp0 = V  + (size_t)(s0 * kB + b) * kD + h * kHD + dv0;
        const __half* vp1 = V  + (size_t)(s1 * kB + b) * kD + h * kHD + dv0;
        cp16(sKu + bo + so0, kp0);
        cp16(sKu + bo + so1, kp1);
        cp16(sVu + bo + so0, vp0);
        cp16(sVu + bo + so1, vp1);
        CP_COMMIT();
    };

#pragma unroll
    for (int r = 0; r < 4; ++r) {
        int s = qt * 128 + i0 + r * 32;
        cp16(sQu + sw128((uint32_t)(i0 + r * 32) * 128 + dv0 * 2),
             Q + (size_t)(s * kB + b) * kD + h * kHD + dv0);
    }
    issueKV(0, 0);

    uint32_t aRow = (uint32_t)(wm + (lane & 15));
    uint32_t aKb  = (lane & 16) ? 16u : 0u;
    uint32_t bRow = (uint32_t)((lane & 7) + ((lane >> 4) & 1) * 8);
    uint32_t bKb  = ((lane >> 3) & 1) * 16u;
    uint32_t vKey = (uint32_t)(((lane >> 3) & 1) * 8 + (lane & 7));
    uint32_t vDimB = (uint32_t)(((lane >> 4) & 1) * 8) * 2;

    uint32_t qf[4][4];
    float acc_o[8][4];
#pragma unroll
    for (int fn = 0; fn < 8; ++fn)
#pragma unroll
        for (int v = 0; v < 4; ++v) acc_o[fn][v] = 0.f;
    float m0 = -1e30f, m1 = -1e30f, l0 = 0.f, l1 = 0.f;

    for (int kt = 0; kt < 8; ++kt) {
        CP_WAIT0();
        __syncthreads();
        if (kt == 0) {
#pragma unroll
            for (int kk = 0; kk < 4; ++kk)
                ldmx4(qf[kk], sQu + sw128(aRow * 128 + kk * 32 + aKb));
        }
        if (kt + 1 < 8) issueKV(kt + 1, (kt + 1) & 1);
        uint32_t bo = (uint32_t)(kt & 1) * 8192u;

        float s_[8][4];
#pragma unroll
        for (int fn = 0; fn < 8; ++fn)
#pragma unroll
            for (int v = 0; v < 4; ++v) s_[fn][v] = 0.f;
#pragma unroll
        for (int kk = 0; kk < 4; ++kk) {
            uint32_t bfr[4][4];
#pragma unroll
            for (int f4 = 0; f4 < 4; ++f4)
                ldmx4(bfr[f4], sKu + bo + sw128((bRow + f4 * 16) * 128 + kk * 32 + bKb));
#pragma unroll
            for (int fn = 0; fn < 8; ++fn)
                mma16816(s_[fn], qf[kk], bfr[fn >> 1][(fn & 1) * 2], bfr[fn >> 1][(fn & 1) * 2 + 1]);
        }

        float mt0 = -1e30f, mt1 = -1e30f;
#pragma unroll
        for (int fn = 0; fn < 8; ++fn) {
            s_[fn][0] *= 0.125f; s_[fn][1] *= 0.125f;
            s_[fn][2] *= 0.125f; s_[fn][3] *= 0.125f;
            mt0 = fmaxf(mt0, fmaxf(s_[fn][0], s_[fn][1]));
            mt1 = fmaxf(mt1, fmaxf(s_[fn][2], s_[fn][3]));
        }
        mt0 = fmaxf(mt0, __shfl_xor_sync(0xffffffffu, mt0, 1));
        mt0 = fmaxf(mt0, __shfl_xor_sync(0xffffffffu, mt0, 2));
        mt1 = fmaxf(mt1, __shfl_xor_sync(0xffffffffu, mt1, 1));
        mt1 = fmaxf(mt1, __shfl_xor_sync(0xffffffffu, mt1, 2));
        float nm0 = fmaxf(m0, mt0), nm1 = fmaxf(m1, mt1);
        float sc0 = __expf(m0 - nm0), sc1 = __expf(m1 - nm1);

        uint32_t ph0[8], ph1[8];
        float rs0 = 0.f, rs1 = 0.f;
#pragma unroll
        for (int fn = 0; fn < 8; ++fn) {
            float p0 = __expf(s_[fn][0] - nm0);
            float p1 = __expf(s_[fn][1] - nm0);
            float p2 = __expf(s_[fn][2] - nm1);
            float p3 = __expf(s_[fn][3] - nm1);
            rs0 += p0 + p1; rs1 += p2 + p3;
            __half2 h0 = __floats2half2_rn(p0, p1);
            __half2 h1 = __floats2half2_rn(p2, p3);
            ph0[fn] = *(uint32_t*)&h0;
            ph1[fn] = *(uint32_t*)&h1;
        }
        rs0 += __shfl_xor_sync(0xffffffffu, rs0, 1);
        rs0 += __shfl_xor_sync(0xffffffffu, rs0, 2);
        rs1 += __shfl_xor_sync(0xffffffffu, rs1, 1);
        rs1 += __shfl_xor_sync(0xffffffffu, rs1, 2);
        l0 = l0 * sc0 + rs0;
        l1 = l1 * sc1 + rs1;
        m0 = nm0; m1 = nm1;
#pragma unroll
        for (int fn = 0; fn < 8; ++fn) {
            acc_o[fn][0] *= sc0; acc_o[fn][1] *= sc0;
            acc_o[fn][2] *= sc1; acc_o[fn][3] *= sc1;
        }

#pragma unroll
        for (int kk2 = 0; kk2 < 4; ++kk2) {
            uint32_t a[4] = { ph0[2 * kk2], ph1[2 * kk2], ph0[2 * kk2 + 1], ph1[2 * kk2 + 1] };
            uint32_t bv_[4][4];
#pragma unroll
            for (int fd = 0; fd < 4; ++fd)
                ldmx4t(bv_[fd], sVu + bo + sw128((kk2 * 16 + vKey) * 128 + vDimB + fd * 32));
#pragma unroll
            for (int fn = 0; fn < 8; ++fn)
                mma16816(acc_o[fn], a, bv_[fn >> 1][(fn & 1) * 2], bv_[fn >> 1][(fn & 1) * 2 + 1]);
        }
    }

    float inv0 = 1.0f / l0, inv1 = 1.0f / l1;
    int r0g = qt * 128 + wm + (lane >> 2);
    int r1g = r0g + 8;
#pragma unroll
    for (int fn = 0; fn < 8; ++fn) {
        int col = fn * 8 + (lane & 3) * 2;
        *(__half2*)(O + (size_t)(r0g * kB + b) * kD + h * kHD + col) =
            __floats2half2_rn(acc_o[fn][0] * inv0, acc_o[fn][1] * inv0);
        *(__half2*)(O + (size_t)(r1g * kB + b) * kD + h * kHD + col) =
            __floats2half2_rn(acc_o[fn][2] * inv1, acc_o[fn][3] * inv1);
    }
}

// ---------------- router ----------------
__global__ void router_kernel(const float* __restrict__ tin, const float* __restrict__ wg,
                              const float* __restrict__ bg)
{
    int warp = threadIdx.x >> 5;
    int tok  = blockIdx.x * 8 + warp;
    int lane = threadIdx.x & 31;
    const float* row = tin + (size_t)tok * kD;
    int e = lane >> 2, j = lane & 3;
    float s = 0.f;
    for (int d = j; d < kD; d += 4) s += row[d] * wg[d * kE + e];
    s += __shfl_xor_sync(0xffffffffu, s, 1);
    s += __shfl_xor_sync(0xffffffffu, s, 2);
    s += bg[e];
    float lg[kE];
#pragma unroll
    for (int ee = 0; ee < kE; ++ee) lg[ee] = __shfl_sync(0xffffffffu, s, ee * 4);
    if (lane == 0) {
        int best = 0; float bm = lg[0];
#pragma unroll
        for (int ee = 1; ee < kE; ++ee) if (lg[ee] > bm) { bm = lg[ee]; best = ee; }
        float se = 0.f;
#pragma unroll
        for (int ee = 0; ee < kE; ++ee) se += expf(lg[ee] - bm);
        g_idx[tok]  = best;
        g_gate[tok] = 1.0f / se;
        atomicAdd(&g_cnt[best], 1);
    }
}

__global__ void init_kernel()
{
    int t = threadIdx.x;
    if (t < kE) { g_cnt[t] = 0; g_fill[t] = 0; }
}

__global__ void prefix_kernel()
{
    int acc = 0;
    for (int e = 0; e < kE; ++e) { g_off[e] = acc; acc += g_cnt[e]; }
}

__global__ void scatter_kernel()
{
    int t = blockIdx.x * 256 + threadIdx.x;
    int e = g_idx[t];
    int p = atomicAdd(&g_fill[e], 1);
    g_perm[g_off[e] + p] = t;
}

// ---------------- launch ----------------
extern "C" void kernel_launch(void* const* d_in, const int* in_sizes, int n_in,
                              void* d_out, int out_size)
{
    const float* x    = (const float*)d_in[0];
    const float* ln1w = (const float*)d_in[1];
    const float* ln1b = (const float*)d_in[2];
    const float* wq   = (const float*)d_in[3];
    const float* bq   = (const float*)d_in[4];
    const float* wk   = (const float*)d_in[5];
    const float* bk   = (const float*)d_in[6];
    const float* wv   = (const float*)d_in[7];
    const float* bv   = (const float*)d_in[8];
    const float* wo   = (const float*)d_in[9];
    const float* bo   = (const float*)d_in[10];
    const float* ln2w = (const float*)d_in[11];
    const float* ln2b = (const float*)d_in[12];
    const float* wg   = (const float*)d_in[13];
    const float* bg   = (const float*)d_in[14];
    const float* w1   = (const float*)d_in[15];
    const float* b1   = (const float*)d_in[16];
    const float* w2   = (const float*)d_in[17];
    const float* b2   = (const float*)d_in[18];
    float* out = (float*)d_out;

    float *p_x1, *p_t;
    __half *p_wqkvt, *p_wot, *p_w1t, *p_w2t;
    __half *p_qin_h, *p_x_h, *p_qh, *p_kh, *p_vh, *p_attn_h, *p_t_h, *p_h_h;
    cudaGetSymbolAddress((void**)&p_x1,    g_x1);
    cudaGetSymbolAddress((void**)&p_t,     g_tn);
    cudaGetSymbolAddress((void**)&p_wqkvt, g_wqkvt);
    cudaGetSymbolAddress((void**)&p_wot,   g_wot);
    cudaGetSymbolAddress((void**)&p_w1t,   g_w1t);
    cudaGetSymbolAddress((void**)&p_w2t,   g_w2t);
    cudaGetSymbolAddress((void**)&p_qin_h, g_qin_h);
    cudaGetSymbolAddress((void**)&p_x_h,   g_x_h);
    cudaGetSymbolAddress((void**)&p_qh,    g_qh);
    cudaGetSymbolAddress((void**)&p_kh,    g_kh);
    cudaGetSymbolAddress((void**)&p_vh,    g_vh);
    cudaGetSymbolAddress((void**)&p_attn_h, g_attn_h);
    cudaGetSymbolAddress((void**)&p_t_h,   g_t_h);
    cudaGetSymbolAddress((void**)&p_h_h,   g_h_h);

    cudaFuncSetAttribute(attn_fa, cudaFuncAttributeMaxDynamicSharedMemorySize, FA_SMEM);
    cudaFuncSetAttribute(tc_gemm<1>, cudaFuncAttributeMaxDynamicSharedMemorySize, GEMM_SMEM);
    cudaFuncSetAttribute(tc_gemm<2>, cudaFuncAttributeMaxDynamicSharedMemorySize, GEMM_SMEM);
    cudaFuncSetAttribute(tc_gemm<3>, cudaFuncAttributeMaxDynamicSharedMemorySize, GEMM_SMEM);
    cudaFuncSetAttribute(tc_gemm<6>, cudaFuncAttributeMaxDynamicSharedMemorySize, GEMM_SMEM);

    // all weight transposes in one launch
    tconv_all<<<2304 + 2 * 18432, dim3(32, 8)>>>(wq, wk, wv, wo, w1, w2,
                                                 p_wqkvt, p_wot, p_w1t, p_w2t);

    // LN1 -> qin_h, x -> x_h in one pass
    ln_kernel<2><<<kT, 256>>>(x, ln1w, ln1b, nullptr, p_qin_h, p_x_h);

    // fused QKV projection
    tc_gemm<6><<<dim3(kT / 256, 18), 512, GEMM_SMEM>>>(
        nullptr, p_wqkvt, bq, bk, (float*)bv, nullptr, kT, 3 * kD, kD);

    // flash attention (half out)
    attn_fa<<<dim3(kB * kH, kS / 128), 256, FA_SMEM>>>(p_qh, p_kh, p_vh, p_attn_h);

    // out projection + residual -> x1 (fp32)
    tc_gemm<1><<<dim3(kT / 256, kD / 128), 512, GEMM_SMEM>>>(
        p_attn_h, p_wot, bo, x, p_x1, nullptr, kT, kD, kD);

    // LN2 -> t (fp32 for router) + t_h (half for gemms)
    ln_kernel<1><<<kT, 256>>>(p_x1, ln2w, ln2b, p_t, p_t_h, nullptr);

    // routing
    init_kernel<<<1, 32>>>();
    router_kernel<<<kT / 8, 256>>>(p_t, wg, bg);
    prefix_kernel<<<1, 1>>>();
    scatter_kernel<<<kT / 256, 256>>>();

    // MoE expert GEMMs
    tc_gemm<2><<<dim3(kT / 256, kHID / 128, kE), 512, GEMM_SMEM>>>(
        p_t_h, p_w1t, b1, nullptr, nullptr, p_h_h, kT, kHID, kD);
    tc_gemm<3><<<dim3(kT / 256, kD / 128, kE), 512, GEMM_SMEM>>>(
        p_h_h, p_w2t, b2, p_x1, out, nullptr, kT, kD, kHID);
}